// round 1
// baseline (speedup 1.0000x reference)
#include <cuda_runtime.h>
#include <math.h>

// ---------------------------------------------------------------------------
// Problem constants
// ---------------------------------------------------------------------------
#define BATCH   2
#define SEQ     2048
#define DMODEL  1024
#define NHEADS  16
#define HEADDIM 64
#define DFF     4096
#define BS      (BATCH * SEQ)          // 4096 rows
#define LN_EPS  1e-5f
#define ATTN_SCALE 0.08838834764831845f   // 1/sqrt(128)

// ---------------------------------------------------------------------------
// Scratch buffers (device globals: no allocation allowed in kernel_launch)
// ---------------------------------------------------------------------------
__device__ float g_bufQ   [BS * DMODEL];              // q raw; later reused for Wo out & attn-proj
__device__ float g_bufK   [BS * DMODEL];              // k raw; later reused for FFN-2 out
__device__ float g_bufV   [BS * DMODEL];              // v raw (kept in (B,S,D) layout for attention)
__device__ float g_bufQP  [BATCH * NHEADS * SEQ * 2 * HEADDIM];  // q_pope (B,H,S,128)
__device__ float g_bufKP  [BATCH * NHEADS * SEQ * 2 * HEADDIM];  // k_pope (B,H,S,128)
__device__ float g_bufAttn[BS * DMODEL];              // attention output (B,S,D)
__device__ float g_bufX1  [BS * DMODEL];              // after first LN
__device__ float g_bufFF  [BS * DFF];                 // FFN hidden

// ---------------------------------------------------------------------------
// SGEMM: C(MxN) = A(MxK) @ B(KxN) + bias(N), optional ReLU.
// 128x128 tile, BK=16, 256 threads, 8x8 per-thread micro-tile.
// All dims are multiples of the tile sizes for this problem (no bounds checks).
// ---------------------------------------------------------------------------
#define GBM 128
#define GBN 128
#define GBK 16

template<int RELU>
__global__ __launch_bounds__(256)
void sgemm_kernel(const float* __restrict__ A, const float* __restrict__ B,
                  const float* __restrict__ bias, float* __restrict__ C,
                  int M, int N, int K)
{
    __shared__ float As[GBK][GBM];   // stored transposed: As[k][m]
    __shared__ float Bs[GBK][GBN];

    const int tid = threadIdx.x;
    const int block_row = blockIdx.y * GBM;
    const int block_col = blockIdx.x * GBN;
    const int ty = tid >> 4;         // 0..15
    const int tx = tid & 15;         // 0..15

    // A-load mapping: 128 rows x 16 cols, each thread loads 2 float4
    const int ar = tid >> 2;          // 0..63
    const int ac = (tid & 3) * 4;     // 0,4,8,12
    // B-load mapping: 16 rows x 128 cols, each thread loads 2 float4
    const int br = tid >> 5;          // 0..7
    const int bc = (tid & 31) * 4;    // 0..124

    float acc[8][8];
#pragma unroll
    for (int i = 0; i < 8; ++i)
#pragma unroll
        for (int j = 0; j < 8; ++j) acc[i][j] = 0.f;

    for (int k0 = 0; k0 < K; k0 += GBK) {
#pragma unroll
        for (int r = 0; r < 2; ++r) {
            float4 av = *(const float4*)&A[(size_t)(block_row + ar + r * 64) * K + k0 + ac];
            As[ac + 0][ar + r * 64] = av.x;
            As[ac + 1][ar + r * 64] = av.y;
            As[ac + 2][ar + r * 64] = av.z;
            As[ac + 3][ar + r * 64] = av.w;
        }
#pragma unroll
        for (int r = 0; r < 2; ++r) {
            float4 bv = *(const float4*)&B[(size_t)(k0 + br + r * 8) * N + block_col + bc];
            *(float4*)&Bs[br + r * 8][bc] = bv;
        }
        __syncthreads();

#pragma unroll
        for (int kk = 0; kk < GBK; ++kk) {
            float af[8], bf[8];
#pragma unroll
            for (int i = 0; i < 8; ++i) af[i] = As[kk][ty * 8 + i];
#pragma unroll
            for (int j = 0; j < 8; ++j) bf[j] = Bs[kk][tx * 8 + j];
#pragma unroll
            for (int i = 0; i < 8; ++i)
#pragma unroll
                for (int j = 0; j < 8; ++j)
                    acc[i][j] = fmaf(af[i], bf[j], acc[i][j]);
        }
        __syncthreads();
    }

#pragma unroll
    for (int i = 0; i < 8; ++i) {
        const size_t row = block_row + ty * 8 + i;
#pragma unroll
        for (int j = 0; j < 8; j += 4) {
            float4 o;
            float vx = acc[i][j + 0] + bias[block_col + tx * 8 + j + 0];
            float vy = acc[i][j + 1] + bias[block_col + tx * 8 + j + 1];
            float vz = acc[i][j + 2] + bias[block_col + tx * 8 + j + 2];
            float vw = acc[i][j + 3] + bias[block_col + tx * 8 + j + 3];
            if (RELU) { vx = fmaxf(vx, 0.f); vy = fmaxf(vy, 0.f); vz = fmaxf(vz, 0.f); vw = fmaxf(vw, 0.f); }
            o.x = vx; o.y = vy; o.z = vz; o.w = vw;
            *(float4*)&C[row * N + block_col + tx * 8 + j] = o;
        }
    }
}

// ---------------------------------------------------------------------------
// PoPE transform: softplus magnitudes, phases = pos*freq + bias.
// Scale 1/sqrt(128) is folded into q_pope.
// Output layout: (B,H,S,128) with [mu*cos | mu*sin].
// ---------------------------------------------------------------------------
__device__ __forceinline__ float softplus_f(float x) {
    return fmaxf(x, 0.f) + log1pf(expf(-fabsf(x)));
}

__global__ void pope_kernel(const float* __restrict__ q, const float* __restrict__ k,
                            const int* __restrict__ positions,
                            const float* __restrict__ freqs,
                            const float* __restrict__ phase_bias,
                            float* __restrict__ qp, float* __restrict__ kp)
{
    int idx = blockIdx.x * blockDim.x + threadIdx.x;     // B*H*S*64 = 4194304
    if (idx >= BATCH * NHEADS * SEQ * HEADDIM) return;
    int d = idx & 63;
    int s = (idx >> 6) & (SEQ - 1);
    int h = (idx >> 17) & (NHEADS - 1);
    int b = idx >> 21;

    float qv = q[(size_t)(b * SEQ + s) * DMODEL + h * HEADDIM + d];
    float kv = k[(size_t)(b * SEQ + s) * DMODEL + h * HEADDIM + d];

    float phase = (float)positions[s] * freqs[d] + phase_bias[h * HEADDIM + d];
    float cp, sp;
    sincosf(phase, &sp, &cp);

    float mq = softplus_f(qv) * ATTN_SCALE;
    float mk = softplus_f(kv);

    size_t base = (((size_t)(b * NHEADS + h) * SEQ) + s) * 128 + d;
    qp[base]      = mq * cp;
    qp[base + 64] = mq * sp;
    kp[base]      = mk * cp;
    kp[base + 64] = mk * sp;
}

// ---------------------------------------------------------------------------
// Flash-style causal attention with softmax1 (denominator 1 + sum(e)).
// 64 queries x 64 keys tiles, 256 threads (16x16), 4x4 micro-tile per thread.
// K tile is stored transposed in smem (stride 65) for conflict-free loads.
// ---------------------------------------------------------------------------
#define ATN_SMEM_FLOATS (64*128 + 128*65 + 64*64 + 64*64)

__global__ __launch_bounds__(256)
void attn_kernel(const float* __restrict__ qp, const float* __restrict__ kp,
                 const float* __restrict__ v, float* __restrict__ out)
{
    extern __shared__ float sm[];
    float* Qs = sm;                    // 64 x 128
    float* Kt = Qs + 64 * 128;         // 128 x 65 (transposed)
    float* Vs = Kt + 128 * 65;         // 64 x 64
    float* Ps = Vs + 64 * 64;          // 64 x 64

    const int b  = blockIdx.z;
    const int h  = blockIdx.y;
    const int q0 = blockIdx.x * 64;
    const int tid = threadIdx.x;
    const int ty = tid >> 4;           // 0..15
    const int tx = tid & 15;           // 0..15

    const float* qbase = qp + (((size_t)(b * NHEADS + h)) * SEQ) * 128;
    const float* kbase = kp + (((size_t)(b * NHEADS + h)) * SEQ) * 128;

    // Load Q tile (64 x 128)
    for (int i = tid; i < 64 * 128 / 4; i += 256)
        ((float4*)Qs)[i] = ((const float4*)(qbase + (size_t)q0 * 128))[i];

    float acc[4][4];
    float mrow[4], lrow[4];
#pragma unroll
    for (int i = 0; i < 4; ++i) {
        mrow[i] = -INFINITY; lrow[i] = 0.f;
#pragma unroll
        for (int j = 0; j < 4; ++j) acc[i][j] = 0.f;
    }

    for (int kt = 0; kt <= q0; kt += 64) {
        __syncthreads();   // also protects Q on first iter / prev-iter Ps,Vs,Kt reuse

        // Load K tile transposed: Kt[d][r]
        for (int i = tid; i < 64 * 128 / 4; i += 256) {
            int r  = i >> 5;
            int c4 = (i & 31) * 4;
            float4 kv4 = ((const float4*)(kbase + (size_t)kt * 128))[i];
            Kt[(c4 + 0) * 65 + r] = kv4.x;
            Kt[(c4 + 1) * 65 + r] = kv4.y;
            Kt[(c4 + 2) * 65 + r] = kv4.z;
            Kt[(c4 + 3) * 65 + r] = kv4.w;
        }
        // Load V tile (64 keys x 64 dims) from (B,S,D) layout
        for (int i = tid; i < 64 * 64 / 4; i += 256) {
            int r  = i >> 4;
            int c4 = (i & 15) * 4;
            float4 vv = *(const float4*)&v[((size_t)b * SEQ + kt + r) * DMODEL + h * HEADDIM + c4];
            *(float4*)&Vs[r * 64 + c4] = vv;
        }
        __syncthreads();

        // Scores: s[i][j] = sum_d Q[4ty+i][d] * K[4tx+j][d]   (scale pre-folded)
        float s[4][4];
#pragma unroll
        for (int i = 0; i < 4; ++i)
#pragma unroll
            for (int j = 0; j < 4; ++j) s[i][j] = 0.f;

        for (int d = 0; d < 128; ++d) {
            float qv[4], kv[4];
#pragma unroll
            for (int i = 0; i < 4; ++i) qv[i] = Qs[(4 * ty + i) * 128 + d];
#pragma unroll
            for (int j = 0; j < 4; ++j) kv[j] = Kt[d * 65 + 4 * tx + j];
#pragma unroll
            for (int i = 0; i < 4; ++i)
#pragma unroll
                for (int j = 0; j < 4; ++j)
                    s[i][j] = fmaf(qv[i], kv[j], s[i][j]);
        }

        // Causal mask (only on the diagonal tile)
        if (kt == q0) {
#pragma unroll
            for (int i = 0; i < 4; ++i)
#pragma unroll
                for (int j = 0; j < 4; ++j)
                    if (4 * tx + j > 4 * ty + i) s[i][j] = -INFINITY;
        }

        // Online softmax1 per row (16 lanes per row within half-warp)
#pragma unroll
        for (int i = 0; i < 4; ++i) {
            float mx = fmaxf(fmaxf(s[i][0], s[i][1]), fmaxf(s[i][2], s[i][3]));
#pragma unroll
            for (int off = 8; off >= 1; off >>= 1)
                mx = fmaxf(mx, __shfl_xor_sync(0xffffffffu, mx, off));

            float mnew = fmaxf(mrow[i], mx);
            float corr = expf(mrow[i] - mnew);
            mrow[i] = mnew;

            float ls = 0.f;
#pragma unroll
            for (int j = 0; j < 4; ++j) {
                float p = expf(s[i][j] - mnew);
                s[i][j] = p;
                ls += p;
            }
#pragma unroll
            for (int off = 8; off >= 1; off >>= 1)
                ls += __shfl_xor_sync(0xffffffffu, ls, off);

            lrow[i] = lrow[i] * corr + ls;
#pragma unroll
            for (int j = 0; j < 4; ++j) acc[i][j] *= corr;

#pragma unroll
            for (int j = 0; j < 4; ++j)
                Ps[(4 * ty + i) * 64 + 4 * tx + j] = s[i][j];
        }
        __syncthreads();

        // acc += P @ V
        for (int kk = 0; kk < 64; ++kk) {
            float pv[4], vv[4];
#pragma unroll
            for (int i = 0; i < 4; ++i) pv[i] = Ps[(4 * ty + i) * 64 + kk];
#pragma unroll
            for (int j = 0; j < 4; ++j) vv[j] = Vs[kk * 64 + 4 * tx + j];
#pragma unroll
            for (int i = 0; i < 4; ++i)
#pragma unroll
                for (int j = 0; j < 4; ++j)
                    acc[i][j] = fmaf(pv[i], vv[j], acc[i][j]);
        }
    }

    // Epilogue: softmax1 denominator = 1 + l. Write to (B,S,D) layout.
#pragma unroll
    for (int i = 0; i < 4; ++i) {
        float inv = 1.f / (1.f + lrow[i]);
#pragma unroll
        for (int j = 0; j < 4; ++j) {
            out[((size_t)b * SEQ + q0 + 4 * ty + i) * DMODEL + h * HEADDIM + 4 * tx + j] =
                acc[i][j] * inv;
        }
    }
}

// ---------------------------------------------------------------------------
// Fused residual add + LayerNorm. One block (256 threads) per row of 1024.
// ---------------------------------------------------------------------------
__global__ __launch_bounds__(256)
void add_ln_kernel(const float* __restrict__ x, const float* __restrict__ y,
                   const float* __restrict__ g, const float* __restrict__ beta,
                   float* __restrict__ out)
{
    __shared__ float red_s[8];
    __shared__ float red_ss[8];
    __shared__ float s_mu, s_rstd;

    const int row = blockIdx.x;
    const int tid = threadIdx.x;
    const size_t base = (size_t)row * DMODEL;

    float4 xv = ((const float4*)(x + base))[tid];
    float4 yv = ((const float4*)(y + base))[tid];
    float v0 = xv.x + yv.x, v1 = xv.y + yv.y, v2 = xv.z + yv.z, v3 = xv.w + yv.w;

    float sum = v0 + v1 + v2 + v3;
    float ssq = v0 * v0 + v1 * v1 + v2 * v2 + v3 * v3;
#pragma unroll
    for (int off = 16; off >= 1; off >>= 1) {
        sum += __shfl_down_sync(0xffffffffu, sum, off);
        ssq += __shfl_down_sync(0xffffffffu, ssq, off);
    }
    const int warp = tid >> 5;
    if ((tid & 31) == 0) { red_s[warp] = sum; red_ss[warp] = ssq; }
    __syncthreads();
    if (tid == 0) {
        float ts = 0.f, tss = 0.f;
#pragma unroll
        for (int w = 0; w < 8; ++w) { ts += red_s[w]; tss += red_ss[w]; }
        float mu  = ts / (float)DMODEL;
        float var = tss / (float)DMODEL - mu * mu;
        s_mu = mu;
        s_rstd = rsqrtf(var + LN_EPS);
    }
    __syncthreads();
    const float mu = s_mu, rstd = s_rstd;

    float4 gv = ((const float4*)g)[tid];
    float4 bv = ((const float4*)beta)[tid];
    float4 o;
    o.x = (v0 - mu) * rstd * gv.x + bv.x;
    o.y = (v1 - mu) * rstd * gv.y + bv.y;
    o.z = (v2 - mu) * rstd * gv.z + bv.z;
    o.w = (v3 - mu) * rstd * gv.w + bv.w;
    ((float4*)(out + base))[tid] = o;
}

// ---------------------------------------------------------------------------
// Launcher
// ---------------------------------------------------------------------------
extern "C" void kernel_launch(void* const* d_in, const int* in_sizes, int n_in,
                              void* d_out, int out_size)
{
    (void)in_sizes; (void)n_in;
    const float* x          = (const float*)d_in[0];
    const int*   positions  = (const int*)  d_in[1];
    const float* Wq         = (const float*)d_in[2];
    const float* bq         = (const float*)d_in[3];
    const float* Wk         = (const float*)d_in[4];
    const float* bk         = (const float*)d_in[5];
    const float* Wv         = (const float*)d_in[6];
    const float* bv         = (const float*)d_in[7];
    const float* Wo         = (const float*)d_in[8];
    const float* bo         = (const float*)d_in[9];
    const float* phase_bias = (const float*)d_in[10];
    const float* freqs      = (const float*)d_in[11];
    const float* W1         = (const float*)d_in[12];
    const float* b1         = (const float*)d_in[13];
    const float* W2         = (const float*)d_in[14];
    const float* b2         = (const float*)d_in[15];
    const float* g1         = (const float*)d_in[16];
    const float* beta1      = (const float*)d_in[17];
    const float* g2         = (const float*)d_in[18];
    const float* beta2      = (const float*)d_in[19];
    float* outp             = (float*)d_out;
    (void)out_size;

    float *bufQ, *bufK, *bufV, *bufQP, *bufKP, *bufAttn, *bufX1, *bufFF;
    cudaGetSymbolAddress((void**)&bufQ,    g_bufQ);
    cudaGetSymbolAddress((void**)&bufK,    g_bufK);
    cudaGetSymbolAddress((void**)&bufV,    g_bufV);
    cudaGetSymbolAddress((void**)&bufQP,   g_bufQP);
    cudaGetSymbolAddress((void**)&bufKP,   g_bufKP);
    cudaGetSymbolAddress((void**)&bufAttn, g_bufAttn);
    cudaGetSymbolAddress((void**)&bufX1,   g_bufX1);
    cudaGetSymbolAddress((void**)&bufFF,   g_bufFF);

    // Allow ~97KB dynamic smem for the attention kernel.
    static const size_t attn_smem = ATN_SMEM_FLOATS * sizeof(float);
    cudaFuncSetAttribute(attn_kernel, cudaFuncAttributeMaxDynamicSharedMemorySize,
                         (int)attn_smem);

    dim3 gemm_block(256);

    // 1-3: QKV projections
    {
        dim3 grid(DMODEL / GBN, BS / GBM);
        sgemm_kernel<0><<<grid, gemm_block>>>(x, Wq, bq, bufQ, BS, DMODEL, DMODEL);
        sgemm_kernel<0><<<grid, gemm_block>>>(x, Wk, bk, bufK, BS, DMODEL, DMODEL);
        sgemm_kernel<0><<<grid, gemm_block>>>(x, Wv, bv, bufV, BS, DMODEL, DMODEL);
    }

    // 4: PoPE transform
    {
        int total = BATCH * NHEADS * SEQ * HEADDIM;
        pope_kernel<<<(total + 255) / 256, 256>>>(bufQ, bufK, positions, freqs,
                                                  phase_bias, bufQP, bufKP);
    }

    // 5: causal attention with softmax1
    {
        dim3 grid(SEQ / 64, NHEADS, BATCH);
        attn_kernel<<<grid, 256, attn_smem>>>(bufQP, bufKP, bufV, bufAttn);
    }

    // 6: output projection (reuse bufQ)
    {
        dim3 grid(DMODEL / GBN, BS / GBM);
        sgemm_kernel<0><<<grid, gemm_block>>>(bufAttn, Wo, bo, bufQ, BS, DMODEL, DMODEL);
    }

    // 7: residual + LN1 -> bufX1
    add_ln_kernel<<<BS, 256>>>(x, bufQ, g1, beta1, bufX1);

    // 8: FFN up + ReLU
    {
        dim3 grid(DFF / GBN, BS / GBM);
        sgemm_kernel<1><<<grid, gemm_block>>>(bufX1, W1, b1, bufFF, BS, DFF, DMODEL);
    }

    // 9: FFN down (reuse bufK)
    {
        dim3 grid(DMODEL / GBN, BS / GBM);
        sgemm_kernel<0><<<grid, gemm_block>>>(bufFF, W2, b2, bufK, BS, DMODEL, DFF);
    }

    // 10: residual + LN2 -> output
    add_ln_kernel<<<BS, 256>>>(bufX1, bufK, g2, beta2, outp);
}

// round 3
// speedup vs baseline: 1.9199x; 1.9199x over previous
#include <cuda_runtime.h>
#include <math.h>
#include <stdint.h>

// ---------------------------------------------------------------------------
// Problem constants
// ---------------------------------------------------------------------------
#define BATCH   2
#define SEQ     2048
#define DMODEL  1024
#define NHEADS  16
#define HEADDIM 64
#define DFF     4096
#define BS      (BATCH * SEQ)          // 4096 rows
#define LN_EPS  1e-5f
#define ATTN_SCALE 0.08838834764831845f   // 1/sqrt(128)

// ---------------------------------------------------------------------------
// Scratch buffers
// ---------------------------------------------------------------------------
__device__ float g_bufQ   [BS * DMODEL];
__device__ float g_bufK   [BS * DMODEL];
__device__ float g_bufV   [BS * DMODEL];
__device__ float g_bufQP  [BATCH * NHEADS * SEQ * 2 * HEADDIM];
__device__ float g_bufKP  [BATCH * NHEADS * SEQ * 2 * HEADDIM];
__device__ float g_bufAttn[BS * DMODEL];
__device__ float g_bufX1  [BS * DMODEL];
__device__ float g_bufFF  [BS * DFF];

// Pre-transposed (tf32-rounded) weights: [N][K]
__device__ float g_WqT[DMODEL * DMODEL];
__device__ float g_WkT[DMODEL * DMODEL];
__device__ float g_WvT[DMODEL * DMODEL];
__device__ float g_WoT[DMODEL * DMODEL];
__device__ float g_W1T[DMODEL * DFF];
__device__ float g_W2T[DFF * DMODEL];

// ---------------------------------------------------------------------------
// Helpers
// ---------------------------------------------------------------------------
__device__ __forceinline__ uint32_t smem_u32(const void* p) {
    uint32_t a;
    asm("{ .reg .u64 t; cvta.to.shared.u64 t, %1; cvt.u32.u64 %0, t; }"
        : "=r"(a) : "l"(p));
    return a;
}

__device__ __forceinline__ float to_tf32_f(float x) {
    float r;
    asm("cvt.rna.tf32.f32 %0, %1;" : "=f"(r) : "f"(x));
    return r;
}

__device__ __forceinline__ uint32_t f2tf32(float x) {
    uint32_t r;
    asm("cvt.rna.tf32.f32 %0, %1;" : "=r"(r) : "f"(x));
    return r;
}

__device__ __forceinline__ void cp_async16(uint32_t saddr, const void* gptr) {
    asm volatile("cp.async.cg.shared.global [%0], [%1], 16;"
                 :: "r"(saddr), "l"(gptr) : "memory");
}

__device__ __forceinline__ void mma_tf32(float (&d)[4],
                                         const uint32_t (&a)[4],
                                         uint32_t b0, uint32_t b1)
{
    asm volatile(
        "mma.sync.aligned.m16n8k8.row.col.f32.tf32.tf32.f32 "
        "{%0,%1,%2,%3}, {%4,%5,%6,%7}, {%8,%9}, {%0,%1,%2,%3};"
        : "+f"(d[0]), "+f"(d[1]), "+f"(d[2]), "+f"(d[3])
        : "r"(a[0]), "r"(a[1]), "r"(a[2]), "r"(a[3]), "r"(b0), "r"(b1));
}

// ---------------------------------------------------------------------------
// Weight transpose + tf32 rounding: in[K][N] -> out[N][K]
// ---------------------------------------------------------------------------
__global__ __launch_bounds__(256)
void transpose_tf32_kernel(const float* __restrict__ in, float* __restrict__ out,
                           int K, int N)
{
    __shared__ float t[32][33];
    const int n0 = blockIdx.x * 32, k0 = blockIdx.y * 32;
    const int tx = threadIdx.x, ty = threadIdx.y;
#pragma unroll
    for (int i = 0; i < 32; i += 8)
        t[ty + i][tx] = in[(size_t)(k0 + ty + i) * N + n0 + tx];
    __syncthreads();
#pragma unroll
    for (int i = 0; i < 32; i += 8)
        out[(size_t)(n0 + ty + i) * K + k0 + tx] = to_tf32_f(t[tx][ty + i]);
}

// ---------------------------------------------------------------------------
// tf32 mma.sync GEMM: C(MxN) = A(MxK) @ Bt(NxK)^T + bias, optional ReLU.
// 128x128x32 tiles, 8 warps (4x2), cp.async double-buffered smem.
// Smem row stride 36 floats: conflict-free fragment loads, 16B-aligned rows.
// ---------------------------------------------------------------------------
#define MM_STRIDE 36
#define MM_STAGE  (128 * MM_STRIDE)
#define MM_SMEM_BYTES (4 * MM_STAGE * 4)     // 2 stages x (A+B) = 73728 B

template<int RELU>
__global__ __launch_bounds__(256)
void mma_gemm_kernel(const float* __restrict__ A, const float* __restrict__ Bt,
                     const float* __restrict__ bias, float* __restrict__ C,
                     int M, int N, int K)
{
    extern __shared__ float sm[];
    float* As = sm;                       // [2][128][36]
    float* Bs = sm + 2 * MM_STAGE;        // [2][128][36]

    const int tid  = threadIdx.x;
    const int lane = tid & 31, wid = tid >> 5;
    const int wm = wid >> 1, wn = wid & 1;        // 4 x 2 warp grid
    const int grp = lane >> 2, tig = lane & 3;
    const int m0 = blockIdx.y * 128, n0 = blockIdx.x * 128;

    const uint32_t asmem = smem_u32(As);
    const uint32_t bsmem = smem_u32(Bs);

    float acc[2][8][4];
#pragma unroll
    for (int mi = 0; mi < 2; ++mi)
#pragma unroll
        for (int nj = 0; nj < 8; ++nj)
#pragma unroll
            for (int r = 0; r < 4; ++r) acc[mi][nj][r] = 0.f;

    // tile loader: 1024 float4 per operand tile, 4 per thread
    auto load_tiles = [&](int stage, int k0) {
        uint32_t ab = asmem + stage * MM_STAGE * 4;
        uint32_t bb = bsmem + stage * MM_STAGE * 4;
#pragma unroll
        for (int i = 0; i < 4; ++i) {
            int idx = tid + i * 256;
            int r = idx >> 3, c4 = idx & 7;
            cp_async16(ab + (uint32_t)(r * MM_STRIDE + c4 * 4) * 4,
                       A + (size_t)(m0 + r) * K + k0 + c4 * 4);
            cp_async16(bb + (uint32_t)(r * MM_STRIDE + c4 * 4) * 4,
                       Bt + (size_t)(n0 + r) * K + k0 + c4 * 4);
        }
    };

    load_tiles(0, 0);
    asm volatile("cp.async.commit_group;" ::: "memory");

    const int nIt = K / 32;
    for (int it = 0; it < nIt; ++it) {
        if (it + 1 < nIt) {
            load_tiles((it + 1) & 1, (it + 1) * 32);
            asm volatile("cp.async.commit_group;" ::: "memory");
            asm volatile("cp.async.wait_group 1;" ::: "memory");
        } else {
            asm volatile("cp.async.wait_group 0;" ::: "memory");
        }
        __syncthreads();

        const float* a = As + (it & 1) * MM_STAGE;
        const float* b = Bs + (it & 1) * MM_STAGE;

#pragma unroll
        for (int kk = 0; kk < 4; ++kk) {
            const int k = kk * 8;
            uint32_t af[2][4];
#pragma unroll
            for (int mi = 0; mi < 2; ++mi) {
                int r = wm * 32 + mi * 16 + grp;
                af[mi][0] = f2tf32(a[r       * MM_STRIDE + k + tig]);
                af[mi][1] = f2tf32(a[(r + 8) * MM_STRIDE + k + tig]);
                af[mi][2] = f2tf32(a[r       * MM_STRIDE + k + 4 + tig]);
                af[mi][3] = f2tf32(a[(r + 8) * MM_STRIDE + k + 4 + tig]);
            }
#pragma unroll
            for (int nj = 0; nj < 8; ++nj) {
                int nr = wn * 64 + nj * 8 + grp;
                uint32_t b0 = __float_as_uint(b[nr * MM_STRIDE + k + tig]);
                uint32_t b1 = __float_as_uint(b[nr * MM_STRIDE + k + 4 + tig]);
#pragma unroll
                for (int mi = 0; mi < 2; ++mi)
                    mma_tf32(acc[mi][nj], af[mi], b0, b1);
            }
        }
        __syncthreads();
    }

    // Epilogue: bias (+ReLU), direct global write
#pragma unroll
    for (int mi = 0; mi < 2; ++mi) {
        int r = m0 + wm * 32 + mi * 16 + grp;
#pragma unroll
        for (int nj = 0; nj < 8; ++nj) {
            int c = n0 + wn * 64 + nj * 8 + tig * 2;
            float bb0 = bias[c], bb1 = bias[c + 1];
            float v0 = acc[mi][nj][0] + bb0;
            float v1 = acc[mi][nj][1] + bb1;
            float v2 = acc[mi][nj][2] + bb0;
            float v3 = acc[mi][nj][3] + bb1;
            if (RELU) {
                v0 = fmaxf(v0, 0.f); v1 = fmaxf(v1, 0.f);
                v2 = fmaxf(v2, 0.f); v3 = fmaxf(v3, 0.f);
            }
            float2 lo; lo.x = v0; lo.y = v1;
            float2 hi; hi.x = v2; hi.y = v3;
            *(float2*)&C[(size_t)r * N + c]       = lo;
            *(float2*)&C[(size_t)(r + 8) * N + c] = hi;
        }
    }
}

// ---------------------------------------------------------------------------
// PoPE transform
// ---------------------------------------------------------------------------
__device__ __forceinline__ float softplus_f(float x) {
    return fmaxf(x, 0.f) + log1pf(expf(-fabsf(x)));
}

__global__ void pope_kernel(const float* __restrict__ q, const float* __restrict__ k,
                            const int* __restrict__ positions,
                            const float* __restrict__ freqs,
                            const float* __restrict__ phase_bias,
                            float* __restrict__ qp, float* __restrict__ kp)
{
    int idx = blockIdx.x * blockDim.x + threadIdx.x;
    if (idx >= BATCH * NHEADS * SEQ * HEADDIM) return;
    int d = idx & 63;
    int s = (idx >> 6) & (SEQ - 1);
    int h = (idx >> 17) & (NHEADS - 1);
    int b = idx >> 21;

    float qv = q[(size_t)(b * SEQ + s) * DMODEL + h * HEADDIM + d];
    float kv = k[(size_t)(b * SEQ + s) * DMODEL + h * HEADDIM + d];

    float phase = (float)positions[s] * freqs[d] + phase_bias[h * HEADDIM + d];
    float cp, sp;
    sincosf(phase, &sp, &cp);

    float mq = softplus_f(qv) * ATTN_SCALE;
    float mk = softplus_f(kv);

    size_t base = (((size_t)(b * NHEADS + h) * SEQ) + s) * 128 + d;
    qp[base]      = mq * cp;
    qp[base + 64] = mq * sp;
    kp[base]      = mk * cp;
    kp[base + 64] = mk * sp;
}

// ---------------------------------------------------------------------------
// Flash-style causal attention with softmax1
// ---------------------------------------------------------------------------
#define ATN_SMEM_FLOATS (64*128 + 128*65 + 64*64 + 64*64)

__global__ __launch_bounds__(256)
void attn_kernel(const float* __restrict__ qp, const float* __restrict__ kp,
                 const float* __restrict__ v, float* __restrict__ out)
{
    extern __shared__ float sm[];
    float* Qs = sm;                    // 64 x 128
    float* Kt = Qs + 64 * 128;         // 128 x 65 (transposed)
    float* Vs = Kt + 128 * 65;         // 64 x 64
    float* Ps = Vs + 64 * 64;          // 64 x 64

    const int b  = blockIdx.z;
    const int h  = blockIdx.y;
    const int q0 = blockIdx.x * 64;
    const int tid = threadIdx.x;
    const int ty = tid >> 4;
    const int tx = tid & 15;

    const float* qbase = qp + (((size_t)(b * NHEADS + h)) * SEQ) * 128;
    const float* kbase = kp + (((size_t)(b * NHEADS + h)) * SEQ) * 128;

    for (int i = tid; i < 64 * 128 / 4; i += 256)
        ((float4*)Qs)[i] = ((const float4*)(qbase + (size_t)q0 * 128))[i];

    float acc[4][4];
    float mrow[4], lrow[4];
#pragma unroll
    for (int i = 0; i < 4; ++i) {
        mrow[i] = -INFINITY; lrow[i] = 0.f;
#pragma unroll
        for (int j = 0; j < 4; ++j) acc[i][j] = 0.f;
    }

    for (int kt = 0; kt <= q0; kt += 64) {
        __syncthreads();

        for (int i = tid; i < 64 * 128 / 4; i += 256) {
            int r  = i >> 5;
            int c4 = (i & 31) * 4;
            float4 kv4 = ((const float4*)(kbase + (size_t)kt * 128))[i];
            Kt[(c4 + 0) * 65 + r] = kv4.x;
            Kt[(c4 + 1) * 65 + r] = kv4.y;
            Kt[(c4 + 2) * 65 + r] = kv4.z;
            Kt[(c4 + 3) * 65 + r] = kv4.w;
        }
        for (int i = tid; i < 64 * 64 / 4; i += 256) {
            int r  = i >> 4;
            int c4 = (i & 15) * 4;
            float4 vv = *(const float4*)&v[((size_t)b * SEQ + kt + r) * DMODEL + h * HEADDIM + c4];
            *(float4*)&Vs[r * 64 + c4] = vv;
        }
        __syncthreads();

        float s[4][4];
#pragma unroll
        for (int i = 0; i < 4; ++i)
#pragma unroll
            for (int j = 0; j < 4; ++j) s[i][j] = 0.f;

        for (int d = 0; d < 128; ++d) {
            float qv[4], kv[4];
#pragma unroll
            for (int i = 0; i < 4; ++i) qv[i] = Qs[(4 * ty + i) * 128 + d];
#pragma unroll
            for (int j = 0; j < 4; ++j) kv[j] = Kt[d * 65 + 4 * tx + j];
#pragma unroll
            for (int i = 0; i < 4; ++i)
#pragma unroll
                for (int j = 0; j < 4; ++j)
                    s[i][j] = fmaf(qv[i], kv[j], s[i][j]);
        }

        if (kt == q0) {
#pragma unroll
            for (int i = 0; i < 4; ++i)
#pragma unroll
                for (int j = 0; j < 4; ++j)
                    if (4 * tx + j > 4 * ty + i) s[i][j] = -INFINITY;
        }

#pragma unroll
        for (int i = 0; i < 4; ++i) {
            float mx = fmaxf(fmaxf(s[i][0], s[i][1]), fmaxf(s[i][2], s[i][3]));
#pragma unroll
            for (int off = 8; off >= 1; off >>= 1)
                mx = fmaxf(mx, __shfl_xor_sync(0xffffffffu, mx, off));

            float mnew = fmaxf(mrow[i], mx);
            float corr = expf(mrow[i] - mnew);
            mrow[i] = mnew;

            float ls = 0.f;
#pragma unroll
            for (int j = 0; j < 4; ++j) {
                float p = expf(s[i][j] - mnew);
                s[i][j] = p;
                ls += p;
            }
#pragma unroll
            for (int off = 8; off >= 1; off >>= 1)
                ls += __shfl_xor_sync(0xffffffffu, ls, off);

            lrow[i] = lrow[i] * corr + ls;
#pragma unroll
            for (int j = 0; j < 4; ++j) acc[i][j] *= corr;

#pragma unroll
            for (int j = 0; j < 4; ++j)
                Ps[(4 * ty + i) * 64 + 4 * tx + j] = s[i][j];
        }
        __syncthreads();

        for (int kk = 0; kk < 64; ++kk) {
            float pv[4], vv[4];
#pragma unroll
            for (int i = 0; i < 4; ++i) pv[i] = Ps[(4 * ty + i) * 64 + kk];
#pragma unroll
            for (int j = 0; j < 4; ++j) vv[j] = Vs[kk * 64 + 4 * tx + j];
#pragma unroll
            for (int i = 0; i < 4; ++i)
#pragma unroll
                for (int j = 0; j < 4; ++j)
                    acc[i][j] = fmaf(pv[i], vv[j], acc[i][j]);
        }
    }

#pragma unroll
    for (int i = 0; i < 4; ++i) {
        float inv = 1.f / (1.f + lrow[i]);
#pragma unroll
        for (int j = 0; j < 4; ++j) {
            out[((size_t)b * SEQ + q0 + 4 * ty + i) * DMODEL + h * HEADDIM + 4 * tx + j] =
                acc[i][j] * inv;
        }
    }
}

// ---------------------------------------------------------------------------
// Fused residual add + LayerNorm
// ---------------------------------------------------------------------------
__global__ __launch_bounds__(256)
void add_ln_kernel(const float* __restrict__ x, const float* __restrict__ y,
                   const float* __restrict__ g, const float* __restrict__ beta,
                   float* __restrict__ out)
{
    __shared__ float red_s[8];
    __shared__ float red_ss[8];
    __shared__ float s_mu, s_rstd;

    const int row = blockIdx.x;
    const int tid = threadIdx.x;
    const size_t base = (size_t)row * DMODEL;

    float4 xv = ((const float4*)(x + base))[tid];
    float4 yv = ((const float4*)(y + base))[tid];
    float v0 = xv.x + yv.x, v1 = xv.y + yv.y, v2 = xv.z + yv.z, v3 = xv.w + yv.w;

    float sum = v0 + v1 + v2 + v3;
    float ssq = v0 * v0 + v1 * v1 + v2 * v2 + v3 * v3;
#pragma unroll
    for (int off = 16; off >= 1; off >>= 1) {
        sum += __shfl_down_sync(0xffffffffu, sum, off);
        ssq += __shfl_down_sync(0xffffffffu, ssq, off);
    }
    const int warp = tid >> 5;
    if ((tid & 31) == 0) { red_s[warp] = sum; red_ss[warp] = ssq; }
    __syncthreads();
    if (tid == 0) {
        float ts = 0.f, tss = 0.f;
#pragma unroll
        for (int w = 0; w < 8; ++w) { ts += red_s[w]; tss += red_ss[w]; }
        float mu  = ts / (float)DMODEL;
        float var = tss / (float)DMODEL - mu * mu;
        s_mu = mu;
        s_rstd = rsqrtf(var + LN_EPS);
    }
    __syncthreads();
    const float mu = s_mu, rstd = s_rstd;

    float4 gv = ((const float4*)g)[tid];
    float4 bv = ((const float4*)beta)[tid];
    float4 o;
    o.x = (v0 - mu) * rstd * gv.x + bv.x;
    o.y = (v1 - mu) * rstd * gv.y + bv.y;
    o.z = (v2 - mu) * rstd * gv.z + bv.z;
    o.w = (v3 - mu) * rstd * gv.w + bv.w;
    ((float4*)(out + base))[tid] = o;
}

// ---------------------------------------------------------------------------
// Launcher
// ---------------------------------------------------------------------------
extern "C" void kernel_launch(void* const* d_in, const int* in_sizes, int n_in,
                              void* d_out, int out_size)
{
    (void)in_sizes; (void)n_in; (void)out_size;
    const float* x          = (const float*)d_in[0];
    const int*   positions  = (const int*)  d_in[1];
    const float* Wq         = (const float*)d_in[2];
    const float* bq         = (const float*)d_in[3];
    const float* Wk         = (const float*)d_in[4];
    const float* bk         = (const float*)d_in[5];
    const float* Wv         = (const float*)d_in[6];
    const float* bv         = (const float*)d_in[7];
    const float* Wo         = (const float*)d_in[8];
    const float* bo         = (const float*)d_in[9];
    const float* phase_bias = (const float*)d_in[10];
    const float* freqs      = (const float*)d_in[11];
    const float* W1         = (const float*)d_in[12];
    const float* b1         = (const float*)d_in[13];
    const float* W2         = (const float*)d_in[14];
    const float* b2         = (const float*)d_in[15];
    const float* g1         = (const float*)d_in[16];
    const float* beta1      = (const float*)d_in[17];
    const float* g2         = (const float*)d_in[18];
    const float* beta2      = (const float*)d_in[19];
    float* outp             = (float*)d_out;

    float *bufQ, *bufK, *bufV, *bufQP, *bufKP, *bufAttn, *bufX1, *bufFF;
    float *WqT, *WkT, *WvT, *WoT, *W1T, *W2T;
    cudaGetSymbolAddress((void**)&bufQ,    g_bufQ);
    cudaGetSymbolAddress((void**)&bufK,    g_bufK);
    cudaGetSymbolAddress((void**)&bufV,    g_bufV);
    cudaGetSymbolAddress((void**)&bufQP,   g_bufQP);
    cudaGetSymbolAddress((void**)&bufKP,   g_bufKP);
    cudaGetSymbolAddress((void**)&bufAttn, g_bufAttn);
    cudaGetSymbolAddress((void**)&bufX1,   g_bufX1);
    cudaGetSymbolAddress((void**)&bufFF,   g_bufFF);
    cudaGetSymbolAddress((void**)&WqT,     g_WqT);
    cudaGetSymbolAddress((void**)&WkT,     g_WkT);
    cudaGetSymbolAddress((void**)&WvT,     g_WvT);
    cudaGetSymbolAddress((void**)&WoT,     g_WoT);
    cudaGetSymbolAddress((void**)&W1T,     g_W1T);
    cudaGetSymbolAddress((void**)&W2T,     g_W2T);

    static const size_t attn_smem = ATN_SMEM_FLOATS * sizeof(float);
    cudaFuncSetAttribute(attn_kernel, cudaFuncAttributeMaxDynamicSharedMemorySize,
                         (int)attn_smem);
    cudaFuncSetAttribute(mma_gemm_kernel<0>, cudaFuncAttributeMaxDynamicSharedMemorySize,
                         MM_SMEM_BYTES);
    cudaFuncSetAttribute(mma_gemm_kernel<1>, cudaFuncAttributeMaxDynamicSharedMemorySize,
                         MM_SMEM_BYTES);

    // 0: weight transposes (+ tf32 RNA rounding)
    {
        dim3 blk(32, 8);
        transpose_tf32_kernel<<<dim3(DMODEL/32, DMODEL/32), blk>>>(Wq, WqT, DMODEL, DMODEL);
        transpose_tf32_kernel<<<dim3(DMODEL/32, DMODEL/32), blk>>>(Wk, WkT, DMODEL, DMODEL);
        transpose_tf32_kernel<<<dim3(DMODEL/32, DMODEL/32), blk>>>(Wv, WvT, DMODEL, DMODEL);
        transpose_tf32_kernel<<<dim3(DMODEL/32, DMODEL/32), blk>>>(Wo, WoT, DMODEL, DMODEL);
        transpose_tf32_kernel<<<dim3(DFF/32,    DMODEL/32), blk>>>(W1, W1T, DMODEL, DFF);
        transpose_tf32_kernel<<<dim3(DMODEL/32, DFF/32),    blk>>>(W2, W2T, DFF, DMODEL);
    }

    // 1-3: QKV projections (tf32 mma.sync)
    {
        dim3 grid(DMODEL / 128, BS / 128);
        mma_gemm_kernel<0><<<grid, 256, MM_SMEM_BYTES>>>(x, WqT, bq, bufQ, BS, DMODEL, DMODEL);
        mma_gemm_kernel<0><<<grid, 256, MM_SMEM_BYTES>>>(x, WkT, bk, bufK, BS, DMODEL, DMODEL);
        mma_gemm_kernel<0><<<grid, 256, MM_SMEM_BYTES>>>(x, WvT, bv, bufV, BS, DMODEL, DMODEL);
    }

    // 4: PoPE transform
    {
        int total = BATCH * NHEADS * SEQ * HEADDIM;
        pope_kernel<<<(total + 255) / 256, 256>>>(bufQ, bufK, positions, freqs,
                                                  phase_bias, bufQP, bufKP);
    }

    // 5: causal attention with softmax1
    {
        dim3 grid(SEQ / 64, NHEADS, BATCH);
        attn_kernel<<<grid, 256, attn_smem>>>(bufQP, bufKP, bufV, bufAttn);
    }

    // 6: output projection (reuse bufQ)
    {
        dim3 grid(DMODEL / 128, BS / 128);
        mma_gemm_kernel<0><<<grid, 256, MM_SMEM_BYTES>>>(bufAttn, WoT, bo, bufQ, BS, DMODEL, DMODEL);
    }

    // 7: residual + LN1 -> bufX1
    add_ln_kernel<<<BS, 256>>>(x, bufQ, g1, beta1, bufX1);

    // 8: FFN up + ReLU
    {
        dim3 grid(DFF / 128, BS / 128);
        mma_gemm_kernel<1><<<grid, 256, MM_SMEM_BYTES>>>(bufX1, W1T, b1, bufFF, BS, DFF, DMODEL);
    }

    // 9: FFN down (reuse bufK)
    {
        dim3 grid(DMODEL / 128, BS / 128);
        mma_gemm_kernel<0><<<grid, 256, MM_SMEM_BYTES>>>(bufFF, W2T, b2, bufK, BS, DMODEL, DFF);
    }

    // 10: residual + LN2 -> output
    add_ln_kernel<<<BS, 256>>>(bufX1, bufK, g2, beta2, outp);
}

// round 4
// speedup vs baseline: 2.7710x; 1.4433x over previous
#include <cuda_runtime.h>
#include <math.h>
#include <stdint.h>

// ---------------------------------------------------------------------------
// Problem constants
// ---------------------------------------------------------------------------
#define BATCH   2
#define SEQ     2048
#define DMODEL  1024
#define NHEADS  16
#define HEADDIM 64
#define DFF     4096
#define BS      (BATCH * SEQ)          // 4096 rows
#define LN_EPS  1e-5f
#define ATTN_SCALE 0.08838834764831845f   // 1/sqrt(128)

// ---------------------------------------------------------------------------
// Scratch buffers
// ---------------------------------------------------------------------------
__device__ float g_bufQ   [BS * DMODEL];
__device__ float g_bufK   [BS * DMODEL];
__device__ float g_bufV   [BS * DMODEL];
__device__ float g_bufQP  [BATCH * NHEADS * SEQ * 2 * HEADDIM];
__device__ float g_bufKP  [BATCH * NHEADS * SEQ * 2 * HEADDIM];
__device__ float g_bufAttn[BS * DMODEL];
__device__ float g_bufX1  [BS * DMODEL];
__device__ float g_bufFF  [BS * DFF];

// Pre-transposed (tf32-rounded) weights: [N][K]
__device__ float g_WqT[DMODEL * DMODEL];
__device__ float g_WkT[DMODEL * DMODEL];
__device__ float g_WvT[DMODEL * DMODEL];
__device__ float g_WoT[DMODEL * DMODEL];
__device__ float g_W1T[DMODEL * DFF];
__device__ float g_W2T[DFF * DMODEL];

// ---------------------------------------------------------------------------
// Helpers
// ---------------------------------------------------------------------------
__device__ __forceinline__ uint32_t smem_u32(const void* p) {
    uint32_t a;
    asm("{ .reg .u64 t; cvta.to.shared.u64 t, %1; cvt.u32.u64 %0, t; }"
        : "=r"(a) : "l"(p));
    return a;
}

__device__ __forceinline__ float to_tf32_f(float x) {
    float r;
    asm("cvt.rna.tf32.f32 %0, %1;" : "=f"(r) : "f"(x));
    return r;
}

__device__ __forceinline__ uint32_t f2tf32(float x) {
    uint32_t r;
    asm("cvt.rna.tf32.f32 %0, %1;" : "=r"(r) : "f"(x));
    return r;
}

__device__ __forceinline__ void cp_async16(uint32_t saddr, const void* gptr) {
    asm volatile("cp.async.cg.shared.global [%0], [%1], 16;"
                 :: "r"(saddr), "l"(gptr) : "memory");
}

__device__ __forceinline__ void mma_tf32(float (&d)[4],
                                         const uint32_t (&a)[4],
                                         uint32_t b0, uint32_t b1)
{
    asm volatile(
        "mma.sync.aligned.m16n8k8.row.col.f32.tf32.tf32.f32 "
        "{%0,%1,%2,%3}, {%4,%5,%6,%7}, {%8,%9}, {%0,%1,%2,%3};"
        : "+f"(d[0]), "+f"(d[1]), "+f"(d[2]), "+f"(d[3])
        : "r"(a[0]), "r"(a[1]), "r"(a[2]), "r"(a[3]), "r"(b0), "r"(b1));
}

// ---------------------------------------------------------------------------
// Weight transpose + tf32 rounding: in[K][N] -> out[N][K]
// ---------------------------------------------------------------------------
__global__ __launch_bounds__(256)
void transpose_tf32_kernel(const float* __restrict__ in, float* __restrict__ out,
                           int K, int N)
{
    __shared__ float t[32][33];
    const int n0 = blockIdx.x * 32, k0 = blockIdx.y * 32;
    const int tx = threadIdx.x, ty = threadIdx.y;
#pragma unroll
    for (int i = 0; i < 32; i += 8)
        t[ty + i][tx] = in[(size_t)(k0 + ty + i) * N + n0 + tx];
    __syncthreads();
#pragma unroll
    for (int i = 0; i < 32; i += 8)
        out[(size_t)(n0 + ty + i) * K + k0 + tx] = to_tf32_f(t[tx][ty + i]);
}

// ---------------------------------------------------------------------------
// tf32 mma.sync GEMM (unchanged from round 3 pass)
// ---------------------------------------------------------------------------
#define MM_STRIDE 36
#define MM_STAGE  (128 * MM_STRIDE)
#define MM_SMEM_BYTES (4 * MM_STAGE * 4)

template<int RELU>
__global__ __launch_bounds__(256)
void mma_gemm_kernel(const float* __restrict__ A, const float* __restrict__ Bt,
                     const float* __restrict__ bias, float* __restrict__ C,
                     int M, int N, int K)
{
    extern __shared__ float sm[];
    float* As = sm;
    float* Bs = sm + 2 * MM_STAGE;

    const int tid  = threadIdx.x;
    const int lane = tid & 31, wid = tid >> 5;
    const int wm = wid >> 1, wn = wid & 1;
    const int grp = lane >> 2, tig = lane & 3;
    const int m0 = blockIdx.y * 128, n0 = blockIdx.x * 128;

    const uint32_t asmem = smem_u32(As);
    const uint32_t bsmem = smem_u32(Bs);

    float acc[2][8][4];
#pragma unroll
    for (int mi = 0; mi < 2; ++mi)
#pragma unroll
        for (int nj = 0; nj < 8; ++nj)
#pragma unroll
            for (int r = 0; r < 4; ++r) acc[mi][nj][r] = 0.f;

    auto load_tiles = [&](int stage, int k0) {
        uint32_t ab = asmem + stage * MM_STAGE * 4;
        uint32_t bb = bsmem + stage * MM_STAGE * 4;
#pragma unroll
        for (int i = 0; i < 4; ++i) {
            int idx = tid + i * 256;
            int r = idx >> 3, c4 = idx & 7;
            cp_async16(ab + (uint32_t)(r * MM_STRIDE + c4 * 4) * 4,
                       A + (size_t)(m0 + r) * K + k0 + c4 * 4);
            cp_async16(bb + (uint32_t)(r * MM_STRIDE + c4 * 4) * 4,
                       Bt + (size_t)(n0 + r) * K + k0 + c4 * 4);
        }
    };

    load_tiles(0, 0);
    asm volatile("cp.async.commit_group;" ::: "memory");

    const int nIt = K / 32;
    for (int it = 0; it < nIt; ++it) {
        if (it + 1 < nIt) {
            load_tiles((it + 1) & 1, (it + 1) * 32);
            asm volatile("cp.async.commit_group;" ::: "memory");
            asm volatile("cp.async.wait_group 1;" ::: "memory");
        } else {
            asm volatile("cp.async.wait_group 0;" ::: "memory");
        }
        __syncthreads();

        const float* a = As + (it & 1) * MM_STAGE;
        const float* b = Bs + (it & 1) * MM_STAGE;

#pragma unroll
        for (int kk = 0; kk < 4; ++kk) {
            const int k = kk * 8;
            uint32_t af[2][4];
#pragma unroll
            for (int mi = 0; mi < 2; ++mi) {
                int r = wm * 32 + mi * 16 + grp;
                af[mi][0] = f2tf32(a[r       * MM_STRIDE + k + tig]);
                af[mi][1] = f2tf32(a[(r + 8) * MM_STRIDE + k + tig]);
                af[mi][2] = f2tf32(a[r       * MM_STRIDE + k + 4 + tig]);
                af[mi][3] = f2tf32(a[(r + 8) * MM_STRIDE + k + 4 + tig]);
            }
#pragma unroll
            for (int nj = 0; nj < 8; ++nj) {
                int nr = wn * 64 + nj * 8 + grp;
                uint32_t b0 = __float_as_uint(b[nr * MM_STRIDE + k + tig]);
                uint32_t b1 = __float_as_uint(b[nr * MM_STRIDE + k + 4 + tig]);
#pragma unroll
                for (int mi = 0; mi < 2; ++mi)
                    mma_tf32(acc[mi][nj], af[mi], b0, b1);
            }
        }
        __syncthreads();
    }

#pragma unroll
    for (int mi = 0; mi < 2; ++mi) {
        int r = m0 + wm * 32 + mi * 16 + grp;
#pragma unroll
        for (int nj = 0; nj < 8; ++nj) {
            int c = n0 + wn * 64 + nj * 8 + tig * 2;
            float bb0 = bias[c], bb1 = bias[c + 1];
            float v0 = acc[mi][nj][0] + bb0;
            float v1 = acc[mi][nj][1] + bb1;
            float v2 = acc[mi][nj][2] + bb0;
            float v3 = acc[mi][nj][3] + bb1;
            if (RELU) {
                v0 = fmaxf(v0, 0.f); v1 = fmaxf(v1, 0.f);
                v2 = fmaxf(v2, 0.f); v3 = fmaxf(v3, 0.f);
            }
            float2 lo; lo.x = v0; lo.y = v1;
            float2 hi; hi.x = v2; hi.y = v3;
            *(float2*)&C[(size_t)r * N + c]       = lo;
            *(float2*)&C[(size_t)(r + 8) * N + c] = hi;
        }
    }
}

// ---------------------------------------------------------------------------
// PoPE transform
// ---------------------------------------------------------------------------
__device__ __forceinline__ float softplus_f(float x) {
    return fmaxf(x, 0.f) + log1pf(expf(-fabsf(x)));
}

__global__ void pope_kernel(const float* __restrict__ q, const float* __restrict__ k,
                            const int* __restrict__ positions,
                            const float* __restrict__ freqs,
                            const float* __restrict__ phase_bias,
                            float* __restrict__ qp, float* __restrict__ kp)
{
    int idx = blockIdx.x * blockDim.x + threadIdx.x;
    if (idx >= BATCH * NHEADS * SEQ * HEADDIM) return;
    int d = idx & 63;
    int s = (idx >> 6) & (SEQ - 1);
    int h = (idx >> 17) & (NHEADS - 1);
    int b = idx >> 21;

    float qv = q[(size_t)(b * SEQ + s) * DMODEL + h * HEADDIM + d];
    float kv = k[(size_t)(b * SEQ + s) * DMODEL + h * HEADDIM + d];

    float phase = (float)positions[s] * freqs[d] + phase_bias[h * HEADDIM + d];
    float cp, sp;
    sincosf(phase, &sp, &cp);

    float mq = softplus_f(qv) * ATTN_SCALE;
    float mk = softplus_f(kv);

    size_t base = (((size_t)(b * NHEADS + h) * SEQ) + s) * 128 + d;
    qp[base]      = mq * cp;
    qp[base + 64] = mq * sp;
    kp[base]      = mk * cp;
    kp[base + 64] = mk * sp;
}

// ---------------------------------------------------------------------------
// Flash attention with softmax1, tf32 mma.sync.
// 128 q-rows x 64-key tiles, 8 warps (16 q-rows each), 256 threads.
// Q pre-loaded to registers (tf32); P tile aliases Q smem.
// Smem strides 132/68 == 4 (mod 32): conflict-free fragment loads.
// ---------------------------------------------------------------------------
#define AT_BQ 128
#define AT_BK 64
#define AT_QS 132
#define AT_VS 68
#define AT_SMEM_FLOATS (AT_BQ * AT_QS + AT_BK * AT_QS + HEADDIM * AT_VS)
#define AT_SMEM_BYTES  (AT_SMEM_FLOATS * 4)

__global__ __launch_bounds__(256, 1)
void attn_mma_kernel(const float* __restrict__ qp, const float* __restrict__ kp,
                     const float* __restrict__ v, float* __restrict__ out)
{
    extern __shared__ float sm[];
    float* Qs = sm;                       // 128 x 132 (staging only)
    float* Ps = sm;                       // 128 x 68  (aliases Qs)
    float* Ks = sm + AT_BQ * AT_QS;       // 64 x 132
    float* Vt = Ks + AT_BK * AT_QS;       // 64(d) x 68(key), transposed

    const int b = blockIdx.z;
    const int h = blockIdx.y;
    const int qtile = gridDim.x - 1 - blockIdx.x;   // heavy tiles first
    const int q0 = qtile * AT_BQ;

    const int tid  = threadIdx.x;
    const int lane = tid & 31, wid = tid >> 5;
    const int grp = lane >> 2, tig = lane & 3;
    const int r0 = wid * 16 + grp;        // local q row (and r0+8)

    const float* qbase = qp + (((size_t)(b * NHEADS + h)) * SEQ) * 128;
    const float* kbase = kp + (((size_t)(b * NHEADS + h)) * SEQ) * 128;

    // --- Stage Q (tf32) and preload fragments into registers ---
    for (int i = tid; i < AT_BQ * 128 / 4; i += 256) {
        int r = i >> 5, c4 = (i & 31) * 4;
        float4 qv = ((const float4*)(qbase + (size_t)q0 * 128))[i];
        Qs[r * AT_QS + c4 + 0] = to_tf32_f(qv.x);
        Qs[r * AT_QS + c4 + 1] = to_tf32_f(qv.y);
        Qs[r * AT_QS + c4 + 2] = to_tf32_f(qv.z);
        Qs[r * AT_QS + c4 + 3] = to_tf32_f(qv.w);
    }
    __syncthreads();

    uint32_t qf[16][4];
#pragma unroll
    for (int kk = 0; kk < 16; ++kk) {
        int k = kk * 8;
        qf[kk][0] = __float_as_uint(Qs[r0       * AT_QS + k + tig]);
        qf[kk][1] = __float_as_uint(Qs[(r0 + 8) * AT_QS + k + tig]);
        qf[kk][2] = __float_as_uint(Qs[r0       * AT_QS + k + 4 + tig]);
        qf[kk][3] = __float_as_uint(Qs[(r0 + 8) * AT_QS + k + 4 + tig]);
    }
    __syncthreads();   // everyone done reading Qs before Ps overwrites it

    float m0 = -INFINITY, m1 = -INFINITY, l0 = 0.f, l1 = 0.f;
    float o[8][4];
#pragma unroll
    for (int nj = 0; nj < 8; ++nj)
#pragma unroll
        for (int r = 0; r < 4; ++r) o[nj][r] = 0.f;

    for (int kt = 0; kt <= q0 + AT_BQ - AT_BK; kt += AT_BK) {
        __syncthreads();   // protect Ks/Vt from previous iteration reads

        // Load K tile (64 x 128, tf32)
        for (int i = tid; i < AT_BK * 128 / 4; i += 256) {
            int r = i >> 5, c4 = (i & 31) * 4;
            float4 kv = ((const float4*)(kbase + (size_t)kt * 128))[i];
            Ks[r * AT_QS + c4 + 0] = to_tf32_f(kv.x);
            Ks[r * AT_QS + c4 + 1] = to_tf32_f(kv.y);
            Ks[r * AT_QS + c4 + 2] = to_tf32_f(kv.z);
            Ks[r * AT_QS + c4 + 3] = to_tf32_f(kv.w);
        }
        // Load V tile transposed (Vt[d][key], tf32)
        for (int i = tid; i < AT_BK * HEADDIM / 4; i += 256) {
            int r = i >> 4, c4 = (i & 15) * 4;
            float4 vv = *(const float4*)&v[((size_t)b * SEQ + kt + r) * DMODEL + h * HEADDIM + c4];
            Vt[(c4 + 0) * AT_VS + r] = to_tf32_f(vv.x);
            Vt[(c4 + 1) * AT_VS + r] = to_tf32_f(vv.y);
            Vt[(c4 + 2) * AT_VS + r] = to_tf32_f(vv.z);
            Vt[(c4 + 3) * AT_VS + r] = to_tf32_f(vv.w);
        }
        __syncthreads();

        // --- scores = Q @ K^T (128 x 64) ---
        float sacc[8][4];
#pragma unroll
        for (int nj = 0; nj < 8; ++nj)
#pragma unroll
            for (int r = 0; r < 4; ++r) sacc[nj][r] = 0.f;

#pragma unroll
        for (int kk = 0; kk < 16; ++kk) {
            int k = kk * 8;
#pragma unroll
            for (int nj = 0; nj < 8; ++nj) {
                int nr = nj * 8 + grp;
                uint32_t b0 = __float_as_uint(Ks[nr * AT_QS + k + tig]);
                uint32_t b1 = __float_as_uint(Ks[nr * AT_QS + k + 4 + tig]);
                mma_tf32(sacc[nj], qf[kk], b0, b1);
            }
        }

        // --- causal mask (only needed on the last two key tiles) ---
        if (kt >= q0) {
            int row0 = q0 + r0, row1 = row0 + 8;
#pragma unroll
            for (int nj = 0; nj < 8; ++nj) {
                int c = kt + nj * 8 + 2 * tig;
                if (c     > row0) sacc[nj][0] = -INFINITY;
                if (c + 1 > row0) sacc[nj][1] = -INFINITY;
                if (c     > row1) sacc[nj][2] = -INFINITY;
                if (c + 1 > row1) sacc[nj][3] = -INFINITY;
            }
        }

        // --- online softmax1 update (rows live in 4-lane quads) ---
        float mx0 = -INFINITY, mx1 = -INFINITY;
#pragma unroll
        for (int nj = 0; nj < 8; ++nj) {
            mx0 = fmaxf(mx0, fmaxf(sacc[nj][0], sacc[nj][1]));
            mx1 = fmaxf(mx1, fmaxf(sacc[nj][2], sacc[nj][3]));
        }
        mx0 = fmaxf(mx0, __shfl_xor_sync(0xffffffffu, mx0, 1));
        mx0 = fmaxf(mx0, __shfl_xor_sync(0xffffffffu, mx0, 2));
        mx1 = fmaxf(mx1, __shfl_xor_sync(0xffffffffu, mx1, 1));
        mx1 = fmaxf(mx1, __shfl_xor_sync(0xffffffffu, mx1, 2));

        float m0n = fmaxf(m0, mx0), m1n = fmaxf(m1, mx1);
        float c0 = expf(m0 - m0n),  c1 = expf(m1 - m1n);
        m0 = m0n; m1 = m1n;

        float ls0 = 0.f, ls1 = 0.f;
#pragma unroll
        for (int nj = 0; nj < 8; ++nj) {
            float p0 = expf(sacc[nj][0] - m0n);
            float p1 = expf(sacc[nj][1] - m0n);
            float p2 = expf(sacc[nj][2] - m1n);
            float p3 = expf(sacc[nj][3] - m1n);
            ls0 += p0 + p1; ls1 += p2 + p3;
            // store P (tf32) — same-warp rows, read back below
            Ps[r0       * AT_VS + nj * 8 + 2 * tig]     = to_tf32_f(p0);
            Ps[r0       * AT_VS + nj * 8 + 2 * tig + 1] = to_tf32_f(p1);
            Ps[(r0 + 8) * AT_VS + nj * 8 + 2 * tig]     = to_tf32_f(p2);
            Ps[(r0 + 8) * AT_VS + nj * 8 + 2 * tig + 1] = to_tf32_f(p3);
        }
        ls0 += __shfl_xor_sync(0xffffffffu, ls0, 1);
        ls0 += __shfl_xor_sync(0xffffffffu, ls0, 2);
        ls1 += __shfl_xor_sync(0xffffffffu, ls1, 1);
        ls1 += __shfl_xor_sync(0xffffffffu, ls1, 2);
        l0 = l0 * c0 + ls0;
        l1 = l1 * c1 + ls1;

#pragma unroll
        for (int nj = 0; nj < 8; ++nj) {
            o[nj][0] *= c0; o[nj][1] *= c0;
            o[nj][2] *= c1; o[nj][3] *= c1;
        }
        __syncwarp();

        // --- O += P @ V (A=P from smem, B=Vt) ---
#pragma unroll
        for (int kk = 0; kk < 8; ++kk) {
            int k = kk * 8;
            uint32_t af[4];
            af[0] = __float_as_uint(Ps[r0       * AT_VS + k + tig]);
            af[1] = __float_as_uint(Ps[(r0 + 8) * AT_VS + k + tig]);
            af[2] = __float_as_uint(Ps[r0       * AT_VS + k + 4 + tig]);
            af[3] = __float_as_uint(Ps[(r0 + 8) * AT_VS + k + 4 + tig]);
#pragma unroll
            for (int nj = 0; nj < 8; ++nj) {
                int nr = nj * 8 + grp;
                uint32_t b0 = __float_as_uint(Vt[nr * AT_VS + k + tig]);
                uint32_t b1 = __float_as_uint(Vt[nr * AT_VS + k + 4 + tig]);
                mma_tf32(o[nj], af, b0, b1);
            }
        }
    }

    // --- epilogue: softmax1 denominator, write (B,S,D) ---
    float inv0 = 1.f / (1.f + l0);
    float inv1 = 1.f / (1.f + l1);
    int row0 = q0 + r0;
#pragma unroll
    for (int nj = 0; nj < 8; ++nj) {
        int c = h * HEADDIM + nj * 8 + 2 * tig;
        float2 lo; lo.x = o[nj][0] * inv0; lo.y = o[nj][1] * inv0;
        float2 hi; hi.x = o[nj][2] * inv1; hi.y = o[nj][3] * inv1;
        *(float2*)&out[((size_t)b * SEQ + row0)     * DMODEL + c] = lo;
        *(float2*)&out[((size_t)b * SEQ + row0 + 8) * DMODEL + c] = hi;
    }
}

// ---------------------------------------------------------------------------
// Fused residual add + LayerNorm
// ---------------------------------------------------------------------------
__global__ __launch_bounds__(256)
void add_ln_kernel(const float* __restrict__ x, const float* __restrict__ y,
                   const float* __restrict__ g, const float* __restrict__ beta,
                   float* __restrict__ out)
{
    __shared__ float red_s[8];
    __shared__ float red_ss[8];
    __shared__ float s_mu, s_rstd;

    const int row = blockIdx.x;
    const int tid = threadIdx.x;
    const size_t base = (size_t)row * DMODEL;

    float4 xv = ((const float4*)(x + base))[tid];
    float4 yv = ((const float4*)(y + base))[tid];
    float v0 = xv.x + yv.x, v1 = xv.y + yv.y, v2 = xv.z + yv.z, v3 = xv.w + yv.w;

    float sum = v0 + v1 + v2 + v3;
    float ssq = v0 * v0 + v1 * v1 + v2 * v2 + v3 * v3;
#pragma unroll
    for (int off = 16; off >= 1; off >>= 1) {
        sum += __shfl_down_sync(0xffffffffu, sum, off);
        ssq += __shfl_down_sync(0xffffffffu, ssq, off);
    }
    const int warp = tid >> 5;
    if ((tid & 31) == 0) { red_s[warp] = sum; red_ss[warp] = ssq; }
    __syncthreads();
    if (tid == 0) {
        float ts = 0.f, tss = 0.f;
#pragma unroll
        for (int w = 0; w < 8; ++w) { ts += red_s[w]; tss += red_ss[w]; }
        float mu  = ts / (float)DMODEL;
        float var = tss / (float)DMODEL - mu * mu;
        s_mu = mu;
        s_rstd = rsqrtf(var + LN_EPS);
    }
    __syncthreads();
    const float mu = s_mu, rstd = s_rstd;

    float4 gv = ((const float4*)g)[tid];
    float4 bv = ((const float4*)beta)[tid];
    float4 o;
    o.x = (v0 - mu) * rstd * gv.x + bv.x;
    o.y = (v1 - mu) * rstd * gv.y + bv.y;
    o.z = (v2 - mu) * rstd * gv.z + bv.z;
    o.w = (v3 - mu) * rstd * gv.w + bv.w;
    ((float4*)(out + base))[tid] = o;
}

// ---------------------------------------------------------------------------
// Launcher
// ---------------------------------------------------------------------------
extern "C" void kernel_launch(void* const* d_in, const int* in_sizes, int n_in,
                              void* d_out, int out_size)
{
    (void)in_sizes; (void)n_in; (void)out_size;
    const float* x          = (const float*)d_in[0];
    const int*   positions  = (const int*)  d_in[1];
    const float* Wq         = (const float*)d_in[2];
    const float* bq         = (const float*)d_in[3];
    const float* Wk         = (const float*)d_in[4];
    const float* bk         = (const float*)d_in[5];
    const float* Wv         = (const float*)d_in[6];
    const float* bv         = (const float*)d_in[7];
    const float* Wo         = (const float*)d_in[8];
    const float* bo         = (const float*)d_in[9];
    const float* phase_bias = (const float*)d_in[10];
    const float* freqs      = (const float*)d_in[11];
    const float* W1         = (const float*)d_in[12];
    const float* b1         = (const float*)d_in[13];
    const float* W2         = (const float*)d_in[14];
    const float* b2         = (const float*)d_in[15];
    const float* g1         = (const float*)d_in[16];
    const float* beta1      = (const float*)d_in[17];
    const float* g2         = (const float*)d_in[18];
    const float* beta2      = (const float*)d_in[19];
    float* outp             = (float*)d_out;

    float *bufQ, *bufK, *bufV, *bufQP, *bufKP, *bufAttn, *bufX1, *bufFF;
    float *WqT, *WkT, *WvT, *WoT, *W1T, *W2T;
    cudaGetSymbolAddress((void**)&bufQ,    g_bufQ);
    cudaGetSymbolAddress((void**)&bufK,    g_bufK);
    cudaGetSymbolAddress((void**)&bufV,    g_bufV);
    cudaGetSymbolAddress((void**)&bufQP,   g_bufQP);
    cudaGetSymbolAddress((void**)&bufKP,   g_bufKP);
    cudaGetSymbolAddress((void**)&bufAttn, g_bufAttn);
    cudaGetSymbolAddress((void**)&bufX1,   g_bufX1);
    cudaGetSymbolAddress((void**)&bufFF,   g_bufFF);
    cudaGetSymbolAddress((void**)&WqT,     g_WqT);
    cudaGetSymbolAddress((void**)&WkT,     g_WkT);
    cudaGetSymbolAddress((void**)&WvT,     g_WvT);
    cudaGetSymbolAddress((void**)&WoT,     g_WoT);
    cudaGetSymbolAddress((void**)&W1T,     g_W1T);
    cudaGetSymbolAddress((void**)&W2T,     g_W2T);

    cudaFuncSetAttribute(attn_mma_kernel, cudaFuncAttributeMaxDynamicSharedMemorySize,
                         AT_SMEM_BYTES);
    cudaFuncSetAttribute(mma_gemm_kernel<0>, cudaFuncAttributeMaxDynamicSharedMemorySize,
                         MM_SMEM_BYTES);
    cudaFuncSetAttribute(mma_gemm_kernel<1>, cudaFuncAttributeMaxDynamicSharedMemorySize,
                         MM_SMEM_BYTES);

    // 0: weight transposes (+ tf32 RNA rounding)
    {
        dim3 blk(32, 8);
        transpose_tf32_kernel<<<dim3(DMODEL/32, DMODEL/32), blk>>>(Wq, WqT, DMODEL, DMODEL);
        transpose_tf32_kernel<<<dim3(DMODEL/32, DMODEL/32), blk>>>(Wk, WkT, DMODEL, DMODEL);
        transpose_tf32_kernel<<<dim3(DMODEL/32, DMODEL/32), blk>>>(Wv, WvT, DMODEL, DMODEL);
        transpose_tf32_kernel<<<dim3(DMODEL/32, DMODEL/32), blk>>>(Wo, WoT, DMODEL, DMODEL);
        transpose_tf32_kernel<<<dim3(DFF/32,    DMODEL/32), blk>>>(W1, W1T, DMODEL, DFF);
        transpose_tf32_kernel<<<dim3(DMODEL/32, DFF/32),    blk>>>(W2, W2T, DFF, DMODEL);
    }

    // 1-3: QKV projections
    {
        dim3 grid(DMODEL / 128, BS / 128);
        mma_gemm_kernel<0><<<grid, 256, MM_SMEM_BYTES>>>(x, WqT, bq, bufQ, BS, DMODEL, DMODEL);
        mma_gemm_kernel<0><<<grid, 256, MM_SMEM_BYTES>>>(x, WkT, bk, bufK, BS, DMODEL, DMODEL);
        mma_gemm_kernel<0><<<grid, 256, MM_SMEM_BYTES>>>(x, WvT, bv, bufV, BS, DMODEL, DMODEL);
    }

    // 4: PoPE transform
    {
        int total = BATCH * NHEADS * SEQ * HEADDIM;
        pope_kernel<<<(total + 255) / 256, 256>>>(bufQ, bufK, positions, freqs,
                                                  phase_bias, bufQP, bufKP);
    }

    // 5: causal attention with softmax1 (tf32 mma)
    {
        dim3 grid(SEQ / AT_BQ, NHEADS, BATCH);
        attn_mma_kernel<<<grid, 256, AT_SMEM_BYTES>>>(bufQP, bufKP, bufV, bufAttn);
    }

    // 6: output projection (reuse bufQ)
    {
        dim3 grid(DMODEL / 128, BS / 128);
        mma_gemm_kernel<0><<<grid, 256, MM_SMEM_BYTES>>>(bufAttn, WoT, bo, bufQ, BS, DMODEL, DMODEL);
    }

    // 7: residual + LN1 -> bufX1
    add_ln_kernel<<<BS, 256>>>(x, bufQ, g1, beta1, bufX1);

    // 8: FFN up + ReLU
    {
        dim3 grid(DFF / 128, BS / 128);
        mma_gemm_kernel<1><<<grid, 256, MM_SMEM_BYTES>>>(bufX1, W1T, b1, bufFF, BS, DFF, DMODEL);
    }

    // 9: FFN down (reuse bufK)
    {
        dim3 grid(DMODEL / 128, BS / 128);
        mma_gemm_kernel<0><<<grid, 256, MM_SMEM_BYTES>>>(bufFF, W2T, b2, bufK, BS, DMODEL, DFF);
    }

    // 10: residual + LN2 -> output
    add_ln_kernel<<<BS, 256>>>(bufX1, bufK, g2, beta2, outp);
}

// round 5
// speedup vs baseline: 2.8481x; 1.0278x over previous
#include <cuda_runtime.h>
#include <math.h>
#include <stdint.h>

// ---------------------------------------------------------------------------
// Problem constants
// ---------------------------------------------------------------------------
#define BATCH   2
#define SEQ     2048
#define DMODEL  1024
#define NHEADS  16
#define HEADDIM 64
#define DFF     4096
#define BS      (BATCH * SEQ)          // 4096 rows
#define LN_EPS  1e-5f
#define ATTN_SCALE 0.08838834764831845f   // 1/sqrt(128)

// ---------------------------------------------------------------------------
// Scratch buffers
// ---------------------------------------------------------------------------
__device__ float g_bufQ   [BS * DMODEL];
__device__ float g_bufK   [BS * DMODEL];
__device__ float g_bufV   [BS * DMODEL];
__device__ float g_bufQP  [BATCH * NHEADS * SEQ * 2 * HEADDIM];
__device__ float g_bufKP  [BATCH * NHEADS * SEQ * 2 * HEADDIM];
__device__ float g_bufAttn[BS * DMODEL];
__device__ float g_bufX1  [BS * DMODEL];
__device__ float g_bufFF  [BS * DFF];

// Pre-transposed (tf32-rounded) weights: [N][K]
__device__ float g_WqT[DMODEL * DMODEL];
__device__ float g_WkT[DMODEL * DMODEL];
__device__ float g_WvT[DMODEL * DMODEL];
__device__ float g_WoT[DMODEL * DMODEL];
__device__ float g_W1T[DMODEL * DFF];
__device__ float g_W2T[DFF * DMODEL];

// ---------------------------------------------------------------------------
// Helpers
// ---------------------------------------------------------------------------
__device__ __forceinline__ uint32_t smem_u32(const void* p) {
    uint32_t a;
    asm("{ .reg .u64 t; cvta.to.shared.u64 t, %1; cvt.u32.u64 %0, t; }"
        : "=r"(a) : "l"(p));
    return a;
}

__device__ __forceinline__ float to_tf32_f(float x) {
    float r;
    asm("cvt.rna.tf32.f32 %0, %1;" : "=f"(r) : "f"(x));
    return r;
}

__device__ __forceinline__ void cp_async16(uint32_t saddr, const void* gptr) {
    asm volatile("cp.async.cg.shared.global [%0], [%1], 16;"
                 :: "r"(saddr), "l"(gptr) : "memory");
}

__device__ __forceinline__ void mma_tf32(float (&d)[4],
                                         const uint32_t (&a)[4],
                                         uint32_t b0, uint32_t b1)
{
    asm volatile(
        "mma.sync.aligned.m16n8k8.row.col.f32.tf32.tf32.f32 "
        "{%0,%1,%2,%3}, {%4,%5,%6,%7}, {%8,%9}, {%0,%1,%2,%3};"
        : "+f"(d[0]), "+f"(d[1]), "+f"(d[2]), "+f"(d[3])
        : "r"(a[0]), "r"(a[1]), "r"(a[2]), "r"(a[3]), "r"(b0), "r"(b1));
}

// ---------------------------------------------------------------------------
// Weight transpose + tf32 rounding: in[K][N] -> out[N][K]
// ---------------------------------------------------------------------------
__global__ __launch_bounds__(256)
void transpose_tf32_kernel(const float* __restrict__ in, float* __restrict__ out,
                           int K, int N)
{
    __shared__ float t[32][33];
    const int n0 = blockIdx.x * 32, k0 = blockIdx.y * 32;
    const int tx = threadIdx.x, ty = threadIdx.y;
#pragma unroll
    for (int i = 0; i < 32; i += 8)
        t[ty + i][tx] = in[(size_t)(k0 + ty + i) * N + n0 + tx];
    __syncthreads();
#pragma unroll
    for (int i = 0; i < 32; i += 8)
        out[(size_t)(n0 + ty + i) * K + k0 + tx] = to_tf32_f(t[tx][ty + i]);
}

// ---------------------------------------------------------------------------
// tf32 mma.sync GEMM: C(MxN) = A(MxK) @ Bt(NxK)^T + bias, optional ReLU.
// 128x128x32 tiles, 8 warps (4x2), cp.async double-buffered smem.
// __launch_bounds__(256,2): 2 CTAs/SM (regs<=112, 144KB smem/SM) so the
// 256-CTA grids (QKV/Wo/FFN-down) fit in ONE wave (296 slots).
// A fragments fed as raw fp32 bits (HW tf32-truncates); B pre-rounded RNA.
// ---------------------------------------------------------------------------
#define MM_STRIDE 36
#define MM_STAGE  (128 * MM_STRIDE)
#define MM_SMEM_BYTES (4 * MM_STAGE * 4)     // 73728 B

template<int RELU>
__global__ __launch_bounds__(256, 2)
void mma_gemm_kernel(const float* __restrict__ A, const float* __restrict__ Bt,
                     const float* __restrict__ bias, float* __restrict__ C,
                     int M, int N, int K)
{
    extern __shared__ float sm[];
    float* As = sm;
    float* Bs = sm + 2 * MM_STAGE;

    const int tid  = threadIdx.x;
    const int lane = tid & 31, wid = tid >> 5;
    const int wm = wid >> 1, wn = wid & 1;
    const int grp = lane >> 2, tig = lane & 3;
    const int m0 = blockIdx.y * 128, n0 = blockIdx.x * 128;

    const uint32_t asmem = smem_u32(As);
    const uint32_t bsmem = smem_u32(Bs);

    float acc[2][8][4];
#pragma unroll
    for (int mi = 0; mi < 2; ++mi)
#pragma unroll
        for (int nj = 0; nj < 8; ++nj)
#pragma unroll
            for (int r = 0; r < 4; ++r) acc[mi][nj][r] = 0.f;

    auto load_tiles = [&](int stage, int k0) {
        uint32_t ab = asmem + stage * MM_STAGE * 4;
        uint32_t bb = bsmem + stage * MM_STAGE * 4;
#pragma unroll
        for (int i = 0; i < 4; ++i) {
            int idx = tid + i * 256;
            int r = idx >> 3, c4 = idx & 7;
            cp_async16(ab + (uint32_t)(r * MM_STRIDE + c4 * 4) * 4,
                       A + (size_t)(m0 + r) * K + k0 + c4 * 4);
            cp_async16(bb + (uint32_t)(r * MM_STRIDE + c4 * 4) * 4,
                       Bt + (size_t)(n0 + r) * K + k0 + c4 * 4);
        }
    };

    load_tiles(0, 0);
    asm volatile("cp.async.commit_group;" ::: "memory");

    const int nIt = K / 32;
    for (int it = 0; it < nIt; ++it) {
        if (it + 1 < nIt) {
            load_tiles((it + 1) & 1, (it + 1) * 32);
            asm volatile("cp.async.commit_group;" ::: "memory");
            asm volatile("cp.async.wait_group 1;" ::: "memory");
        } else {
            asm volatile("cp.async.wait_group 0;" ::: "memory");
        }
        __syncthreads();

        const float* a = As + (it & 1) * MM_STAGE;
        const float* b = Bs + (it & 1) * MM_STAGE;

#pragma unroll
        for (int kk = 0; kk < 4; ++kk) {
            const int k = kk * 8;
            uint32_t af[2][4];
#pragma unroll
            for (int mi = 0; mi < 2; ++mi) {
                int r = wm * 32 + mi * 16 + grp;
                af[mi][0] = __float_as_uint(a[r       * MM_STRIDE + k + tig]);
                af[mi][1] = __float_as_uint(a[(r + 8) * MM_STRIDE + k + tig]);
                af[mi][2] = __float_as_uint(a[r       * MM_STRIDE + k + 4 + tig]);
                af[mi][3] = __float_as_uint(a[(r + 8) * MM_STRIDE + k + 4 + tig]);
            }
#pragma unroll
            for (int nj = 0; nj < 8; ++nj) {
                int nr = wn * 64 + nj * 8 + grp;
                uint32_t b0 = __float_as_uint(b[nr * MM_STRIDE + k + tig]);
                uint32_t b1 = __float_as_uint(b[nr * MM_STRIDE + k + 4 + tig]);
#pragma unroll
                for (int mi = 0; mi < 2; ++mi)
                    mma_tf32(acc[mi][nj], af[mi], b0, b1);
            }
        }
        __syncthreads();
    }

#pragma unroll
    for (int mi = 0; mi < 2; ++mi) {
        int r = m0 + wm * 32 + mi * 16 + grp;
#pragma unroll
        for (int nj = 0; nj < 8; ++nj) {
            int c = n0 + wn * 64 + nj * 8 + tig * 2;
            float bb0 = bias[c], bb1 = bias[c + 1];
            float v0 = acc[mi][nj][0] + bb0;
            float v1 = acc[mi][nj][1] + bb1;
            float v2 = acc[mi][nj][2] + bb0;
            float v3 = acc[mi][nj][3] + bb1;
            if (RELU) {
                v0 = fmaxf(v0, 0.f); v1 = fmaxf(v1, 0.f);
                v2 = fmaxf(v2, 0.f); v3 = fmaxf(v3, 0.f);
            }
            float2 lo; lo.x = v0; lo.y = v1;
            float2 hi; hi.x = v2; hi.y = v3;
            *(float2*)&C[(size_t)r * N + c]       = lo;
            *(float2*)&C[(size_t)(r + 8) * N + c] = hi;
        }
    }
}

// ---------------------------------------------------------------------------
// PoPE transform
// ---------------------------------------------------------------------------
__device__ __forceinline__ float softplus_f(float x) {
    return fmaxf(x, 0.f) + log1pf(expf(-fabsf(x)));
}

__global__ void pope_kernel(const float* __restrict__ q, const float* __restrict__ k,
                            const int* __restrict__ positions,
                            const float* __restrict__ freqs,
                            const float* __restrict__ phase_bias,
                            float* __restrict__ qp, float* __restrict__ kp)
{
    int idx = blockIdx.x * blockDim.x + threadIdx.x;
    if (idx >= BATCH * NHEADS * SEQ * HEADDIM) return;
    int d = idx & 63;
    int s = (idx >> 6) & (SEQ - 1);
    int h = (idx >> 17) & (NHEADS - 1);
    int b = idx >> 21;

    float qv = q[(size_t)(b * SEQ + s) * DMODEL + h * HEADDIM + d];
    float kv = k[(size_t)(b * SEQ + s) * DMODEL + h * HEADDIM + d];

    float phase = (float)positions[s] * freqs[d] + phase_bias[h * HEADDIM + d];
    float cp, sp;
    sincosf(phase, &sp, &cp);

    float mq = softplus_f(qv) * ATTN_SCALE;
    float mk = softplus_f(kv);

    size_t base = (((size_t)(b * NHEADS + h) * SEQ) + s) * 128 + d;
    qp[base]      = mq * cp;
    qp[base + 64] = mq * sp;
    kp[base]      = mk * cp;
    kp[base + 64] = mk * sp;
}

// ---------------------------------------------------------------------------
// Flash attention with softmax1, tf32 mma.sync (unchanged from round 4 pass)
// ---------------------------------------------------------------------------
#define AT_BQ 128
#define AT_BK 64
#define AT_QS 132
#define AT_VS 68
#define AT_SMEM_FLOATS (AT_BQ * AT_QS + AT_BK * AT_QS + HEADDIM * AT_VS)
#define AT_SMEM_BYTES  (AT_SMEM_FLOATS * 4)

__global__ __launch_bounds__(256, 1)
void attn_mma_kernel(const float* __restrict__ qp, const float* __restrict__ kp,
                     const float* __restrict__ v, float* __restrict__ out)
{
    extern __shared__ float sm[];
    float* Qs = sm;                       // 128 x 132 (staging only)
    float* Ps = sm;                       // 128 x 68  (aliases Qs)
    float* Ks = sm + AT_BQ * AT_QS;       // 64 x 132
    float* Vt = Ks + AT_BK * AT_QS;       // 64(d) x 68(key), transposed

    const int b = blockIdx.z;
    const int h = blockIdx.y;
    const int qtile = gridDim.x - 1 - blockIdx.x;   // heavy tiles first
    const int q0 = qtile * AT_BQ;

    const int tid  = threadIdx.x;
    const int lane = tid & 31, wid = tid >> 5;
    const int grp = lane >> 2, tig = lane & 3;
    const int r0 = wid * 16 + grp;        // local q row (and r0+8)

    const float* qbase = qp + (((size_t)(b * NHEADS + h)) * SEQ) * 128;
    const float* kbase = kp + (((size_t)(b * NHEADS + h)) * SEQ) * 128;

    for (int i = tid; i < AT_BQ * 128 / 4; i += 256) {
        int r = i >> 5, c4 = (i & 31) * 4;
        float4 qv = ((const float4*)(qbase + (size_t)q0 * 128))[i];
        Qs[r * AT_QS + c4 + 0] = to_tf32_f(qv.x);
        Qs[r * AT_QS + c4 + 1] = to_tf32_f(qv.y);
        Qs[r * AT_QS + c4 + 2] = to_tf32_f(qv.z);
        Qs[r * AT_QS + c4 + 3] = to_tf32_f(qv.w);
    }
    __syncthreads();

    uint32_t qf[16][4];
#pragma unroll
    for (int kk = 0; kk < 16; ++kk) {
        int k = kk * 8;
        qf[kk][0] = __float_as_uint(Qs[r0       * AT_QS + k + tig]);
        qf[kk][1] = __float_as_uint(Qs[(r0 + 8) * AT_QS + k + tig]);
        qf[kk][2] = __float_as_uint(Qs[r0       * AT_QS + k + 4 + tig]);
        qf[kk][3] = __float_as_uint(Qs[(r0 + 8) * AT_QS + k + 4 + tig]);
    }
    __syncthreads();   // everyone done reading Qs before Ps overwrites it

    float m0 = -INFINITY, m1 = -INFINITY, l0 = 0.f, l1 = 0.f;
    float o[8][4];
#pragma unroll
    for (int nj = 0; nj < 8; ++nj)
#pragma unroll
        for (int r = 0; r < 4; ++r) o[nj][r] = 0.f;

    for (int kt = 0; kt <= q0 + AT_BQ - AT_BK; kt += AT_BK) {
        __syncthreads();

        for (int i = tid; i < AT_BK * 128 / 4; i += 256) {
            int r = i >> 5, c4 = (i & 31) * 4;
            float4 kv = ((const float4*)(kbase + (size_t)kt * 128))[i];
            Ks[r * AT_QS + c4 + 0] = to_tf32_f(kv.x);
            Ks[r * AT_QS + c4 + 1] = to_tf32_f(kv.y);
            Ks[r * AT_QS + c4 + 2] = to_tf32_f(kv.z);
            Ks[r * AT_QS + c4 + 3] = to_tf32_f(kv.w);
        }
        for (int i = tid; i < AT_BK * HEADDIM / 4; i += 256) {
            int r = i >> 4, c4 = (i & 15) * 4;
            float4 vv = *(const float4*)&v[((size_t)b * SEQ + kt + r) * DMODEL + h * HEADDIM + c4];
            Vt[(c4 + 0) * AT_VS + r] = to_tf32_f(vv.x);
            Vt[(c4 + 1) * AT_VS + r] = to_tf32_f(vv.y);
            Vt[(c4 + 2) * AT_VS + r] = to_tf32_f(vv.z);
            Vt[(c4 + 3) * AT_VS + r] = to_tf32_f(vv.w);
        }
        __syncthreads();

        float sacc[8][4];
#pragma unroll
        for (int nj = 0; nj < 8; ++nj)
#pragma unroll
            for (int r = 0; r < 4; ++r) sacc[nj][r] = 0.f;

#pragma unroll
        for (int kk = 0; kk < 16; ++kk) {
            int k = kk * 8;
#pragma unroll
            for (int nj = 0; nj < 8; ++nj) {
                int nr = nj * 8 + grp;
                uint32_t b0 = __float_as_uint(Ks[nr * AT_QS + k + tig]);
                uint32_t b1 = __float_as_uint(Ks[nr * AT_QS + k + 4 + tig]);
                mma_tf32(sacc[nj], qf[kk], b0, b1);
            }
        }

        if (kt >= q0) {
            int row0 = q0 + r0, row1 = row0 + 8;
#pragma unroll
            for (int nj = 0; nj < 8; ++nj) {
                int c = kt + nj * 8 + 2 * tig;
                if (c     > row0) sacc[nj][0] = -INFINITY;
                if (c + 1 > row0) sacc[nj][1] = -INFINITY;
                if (c     > row1) sacc[nj][2] = -INFINITY;
                if (c + 1 > row1) sacc[nj][3] = -INFINITY;
            }
        }

        float mx0 = -INFINITY, mx1 = -INFINITY;
#pragma unroll
        for (int nj = 0; nj < 8; ++nj) {
            mx0 = fmaxf(mx0, fmaxf(sacc[nj][0], sacc[nj][1]));
            mx1 = fmaxf(mx1, fmaxf(sacc[nj][2], sacc[nj][3]));
        }
        mx0 = fmaxf(mx0, __shfl_xor_sync(0xffffffffu, mx0, 1));
        mx0 = fmaxf(mx0, __shfl_xor_sync(0xffffffffu, mx0, 2));
        mx1 = fmaxf(mx1, __shfl_xor_sync(0xffffffffu, mx1, 1));
        mx1 = fmaxf(mx1, __shfl_xor_sync(0xffffffffu, mx1, 2));

        float m0n = fmaxf(m0, mx0), m1n = fmaxf(m1, mx1);
        float c0 = expf(m0 - m0n),  c1 = expf(m1 - m1n);
        m0 = m0n; m1 = m1n;

        float ls0 = 0.f, ls1 = 0.f;
#pragma unroll
        for (int nj = 0; nj < 8; ++nj) {
            float p0 = expf(sacc[nj][0] - m0n);
            float p1 = expf(sacc[nj][1] - m0n);
            float p2 = expf(sacc[nj][2] - m1n);
            float p3 = expf(sacc[nj][3] - m1n);
            ls0 += p0 + p1; ls1 += p2 + p3;
            Ps[r0       * AT_VS + nj * 8 + 2 * tig]     = to_tf32_f(p0);
            Ps[r0       * AT_VS + nj * 8 + 2 * tig + 1] = to_tf32_f(p1);
            Ps[(r0 + 8) * AT_VS + nj * 8 + 2 * tig]     = to_tf32_f(p2);
            Ps[(r0 + 8) * AT_VS + nj * 8 + 2 * tig + 1] = to_tf32_f(p3);
        }
        ls0 += __shfl_xor_sync(0xffffffffu, ls0, 1);
        ls0 += __shfl_xor_sync(0xffffffffu, ls0, 2);
        ls1 += __shfl_xor_sync(0xffffffffu, ls1, 1);
        ls1 += __shfl_xor_sync(0xffffffffu, ls1, 2);
        l0 = l0 * c0 + ls0;
        l1 = l1 * c1 + ls1;

#pragma unroll
        for (int nj = 0; nj < 8; ++nj) {
            o[nj][0] *= c0; o[nj][1] *= c0;
            o[nj][2] *= c1; o[nj][3] *= c1;
        }
        __syncwarp();

#pragma unroll
        for (int kk = 0; kk < 8; ++kk) {
            int k = kk * 8;
            uint32_t af[4];
            af[0] = __float_as_uint(Ps[r0       * AT_VS + k + tig]);
            af[1] = __float_as_uint(Ps[(r0 + 8) * AT_VS + k + tig]);
            af[2] = __float_as_uint(Ps[r0       * AT_VS + k + 4 + tig]);
            af[3] = __float_as_uint(Ps[(r0 + 8) * AT_VS + k + 4 + tig]);
#pragma unroll
            for (int nj = 0; nj < 8; ++nj) {
                int nr = nj * 8 + grp;
                uint32_t b0 = __float_as_uint(Vt[nr * AT_VS + k + tig]);
                uint32_t b1 = __float_as_uint(Vt[nr * AT_VS + k + 4 + tig]);
                mma_tf32(o[nj], af, b0, b1);
            }
        }
    }

    float inv0 = 1.f / (1.f + l0);
    float inv1 = 1.f / (1.f + l1);
    int row0 = q0 + r0;
#pragma unroll
    for (int nj = 0; nj < 8; ++nj) {
        int c = h * HEADDIM + nj * 8 + 2 * tig;
        float2 lo; lo.x = o[nj][0] * inv0; lo.y = o[nj][1] * inv0;
        float2 hi; hi.x = o[nj][2] * inv1; hi.y = o[nj][3] * inv1;
        *(float2*)&out[((size_t)b * SEQ + row0)     * DMODEL + c] = lo;
        *(float2*)&out[((size_t)b * SEQ + row0 + 8) * DMODEL + c] = hi;
    }
}

// ---------------------------------------------------------------------------
// Fused residual add + LayerNorm
// ---------------------------------------------------------------------------
__global__ __launch_bounds__(256)
void add_ln_kernel(const float* __restrict__ x, const float* __restrict__ y,
                   const float* __restrict__ g, const float* __restrict__ beta,
                   float* __restrict__ out)
{
    __shared__ float red_s[8];
    __shared__ float red_ss[8];
    __shared__ float s_mu, s_rstd;

    const int row = blockIdx.x;
    const int tid = threadIdx.x;
    const size_t base = (size_t)row * DMODEL;

    float4 xv = ((const float4*)(x + base))[tid];
    float4 yv = ((const float4*)(y + base))[tid];
    float v0 = xv.x + yv.x, v1 = xv.y + yv.y, v2 = xv.z + yv.z, v3 = xv.w + yv.w;

    float sum = v0 + v1 + v2 + v3;
    float ssq = v0 * v0 + v1 * v1 + v2 * v2 + v3 * v3;
#pragma unroll
    for (int off = 16; off >= 1; off >>= 1) {
        sum += __shfl_down_sync(0xffffffffu, sum, off);
        ssq += __shfl_down_sync(0xffffffffu, ssq, off);
    }
    const int warp = tid >> 5;
    if ((tid & 31) == 0) { red_s[warp] = sum; red_ss[warp] = ssq; }
    __syncthreads();
    if (tid == 0) {
        float ts = 0.f, tss = 0.f;
#pragma unroll
        for (int w = 0; w < 8; ++w) { ts += red_s[w]; tss += red_ss[w]; }
        float mu  = ts / (float)DMODEL;
        float var = tss / (float)DMODEL - mu * mu;
        s_mu = mu;
        s_rstd = rsqrtf(var + LN_EPS);
    }
    __syncthreads();
    const float mu = s_mu, rstd = s_rstd;

    float4 gv = ((const float4*)g)[tid];
    float4 bv = ((const float4*)beta)[tid];
    float4 o;
    o.x = (v0 - mu) * rstd * gv.x + bv.x;
    o.y = (v1 - mu) * rstd * gv.y + bv.y;
    o.z = (v2 - mu) * rstd * gv.z + bv.z;
    o.w = (v3 - mu) * rstd * gv.w + bv.w;
    ((float4*)(out + base))[tid] = o;
}

// ---------------------------------------------------------------------------
// Launcher
// ---------------------------------------------------------------------------
extern "C" void kernel_launch(void* const* d_in, const int* in_sizes, int n_in,
                              void* d_out, int out_size)
{
    (void)in_sizes; (void)n_in; (void)out_size;
    const float* x          = (const float*)d_in[0];
    const int*   positions  = (const int*)  d_in[1];
    const float* Wq         = (const float*)d_in[2];
    const float* bq         = (const float*)d_in[3];
    const float* Wk         = (const float*)d_in[4];
    const float* bk         = (const float*)d_in[5];
    const float* Wv         = (const float*)d_in[6];
    const float* bv         = (const float*)d_in[7];
    const float* Wo         = (const float*)d_in[8];
    const float* bo         = (const float*)d_in[9];
    const float* phase_bias = (const float*)d_in[10];
    const float* freqs      = (const float*)d_in[11];
    const float* W1         = (const float*)d_in[12];
    const float* b1         = (const float*)d_in[13];
    const float* W2         = (const float*)d_in[14];
    const float* b2         = (const float*)d_in[15];
    const float* g1         = (const float*)d_in[16];
    const float* beta1      = (const float*)d_in[17];
    const float* g2         = (const float*)d_in[18];
    const float* beta2      = (const float*)d_in[19];
    float* outp             = (float*)d_out;

    float *bufQ, *bufK, *bufV, *bufQP, *bufKP, *bufAttn, *bufX1, *bufFF;
    float *WqT, *WkT, *WvT, *WoT, *W1T, *W2T;
    cudaGetSymbolAddress((void**)&bufQ,    g_bufQ);
    cudaGetSymbolAddress((void**)&bufK,    g_bufK);
    cudaGetSymbolAddress((void**)&bufV,    g_bufV);
    cudaGetSymbolAddress((void**)&bufQP,   g_bufQP);
    cudaGetSymbolAddress((void**)&bufKP,   g_bufKP);
    cudaGetSymbolAddress((void**)&bufAttn, g_bufAttn);
    cudaGetSymbolAddress((void**)&bufX1,   g_bufX1);
    cudaGetSymbolAddress((void**)&bufFF,   g_bufFF);
    cudaGetSymbolAddress((void**)&WqT,     g_WqT);
    cudaGetSymbolAddress((void**)&WkT,     g_WkT);
    cudaGetSymbolAddress((void**)&WvT,     g_WvT);
    cudaGetSymbolAddress((void**)&WoT,     g_WoT);
    cudaGetSymbolAddress((void**)&W1T,     g_W1T);
    cudaGetSymbolAddress((void**)&W2T,     g_W2T);

    cudaFuncSetAttribute(attn_mma_kernel, cudaFuncAttributeMaxDynamicSharedMemorySize,
                         AT_SMEM_BYTES);
    cudaFuncSetAttribute(mma_gemm_kernel<0>, cudaFuncAttributeMaxDynamicSharedMemorySize,
                         MM_SMEM_BYTES);
    cudaFuncSetAttribute(mma_gemm_kernel<1>, cudaFuncAttributeMaxDynamicSharedMemorySize,
                         MM_SMEM_BYTES);

    // 0: weight transposes (+ tf32 RNA rounding)
    {
        dim3 blk(32, 8);
        transpose_tf32_kernel<<<dim3(DMODEL/32, DMODEL/32), blk>>>(Wq, WqT, DMODEL, DMODEL);
        transpose_tf32_kernel<<<dim3(DMODEL/32, DMODEL/32), blk>>>(Wk, WkT, DMODEL, DMODEL);
        transpose_tf32_kernel<<<dim3(DMODEL/32, DMODEL/32), blk>>>(Wv, WvT, DMODEL, DMODEL);
        transpose_tf32_kernel<<<dim3(DMODEL/32, DMODEL/32), blk>>>(Wo, WoT, DMODEL, DMODEL);
        transpose_tf32_kernel<<<dim3(DFF/32,    DMODEL/32), blk>>>(W1, W1T, DMODEL, DFF);
        transpose_tf32_kernel<<<dim3(DMODEL/32, DFF/32),    blk>>>(W2, W2T, DFF, DMODEL);
    }

    // 1-3: QKV projections
    {
        dim3 grid(DMODEL / 128, BS / 128);
        mma_gemm_kernel<0><<<grid, 256, MM_SMEM_BYTES>>>(x, WqT, bq, bufQ, BS, DMODEL, DMODEL);
        mma_gemm_kernel<0><<<grid, 256, MM_SMEM_BYTES>>>(x, WkT, bk, bufK, BS, DMODEL, DMODEL);
        mma_gemm_kernel<0><<<grid, 256, MM_SMEM_BYTES>>>(x, WvT, bv, bufV, BS, DMODEL, DMODEL);
    }

    // 4: PoPE transform
    {
        int total = BATCH * NHEADS * SEQ * HEADDIM;
        pope_kernel<<<(total + 255) / 256, 256>>>(bufQ, bufK, positions, freqs,
                                                  phase_bias, bufQP, bufKP);
    }

    // 5: causal attention with softmax1 (tf32 mma)
    {
        dim3 grid(SEQ / AT_BQ, NHEADS, BATCH);
        attn_mma_kernel<<<grid, 256, AT_SMEM_BYTES>>>(bufQP, bufKP, bufV, bufAttn);
    }

    // 6: output projection (reuse bufQ)
    {
        dim3 grid(DMODEL / 128, BS / 128);
        mma_gemm_kernel<0><<<grid, 256, MM_SMEM_BYTES>>>(bufAttn, WoT, bo, bufQ, BS, DMODEL, DMODEL);
    }

    // 7: residual + LN1 -> bufX1
    add_ln_kernel<<<BS, 256>>>(x, bufQ, g1, beta1, bufX1);

    // 8: FFN up + ReLU
    {
        dim3 grid(DFF / 128, BS / 128);
        mma_gemm_kernel<1><<<grid, 256, MM_SMEM_BYTES>>>(bufX1, W1T, b1, bufFF, BS, DFF, DMODEL);
    }

    // 9: FFN down (reuse bufK)
    {
        dim3 grid(DMODEL / 128, BS / 128);
        mma_gemm_kernel<0><<<grid, 256, MM_SMEM_BYTES>>>(bufFF, W2T, b2, bufK, BS, DMODEL, DFF);
    }

    // 10: residual + LN2 -> output
    add_ln_kernel<<<BS, 256>>>(bufX1, bufK, g2, beta2, outp);
}

// round 6
// speedup vs baseline: 4.4599x; 1.5659x over previous
#include <cuda_runtime.h>
#include <cuda_fp16.h>
#include <math.h>
#include <stdint.h>

// ---------------------------------------------------------------------------
// Problem constants
// ---------------------------------------------------------------------------
#define BATCH   2
#define SEQ     2048
#define DMODEL  1024
#define NHEADS  16
#define HEADDIM 64
#define DFF     4096
#define BS      (BATCH * SEQ)          // 4096 rows
#define LN_EPS  1e-5f
#define ATTN_SCALE 0.08838834764831845f   // 1/sqrt(128)

// ---------------------------------------------------------------------------
// Scratch buffers
// ---------------------------------------------------------------------------
__device__ float  g_bufQ   [BS * DMODEL];            // Q raw (fp32, pope input); reused Wo out
__device__ float  g_bufK   [BS * DMODEL];            // K raw (fp32); reused FFN2 out
__device__ float  g_bufX1  [BS * DMODEL];            // LN1 out fp32
__device__ __half g_xh     [BS * DMODEL];            // x in fp16
__device__ __half g_bufVh  [BS * DMODEL];            // V fp16
__device__ __half g_QPh    [BATCH * NHEADS * SEQ * 2 * HEADDIM];
__device__ __half g_KPh    [BATCH * NHEADS * SEQ * 2 * HEADDIM];
__device__ __half g_AttnH  [BS * DMODEL];            // attention out fp16
__device__ __half g_X1h    [BS * DMODEL];            // LN1 out fp16
__device__ __half g_FFh    [BS * DFF];               // FFN hidden fp16

// Pre-transposed fp16 weights: [N][K]
__device__ __half g_WqT[DMODEL * DMODEL];
__device__ __half g_WkT[DMODEL * DMODEL];
__device__ __half g_WvT[DMODEL * DMODEL];
__device__ __half g_WoT[DMODEL * DMODEL];
__device__ __half g_W1T[DMODEL * DFF];
__device__ __half g_W2T[DFF * DMODEL];

// ---------------------------------------------------------------------------
// Helpers
// ---------------------------------------------------------------------------
__device__ __forceinline__ uint32_t smem_u32(const void* p) {
    uint32_t a;
    asm("{ .reg .u64 t; cvta.to.shared.u64 t, %1; cvt.u32.u64 %0, t; }"
        : "=r"(a) : "l"(p));
    return a;
}

__device__ __forceinline__ void cp_async16(uint32_t saddr, const void* gptr) {
    asm volatile("cp.async.cg.shared.global [%0], [%1], 16;"
                 :: "r"(saddr), "l"(gptr) : "memory");
}

// fp16 mma m16n8k16, fp32 accumulate
__device__ __forceinline__ void mma_f16(float (&d)[4],
                                        const uint32_t (&a)[4],
                                        uint32_t b0, uint32_t b1)
{
    asm volatile(
        "mma.sync.aligned.m16n8k16.row.col.f32.f16.f16.f32 "
        "{%0,%1,%2,%3}, {%4,%5,%6,%7}, {%8,%9}, {%0,%1,%2,%3};"
        : "+f"(d[0]), "+f"(d[1]), "+f"(d[2]), "+f"(d[3])
        : "r"(a[0]), "r"(a[1]), "r"(a[2]), "r"(a[3]), "r"(b0), "r"(b1));
}

// ---------------------------------------------------------------------------
// fp32 -> fp16 convert (8 elements per thread)
// ---------------------------------------------------------------------------
__global__ __launch_bounds__(256)
void f2h_kernel(const float* __restrict__ in, __half* __restrict__ out, int n)
{
    int i = (blockIdx.x * blockDim.x + threadIdx.x) * 8;
    if (i >= n) return;
    float4 a = *(const float4*)(in + i);
    float4 b = *(const float4*)(in + i + 4);
    __half2 h[4];
    h[0] = __floats2half2_rn(a.x, a.y);
    h[1] = __floats2half2_rn(a.z, a.w);
    h[2] = __floats2half2_rn(b.x, b.y);
    h[3] = __floats2half2_rn(b.z, b.w);
    *(uint4*)(out + i) = *(uint4*)h;
}

// ---------------------------------------------------------------------------
// Weight transpose + fp16: in[K][N] fp32 -> out[N][K] fp16
// ---------------------------------------------------------------------------
__global__ __launch_bounds__(256)
void transpose_h_kernel(const float* __restrict__ in, __half* __restrict__ out,
                        int K, int N)
{
    __shared__ float t[32][33];
    const int n0 = blockIdx.x * 32, k0 = blockIdx.y * 32;
    const int tx = threadIdx.x, ty = threadIdx.y;
#pragma unroll
    for (int i = 0; i < 32; i += 8)
        t[ty + i][tx] = in[(size_t)(k0 + ty + i) * N + n0 + tx];
    __syncthreads();
#pragma unroll
    for (int i = 0; i < 32; i += 8)
        out[(size_t)(n0 + ty + i) * K + k0 + tx] = __float2half_rn(t[tx][ty + i]);
}

// ---------------------------------------------------------------------------
// fp16 mma GEMM: C(MxN) = A(MxK) @ Bt(NxK)^T + bias; optional ReLU;
// output fp32 or fp16 (HALFOUT). 128x128x32 tiles, 8 warps, cp.async x2.
// Smem stride 40 halves: conflict-free fragment loads.
// ---------------------------------------------------------------------------
#define HG_STRIDE 40
#define HG_STAGE  (128 * HG_STRIDE)                   // halves
#define HG_SMEM_BYTES (4 * HG_STAGE * 2)              // 2 stages x (A+B) = 40960 B

template<int RELU, int HALFOUT>
__global__ __launch_bounds__(256, 2)
void hgemm_kernel(const __half* __restrict__ A, const __half* __restrict__ Bt,
                  const float* __restrict__ bias, void* __restrict__ Cv,
                  int M, int N, int K)
{
    extern __shared__ __half hsm[];
    __half* As = hsm;
    __half* Bs = hsm + 2 * HG_STAGE;

    const int tid  = threadIdx.x;
    const int lane = tid & 31, wid = tid >> 5;
    const int wm = wid >> 1, wn = wid & 1;
    const int grp = lane >> 2, tig = lane & 3;
    const int m0 = blockIdx.y * 128, n0 = blockIdx.x * 128;

    const uint32_t asmem = smem_u32(As);
    const uint32_t bsmem = smem_u32(Bs);

    float acc[2][8][4];
#pragma unroll
    for (int mi = 0; mi < 2; ++mi)
#pragma unroll
        for (int nj = 0; nj < 8; ++nj)
#pragma unroll
            for (int r = 0; r < 4; ++r) acc[mi][nj][r] = 0.f;

    // 32-K chunk = 64B/row; 512 16B-chunks per operand tile; 2 per thread
    auto load_tiles = [&](int stage, int k0) {
        uint32_t ab = asmem + stage * HG_STAGE * 2;
        uint32_t bb = bsmem + stage * HG_STAGE * 2;
#pragma unroll
        for (int i = 0; i < 2; ++i) {
            int idx = tid + i * 256;
            int r = idx >> 2, c = idx & 3;
            cp_async16(ab + (uint32_t)(r * HG_STRIDE + c * 8) * 2,
                       A + (size_t)(m0 + r) * K + k0 + c * 8);
            cp_async16(bb + (uint32_t)(r * HG_STRIDE + c * 8) * 2,
                       Bt + (size_t)(n0 + r) * K + k0 + c * 8);
        }
    };

    load_tiles(0, 0);
    asm volatile("cp.async.commit_group;" ::: "memory");

    const int nIt = K / 32;
    for (int it = 0; it < nIt; ++it) {
        if (it + 1 < nIt) {
            load_tiles((it + 1) & 1, (it + 1) * 32);
            asm volatile("cp.async.commit_group;" ::: "memory");
            asm volatile("cp.async.wait_group 1;" ::: "memory");
        } else {
            asm volatile("cp.async.wait_group 0;" ::: "memory");
        }
        __syncthreads();

        const __half* a = As + (it & 1) * HG_STAGE;
        const __half* b = Bs + (it & 1) * HG_STAGE;

#pragma unroll
        for (int kk = 0; kk < 2; ++kk) {
            const int k = kk * 16;
            uint32_t af[2][4];
#pragma unroll
            for (int mi = 0; mi < 2; ++mi) {
                int r = wm * 32 + mi * 16 + grp;
                af[mi][0] = *(const uint32_t*)&a[r       * HG_STRIDE + k + 2 * tig];
                af[mi][1] = *(const uint32_t*)&a[(r + 8) * HG_STRIDE + k + 2 * tig];
                af[mi][2] = *(const uint32_t*)&a[r       * HG_STRIDE + k + 8 + 2 * tig];
                af[mi][3] = *(const uint32_t*)&a[(r + 8) * HG_STRIDE + k + 8 + 2 * tig];
            }
#pragma unroll
            for (int nj = 0; nj < 8; ++nj) {
                int nr = wn * 64 + nj * 8 + grp;
                uint32_t b0 = *(const uint32_t*)&b[nr * HG_STRIDE + k + 2 * tig];
                uint32_t b1 = *(const uint32_t*)&b[nr * HG_STRIDE + k + 8 + 2 * tig];
#pragma unroll
                for (int mi = 0; mi < 2; ++mi)
                    mma_f16(acc[mi][nj], af[mi], b0, b1);
            }
        }
        __syncthreads();
    }

#pragma unroll
    for (int mi = 0; mi < 2; ++mi) {
        int r = m0 + wm * 32 + mi * 16 + grp;
#pragma unroll
        for (int nj = 0; nj < 8; ++nj) {
            int c = n0 + wn * 64 + nj * 8 + tig * 2;
            float bb0 = bias[c], bb1 = bias[c + 1];
            float v0 = acc[mi][nj][0] + bb0;
            float v1 = acc[mi][nj][1] + bb1;
            float v2 = acc[mi][nj][2] + bb0;
            float v3 = acc[mi][nj][3] + bb1;
            if (RELU) {
                v0 = fmaxf(v0, 0.f); v1 = fmaxf(v1, 0.f);
                v2 = fmaxf(v2, 0.f); v3 = fmaxf(v3, 0.f);
            }
            if (HALFOUT) {
                __half* C = (__half*)Cv;
                *(__half2*)&C[(size_t)r * N + c]       = __floats2half2_rn(v0, v1);
                *(__half2*)&C[(size_t)(r + 8) * N + c] = __floats2half2_rn(v2, v3);
            } else {
                float* C = (float*)Cv;
                float2 lo; lo.x = v0; lo.y = v1;
                float2 hi; hi.x = v2; hi.y = v3;
                *(float2*)&C[(size_t)r * N + c]       = lo;
                *(float2*)&C[(size_t)(r + 8) * N + c] = hi;
            }
        }
    }
}

// ---------------------------------------------------------------------------
// PoPE transform -> fp16 outputs. Each thread does 2 adjacent dims.
// ---------------------------------------------------------------------------
__device__ __forceinline__ float softplus_f(float x) {
    return fmaxf(x, 0.f) + log1pf(expf(-fabsf(x)));
}

__global__ void pope_kernel(const float* __restrict__ q, const float* __restrict__ k,
                            const int* __restrict__ positions,
                            const float* __restrict__ freqs,
                            const float* __restrict__ phase_bias,
                            __half* __restrict__ qp, __half* __restrict__ kp)
{
    int idx = blockIdx.x * blockDim.x + threadIdx.x;   // B*H*S*32
    if (idx >= BATCH * NHEADS * SEQ * 32) return;
    int d = (idx & 31) * 2;
    int s = (idx >> 5) & (SEQ - 1);
    int h = (idx >> 16) & (NHEADS - 1);
    int b = idx >> 20;

    float2 qv = *(const float2*)&q[(size_t)(b * SEQ + s) * DMODEL + h * HEADDIM + d];
    float2 kv = *(const float2*)&k[(size_t)(b * SEQ + s) * DMODEL + h * HEADDIM + d];

    float pos = (float)positions[s];
    float ph0 = pos * freqs[d]     + phase_bias[h * HEADDIM + d];
    float ph1 = pos * freqs[d + 1] + phase_bias[h * HEADDIM + d + 1];
    float c0, s0, c1, s1;
    sincosf(ph0, &s0, &c0);
    sincosf(ph1, &s1, &c1);

    float mq0 = softplus_f(qv.x) * ATTN_SCALE, mq1 = softplus_f(qv.y) * ATTN_SCALE;
    float mk0 = softplus_f(kv.x),              mk1 = softplus_f(kv.y);

    size_t base = (((size_t)(b * NHEADS + h) * SEQ) + s) * 128 + d;
    *(__half2*)&qp[base]      = __floats2half2_rn(mq0 * c0, mq1 * c1);
    *(__half2*)&qp[base + 64] = __floats2half2_rn(mq0 * s0, mq1 * s1);
    *(__half2*)&kp[base]      = __floats2half2_rn(mk0 * c0, mk1 * c1);
    *(__half2*)&kp[base + 64] = __floats2half2_rn(mk0 * s0, mk1 * s1);
}

// ---------------------------------------------------------------------------
// Flash attention with softmax1, fp16 mma m16n8k16.
// 128 q-rows x 64-key tiles, 8 warps, 256 threads. fp16 in/out, fp32 softmax.
// Smem (halves): Qs 128x136 (aliased by Ps 128x72), Ks 64x136, Vt 64x72.
// ---------------------------------------------------------------------------
#define AT_QS 136
#define AT_PS 72
#define AT_VS 72
#define AT_SMEM_HALVES (128 * AT_QS + 64 * AT_QS + 64 * AT_VS)
#define AT_SMEM_BYTES  (AT_SMEM_HALVES * 2)

__global__ __launch_bounds__(256)
void attn_h_kernel(const __half* __restrict__ qp, const __half* __restrict__ kp,
                   const __half* __restrict__ v, __half* __restrict__ out)
{
    extern __shared__ __half hsm[];
    __half* Qs = hsm;                     // 128 x 136 (staging)
    __half* Ps = hsm;                     // 128 x 72 (aliases Qs)
    __half* Ks = hsm + 128 * AT_QS;       // 64 x 136
    __half* Vt = Ks + 64 * AT_QS;         // 64(d) x 72(key)

    const int b = blockIdx.z;
    const int h = blockIdx.y;
    const int qtile = gridDim.x - 1 - blockIdx.x;   // heavy tiles first
    const int q0 = qtile * 128;

    const int tid  = threadIdx.x;
    const int lane = tid & 31, wid = tid >> 5;
    const int grp = lane >> 2, tig = lane & 3;
    const int r0 = wid * 16 + grp;

    const __half* qbase = qp + (((size_t)(b * NHEADS + h)) * SEQ) * 128;
    const __half* kbase = kp + (((size_t)(b * NHEADS + h)) * SEQ) * 128;

    // Stage Q (fp16 copy): 128 rows x 128 halves = 2048 16B chunks
    for (int i = tid; i < 2048; i += 256) {
        int r = i >> 4, c = i & 15;
        *(uint4*)&Qs[r * AT_QS + c * 8] =
            *(const uint4*)&qbase[(size_t)(q0 + r) * 128 + c * 8];
    }
    __syncthreads();

    // Preload Q fragments: 8 k16 chunks
    uint32_t qf[8][4];
#pragma unroll
    for (int kk = 0; kk < 8; ++kk) {
        int k = kk * 16;
        qf[kk][0] = *(const uint32_t*)&Qs[r0       * AT_QS + k + 2 * tig];
        qf[kk][1] = *(const uint32_t*)&Qs[(r0 + 8) * AT_QS + k + 2 * tig];
        qf[kk][2] = *(const uint32_t*)&Qs[r0       * AT_QS + k + 8 + 2 * tig];
        qf[kk][3] = *(const uint32_t*)&Qs[(r0 + 8) * AT_QS + k + 8 + 2 * tig];
    }
    __syncthreads();   // done reading Qs before Ps overwrites

    float m0 = -INFINITY, m1 = -INFINITY, l0 = 0.f, l1 = 0.f;
    float o[8][4];
#pragma unroll
    for (int nj = 0; nj < 8; ++nj)
#pragma unroll
        for (int r = 0; r < 4; ++r) o[nj][r] = 0.f;

    for (int kt = 0; kt <= q0 + 64; kt += 64) {
        __syncthreads();

        // K tile: 64 x 128 halves = 1024 chunks
        for (int i = tid; i < 1024; i += 256) {
            int r = i >> 4, c = i & 15;
            *(uint4*)&Ks[r * AT_QS + c * 8] =
                *(const uint4*)&kbase[(size_t)(kt + r) * 128 + c * 8];
        }
        // V tile transposed: 64 keys x 64 dims
        for (int i = tid; i < 512; i += 256) {
            int r = i >> 3, c = i & 7;
            uint4 raw = *(const uint4*)&v[((size_t)b * SEQ + kt + r) * DMODEL + h * HEADDIM + c * 8];
            __half* hp = (__half*)&raw;
#pragma unroll
            for (int j = 0; j < 8; ++j)
                Vt[(c * 8 + j) * AT_VS + r] = hp[j];
        }
        __syncthreads();

        // scores = Q @ K^T
        float sacc[8][4];
#pragma unroll
        for (int nj = 0; nj < 8; ++nj)
#pragma unroll
            for (int r = 0; r < 4; ++r) sacc[nj][r] = 0.f;

#pragma unroll
        for (int kk = 0; kk < 8; ++kk) {
            int k = kk * 16;
#pragma unroll
            for (int nj = 0; nj < 8; ++nj) {
                int nr = nj * 8 + grp;
                uint32_t b0 = *(const uint32_t*)&Ks[nr * AT_QS + k + 2 * tig];
                uint32_t b1 = *(const uint32_t*)&Ks[nr * AT_QS + k + 8 + 2 * tig];
                mma_f16(sacc[nj], qf[kk], b0, b1);
            }
        }

        // causal mask (last two key tiles only)
        if (kt >= q0) {
            int row0 = q0 + r0, row1 = row0 + 8;
#pragma unroll
            for (int nj = 0; nj < 8; ++nj) {
                int c = kt + nj * 8 + 2 * tig;
                if (c     > row0) sacc[nj][0] = -INFINITY;
                if (c + 1 > row0) sacc[nj][1] = -INFINITY;
                if (c     > row1) sacc[nj][2] = -INFINITY;
                if (c + 1 > row1) sacc[nj][3] = -INFINITY;
            }
        }

        // online softmax1
        float mx0 = -INFINITY, mx1 = -INFINITY;
#pragma unroll
        for (int nj = 0; nj < 8; ++nj) {
            mx0 = fmaxf(mx0, fmaxf(sacc[nj][0], sacc[nj][1]));
            mx1 = fmaxf(mx1, fmaxf(sacc[nj][2], sacc[nj][3]));
        }
        mx0 = fmaxf(mx0, __shfl_xor_sync(0xffffffffu, mx0, 1));
        mx0 = fmaxf(mx0, __shfl_xor_sync(0xffffffffu, mx0, 2));
        mx1 = fmaxf(mx1, __shfl_xor_sync(0xffffffffu, mx1, 1));
        mx1 = fmaxf(mx1, __shfl_xor_sync(0xffffffffu, mx1, 2));

        float m0n = fmaxf(m0, mx0), m1n = fmaxf(m1, mx1);
        float c0 = expf(m0 - m0n),  c1 = expf(m1 - m1n);
        m0 = m0n; m1 = m1n;

        float ls0 = 0.f, ls1 = 0.f;
#pragma unroll
        for (int nj = 0; nj < 8; ++nj) {
            float p0 = expf(sacc[nj][0] - m0n);
            float p1 = expf(sacc[nj][1] - m0n);
            float p2 = expf(sacc[nj][2] - m1n);
            float p3 = expf(sacc[nj][3] - m1n);
            ls0 += p0 + p1; ls1 += p2 + p3;
            *(__half2*)&Ps[r0       * AT_PS + nj * 8 + 2 * tig] = __floats2half2_rn(p0, p1);
            *(__half2*)&Ps[(r0 + 8) * AT_PS + nj * 8 + 2 * tig] = __floats2half2_rn(p2, p3);
        }
        ls0 += __shfl_xor_sync(0xffffffffu, ls0, 1);
        ls0 += __shfl_xor_sync(0xffffffffu, ls0, 2);
        ls1 += __shfl_xor_sync(0xffffffffu, ls1, 1);
        ls1 += __shfl_xor_sync(0xffffffffu, ls1, 2);
        l0 = l0 * c0 + ls0;
        l1 = l1 * c1 + ls1;

#pragma unroll
        for (int nj = 0; nj < 8; ++nj) {
            o[nj][0] *= c0; o[nj][1] *= c0;
            o[nj][2] *= c1; o[nj][3] *= c1;
        }
        __syncwarp();

        // O += P @ V  (4 k16 chunks over 64 keys)
#pragma unroll
        for (int kk = 0; kk < 4; ++kk) {
            int k = kk * 16;
            uint32_t af[4];
            af[0] = *(const uint32_t*)&Ps[r0       * AT_PS + k + 2 * tig];
            af[1] = *(const uint32_t*)&Ps[(r0 + 8) * AT_PS + k + 2 * tig];
            af[2] = *(const uint32_t*)&Ps[r0       * AT_PS + k + 8 + 2 * tig];
            af[3] = *(const uint32_t*)&Ps[(r0 + 8) * AT_PS + k + 8 + 2 * tig];
#pragma unroll
            for (int nj = 0; nj < 8; ++nj) {
                int nr = nj * 8 + grp;
                uint32_t b0 = *(const uint32_t*)&Vt[nr * AT_VS + k + 2 * tig];
                uint32_t b1 = *(const uint32_t*)&Vt[nr * AT_VS + k + 8 + 2 * tig];
                mma_f16(o[nj], af, b0, b1);
            }
        }
    }

    // epilogue: softmax1 denominator; write fp16 (B,S,D)
    float inv0 = 1.f / (1.f + l0);
    float inv1 = 1.f / (1.f + l1);
    int row0 = q0 + r0;
#pragma unroll
    for (int nj = 0; nj < 8; ++nj) {
        int c = h * HEADDIM + nj * 8 + 2 * tig;
        *(__half2*)&out[((size_t)b * SEQ + row0)     * DMODEL + c] =
            __floats2half2_rn(o[nj][0] * inv0, o[nj][1] * inv0);
        *(__half2*)&out[((size_t)b * SEQ + row0 + 8) * DMODEL + c] =
            __floats2half2_rn(o[nj][2] * inv1, o[nj][3] * inv1);
    }
}

// ---------------------------------------------------------------------------
// Fused residual add + LayerNorm; optional fp16 copy of the output.
// ---------------------------------------------------------------------------
template<int WRITEH>
__global__ __launch_bounds__(256)
void add_ln_kernel(const float* __restrict__ x, const float* __restrict__ y,
                   const float* __restrict__ g, const float* __restrict__ beta,
                   float* __restrict__ out, __half* __restrict__ outh)
{
    __shared__ float red_s[8];
    __shared__ float red_ss[8];
    __shared__ float s_mu, s_rstd;

    const int row = blockIdx.x;
    const int tid = threadIdx.x;
    const size_t base = (size_t)row * DMODEL;

    float4 xv = ((const float4*)(x + base))[tid];
    float4 yv = ((const float4*)(y + base))[tid];
    float v0 = xv.x + yv.x, v1 = xv.y + yv.y, v2 = xv.z + yv.z, v3 = xv.w + yv.w;

    float sum = v0 + v1 + v2 + v3;
    float ssq = v0 * v0 + v1 * v1 + v2 * v2 + v3 * v3;
#pragma unroll
    for (int off = 16; off >= 1; off >>= 1) {
        sum += __shfl_down_sync(0xffffffffu, sum, off);
        ssq += __shfl_down_sync(0xffffffffu, ssq, off);
    }
    const int warp = tid >> 5;
    if ((tid & 31) == 0) { red_s[warp] = sum; red_ss[warp] = ssq; }
    __syncthreads();
    if (tid == 0) {
        float ts = 0.f, tss = 0.f;
#pragma unroll
        for (int w = 0; w < 8; ++w) { ts += red_s[w]; tss += red_ss[w]; }
        float mu  = ts / (float)DMODEL;
        float var = tss / (float)DMODEL - mu * mu;
        s_mu = mu;
        s_rstd = rsqrtf(var + LN_EPS);
    }
    __syncthreads();
    const float mu = s_mu, rstd = s_rstd;

    float4 gv = ((const float4*)g)[tid];
    float4 bv = ((const float4*)beta)[tid];
    float4 o;
    o.x = (v0 - mu) * rstd * gv.x + bv.x;
    o.y = (v1 - mu) * rstd * gv.y + bv.y;
    o.z = (v2 - mu) * rstd * gv.z + bv.z;
    o.w = (v3 - mu) * rstd * gv.w + bv.w;
    ((float4*)(out + base))[tid] = o;
    if (WRITEH) {
        __half2 h0 = __floats2half2_rn(o.x, o.y);
        __half2 h1 = __floats2half2_rn(o.z, o.w);
        ((__half2*)(outh + base))[2 * tid]     = h0;
        ((__half2*)(outh + base))[2 * tid + 1] = h1;
    }
}

// ---------------------------------------------------------------------------
// Launcher
// ---------------------------------------------------------------------------
extern "C" void kernel_launch(void* const* d_in, const int* in_sizes, int n_in,
                              void* d_out, int out_size)
{
    (void)in_sizes; (void)n_in; (void)out_size;
    const float* x          = (const float*)d_in[0];
    const int*   positions  = (const int*)  d_in[1];
    const float* Wq         = (const float*)d_in[2];
    const float* bq         = (const float*)d_in[3];
    const float* Wk         = (const float*)d_in[4];
    const float* bk         = (const float*)d_in[5];
    const float* Wv         = (const float*)d_in[6];
    const float* bv         = (const float*)d_in[7];
    const float* Wo         = (const float*)d_in[8];
    const float* bo         = (const float*)d_in[9];
    const float* phase_bias = (const float*)d_in[10];
    const float* freqs      = (const float*)d_in[11];
    const float* W1         = (const float*)d_in[12];
    const float* b1         = (const float*)d_in[13];
    const float* W2         = (const float*)d_in[14];
    const float* b2         = (const float*)d_in[15];
    const float* g1         = (const float*)d_in[16];
    const float* beta1      = (const float*)d_in[17];
    const float* g2         = (const float*)d_in[18];
    const float* beta2      = (const float*)d_in[19];
    float* outp             = (float*)d_out;

    float  *bufQ, *bufK, *bufX1;
    __half *xh, *bufVh, *QPh, *KPh, *AttnH, *X1h, *FFh;
    __half *WqT, *WkT, *WvT, *WoT, *W1T, *W2T;
    cudaGetSymbolAddress((void**)&bufQ,  g_bufQ);
    cudaGetSymbolAddress((void**)&bufK,  g_bufK);
    cudaGetSymbolAddress((void**)&bufX1, g_bufX1);
    cudaGetSymbolAddress((void**)&xh,    g_xh);
    cudaGetSymbolAddress((void**)&bufVh, g_bufVh);
    cudaGetSymbolAddress((void**)&QPh,   g_QPh);
    cudaGetSymbolAddress((void**)&KPh,   g_KPh);
    cudaGetSymbolAddress((void**)&AttnH, g_AttnH);
    cudaGetSymbolAddress((void**)&X1h,   g_X1h);
    cudaGetSymbolAddress((void**)&FFh,   g_FFh);
    cudaGetSymbolAddress((void**)&WqT,   g_WqT);
    cudaGetSymbolAddress((void**)&WkT,   g_WkT);
    cudaGetSymbolAddress((void**)&WvT,   g_WvT);
    cudaGetSymbolAddress((void**)&WoT,   g_WoT);
    cudaGetSymbolAddress((void**)&W1T,   g_W1T);
    cudaGetSymbolAddress((void**)&W2T,   g_W2T);

    cudaFuncSetAttribute(attn_h_kernel, cudaFuncAttributeMaxDynamicSharedMemorySize,
                         AT_SMEM_BYTES);
    cudaFuncSetAttribute(hgemm_kernel<0,0>, cudaFuncAttributeMaxDynamicSharedMemorySize,
                         HG_SMEM_BYTES);
    cudaFuncSetAttribute(hgemm_kernel<0,1>, cudaFuncAttributeMaxDynamicSharedMemorySize,
                         HG_SMEM_BYTES);
    cudaFuncSetAttribute(hgemm_kernel<1,1>, cudaFuncAttributeMaxDynamicSharedMemorySize,
                         HG_SMEM_BYTES);

    // 0a: x -> fp16
    f2h_kernel<<<(BS * DMODEL / 8 + 255) / 256, 256>>>(x, xh, BS * DMODEL);

    // 0b: weight transposes + fp16
    {
        dim3 blk(32, 8);
        transpose_h_kernel<<<dim3(DMODEL/32, DMODEL/32), blk>>>(Wq, WqT, DMODEL, DMODEL);
        transpose_h_kernel<<<dim3(DMODEL/32, DMODEL/32), blk>>>(Wk, WkT, DMODEL, DMODEL);
        transpose_h_kernel<<<dim3(DMODEL/32, DMODEL/32), blk>>>(Wv, WvT, DMODEL, DMODEL);
        transpose_h_kernel<<<dim3(DMODEL/32, DMODEL/32), blk>>>(Wo, WoT, DMODEL, DMODEL);
        transpose_h_kernel<<<dim3(DFF/32,    DMODEL/32), blk>>>(W1, W1T, DMODEL, DFF);
        transpose_h_kernel<<<dim3(DMODEL/32, DFF/32),    blk>>>(W2, W2T, DFF, DMODEL);
    }

    // 1-3: QKV projections (fp16 mma). Q/K -> fp32 (pope input), V -> fp16.
    {
        dim3 grid(DMODEL / 128, BS / 128);
        hgemm_kernel<0,0><<<grid, 256, HG_SMEM_BYTES>>>(xh, WqT, bq, bufQ,  BS, DMODEL, DMODEL);
        hgemm_kernel<0,0><<<grid, 256, HG_SMEM_BYTES>>>(xh, WkT, bk, bufK,  BS, DMODEL, DMODEL);
        hgemm_kernel<0,1><<<grid, 256, HG_SMEM_BYTES>>>(xh, WvT, bv, bufVh, BS, DMODEL, DMODEL);
    }

    // 4: PoPE -> fp16 qp/kp
    {
        int total = BATCH * NHEADS * SEQ * 32;
        pope_kernel<<<(total + 255) / 256, 256>>>(bufQ, bufK, positions, freqs,
                                                  phase_bias, QPh, KPh);
    }

    // 5: attention -> fp16
    {
        dim3 grid(SEQ / 128, NHEADS, BATCH);
        attn_h_kernel<<<grid, 256, AT_SMEM_BYTES>>>(QPh, KPh, bufVh, AttnH);
    }

    // 6: output projection -> fp32 (bufQ reuse)
    {
        dim3 grid(DMODEL / 128, BS / 128);
        hgemm_kernel<0,0><<<grid, 256, HG_SMEM_BYTES>>>(AttnH, WoT, bo, bufQ, BS, DMODEL, DMODEL);
    }

    // 7: residual + LN1 -> fp32 + fp16
    add_ln_kernel<1><<<BS, 256>>>(x, bufQ, g1, beta1, bufX1, X1h);

    // 8: FFN up + ReLU -> fp16
    {
        dim3 grid(DFF / 128, BS / 128);
        hgemm_kernel<1,1><<<grid, 256, HG_SMEM_BYTES>>>(X1h, W1T, b1, FFh, BS, DFF, DMODEL);
    }

    // 9: FFN down -> fp32 (bufK reuse)
    {
        dim3 grid(DMODEL / 128, BS / 128);
        hgemm_kernel<0,0><<<grid, 256, HG_SMEM_BYTES>>>(FFh, W2T, b2, bufK, BS, DMODEL, DFF);
    }

    // 10: residual + LN2 -> output
    add_ln_kernel<0><<<BS, 256>>>(bufX1, bufK, g2, beta2, outp, nullptr);
}

// round 7
// speedup vs baseline: 4.6370x; 1.0397x over previous
#include <cuda_runtime.h>
#include <cuda_fp16.h>
#include <math.h>
#include <stdint.h>

// ---------------------------------------------------------------------------
// Problem constants
// ---------------------------------------------------------------------------
#define BATCH   2
#define SEQ     2048
#define DMODEL  1024
#define NHEADS  16
#define HEADDIM 64
#define DFF     4096
#define BS      (BATCH * SEQ)          // 4096 rows
#define LN_EPS  1e-5f
#define ATTN_SCALE 0.08838834764831845f   // 1/sqrt(128)

// ---------------------------------------------------------------------------
// Scratch buffers
// ---------------------------------------------------------------------------
__device__ float  g_bufQ   [BS * DMODEL];            // Q raw (fp32, pope input); reused Wo out
__device__ float  g_bufK   [BS * DMODEL];            // K raw (fp32); reused FFN2 out
__device__ float  g_bufX1  [BS * DMODEL];            // LN1 out fp32
__device__ __half g_xh     [BS * DMODEL];            // x in fp16
__device__ __half g_bufVh  [BS * DMODEL];            // V fp16
__device__ __half g_QPh    [BATCH * NHEADS * SEQ * 2 * HEADDIM];
__device__ __half g_KPh    [BATCH * NHEADS * SEQ * 2 * HEADDIM];
__device__ __half g_AttnH  [BS * DMODEL];            // attention out fp16
__device__ __half g_X1h    [BS * DMODEL];            // LN1 out fp16
__device__ __half g_FFh    [BS * DFF];               // FFN hidden fp16

// Pre-transposed fp16 weights: [N][K]
__device__ __half g_WqT[DMODEL * DMODEL];
__device__ __half g_WkT[DMODEL * DMODEL];
__device__ __half g_WvT[DMODEL * DMODEL];
__device__ __half g_WoT[DMODEL * DMODEL];
__device__ __half g_W1T[DMODEL * DFF];
__device__ __half g_W2T[DFF * DMODEL];

// ---------------------------------------------------------------------------
// Helpers
// ---------------------------------------------------------------------------
__device__ __forceinline__ uint32_t smem_u32(const void* p) {
    uint32_t a;
    asm("{ .reg .u64 t; cvta.to.shared.u64 t, %1; cvt.u32.u64 %0, t; }"
        : "=r"(a) : "l"(p));
    return a;
}

__device__ __forceinline__ void cp_async16(uint32_t saddr, const void* gptr) {
    asm volatile("cp.async.cg.shared.global [%0], [%1], 16;"
                 :: "r"(saddr), "l"(gptr) : "memory");
}

// fp16 mma m16n8k16, fp32 accumulate
__device__ __forceinline__ void mma_f16(float (&d)[4],
                                        const uint32_t (&a)[4],
                                        uint32_t b0, uint32_t b1)
{
    asm volatile(
        "mma.sync.aligned.m16n8k16.row.col.f32.f16.f16.f32 "
        "{%0,%1,%2,%3}, {%4,%5,%6,%7}, {%8,%9}, {%0,%1,%2,%3};"
        : "+f"(d[0]), "+f"(d[1]), "+f"(d[2]), "+f"(d[3])
        : "r"(a[0]), "r"(a[1]), "r"(a[2]), "r"(a[3]), "r"(b0), "r"(b1));
}

__device__ __forceinline__ void ldsm_x4(uint32_t (&r)[4], uint32_t saddr) {
    asm volatile("ldmatrix.sync.aligned.m8n8.x4.shared.b16 {%0,%1,%2,%3}, [%4];"
                 : "=r"(r[0]), "=r"(r[1]), "=r"(r[2]), "=r"(r[3]) : "r"(saddr));
}

// ---------------------------------------------------------------------------
// fp32 -> fp16 convert (8 elements per thread)
// ---------------------------------------------------------------------------
__global__ __launch_bounds__(256)
void f2h_kernel(const float* __restrict__ in, __half* __restrict__ out, int n)
{
    int i = (blockIdx.x * blockDim.x + threadIdx.x) * 8;
    if (i >= n) return;
    float4 a = *(const float4*)(in + i);
    float4 b = *(const float4*)(in + i + 4);
    __half2 h[4];
    h[0] = __floats2half2_rn(a.x, a.y);
    h[1] = __floats2half2_rn(a.z, a.w);
    h[2] = __floats2half2_rn(b.x, b.y);
    h[3] = __floats2half2_rn(b.z, b.w);
    *(uint4*)(out + i) = *(uint4*)h;
}

// ---------------------------------------------------------------------------
// Weight transpose + fp16: in[K][N] fp32 -> out[N][K] fp16
// ---------------------------------------------------------------------------
__global__ __launch_bounds__(256)
void transpose_h_kernel(const float* __restrict__ in, __half* __restrict__ out,
                        int K, int N)
{
    __shared__ float t[32][33];
    const int n0 = blockIdx.x * 32, k0 = blockIdx.y * 32;
    const int tx = threadIdx.x, ty = threadIdx.y;
#pragma unroll
    for (int i = 0; i < 32; i += 8)
        t[ty + i][tx] = in[(size_t)(k0 + ty + i) * N + n0 + tx];
    __syncthreads();
#pragma unroll
    for (int i = 0; i < 32; i += 8)
        out[(size_t)(n0 + ty + i) * K + k0 + tx] = __float2half_rn(t[tx][ty + i]);
}

// ---------------------------------------------------------------------------
// fp16 mma GEMM with ldmatrix fragment loads.
// 128x128x32 tiles, 8 warps, cp.async double-buffered smem, stride 40 halves
// (ldmatrix-conflict-free: row offsets 20r mod 32 cover all banks).
// ---------------------------------------------------------------------------
#define HG_STRIDE 40
#define HG_STAGE  (128 * HG_STRIDE)                   // halves
#define HG_SMEM_BYTES (4 * HG_STAGE * 2)              // 40960 B

template<int RELU, int HALFOUT>
__global__ __launch_bounds__(256, 2)
void hgemm_kernel(const __half* __restrict__ A, const __half* __restrict__ Bt,
                  const float* __restrict__ bias, void* __restrict__ Cv,
                  int M, int N, int K)
{
    extern __shared__ __half hsm[];
    __half* As = hsm;
    __half* Bs = hsm + 2 * HG_STAGE;

    const int tid  = threadIdx.x;
    const int lane = tid & 31, wid = tid >> 5;
    const int wm = wid >> 1, wn = wid & 1;
    const int grp = lane >> 2, tig = lane & 3;
    const int m0 = blockIdx.y * 128, n0 = blockIdx.x * 128;

    const uint32_t asmem = smem_u32(As);
    const uint32_t bsmem = smem_u32(Bs);

    // ldmatrix lane->row/col decomposition
    const int l8  = lane & 7;
    const int q01 = (lane >> 3) & 1;     // quad bit 0
    const int q23 = lane >> 4;           // quad bit 1

    float acc[2][8][4];
#pragma unroll
    for (int mi = 0; mi < 2; ++mi)
#pragma unroll
        for (int nj = 0; nj < 8; ++nj)
#pragma unroll
            for (int r = 0; r < 4; ++r) acc[mi][nj][r] = 0.f;

    auto load_tiles = [&](int stage, int k0) {
        uint32_t ab = asmem + stage * HG_STAGE * 2;
        uint32_t bb = bsmem + stage * HG_STAGE * 2;
#pragma unroll
        for (int i = 0; i < 2; ++i) {
            int idx = tid + i * 256;
            int r = idx >> 2, c = idx & 3;
            cp_async16(ab + (uint32_t)(r * HG_STRIDE + c * 8) * 2,
                       A + (size_t)(m0 + r) * K + k0 + c * 8);
            cp_async16(bb + (uint32_t)(r * HG_STRIDE + c * 8) * 2,
                       Bt + (size_t)(n0 + r) * K + k0 + c * 8);
        }
    };

    load_tiles(0, 0);
    asm volatile("cp.async.commit_group;" ::: "memory");

    const int nIt = K / 32;
    for (int it = 0; it < nIt; ++it) {
        if (it + 1 < nIt) {
            load_tiles((it + 1) & 1, (it + 1) * 32);
            asm volatile("cp.async.commit_group;" ::: "memory");
            asm volatile("cp.async.wait_group 1;" ::: "memory");
        } else {
            asm volatile("cp.async.wait_group 0;" ::: "memory");
        }
        __syncthreads();

        const uint32_t abase = asmem + (it & 1) * HG_STAGE * 2;
        const uint32_t bbase = bsmem + (it & 1) * HG_STAGE * 2;

#pragma unroll
        for (int kk = 0; kk < 2; ++kk) {
            const int k = kk * 16;
            uint32_t af[2][4];
#pragma unroll
            for (int mi = 0; mi < 2; ++mi) {
                int row = wm * 32 + mi * 16 + q01 * 8 + l8;
                int col = k + q23 * 8;
                ldsm_x4(af[mi], abase + (uint32_t)(row * HG_STRIDE + col) * 2);
            }
#pragma unroll
            for (int g = 0; g < 4; ++g) {
                uint32_t bf[4];
                int row = wn * 64 + g * 16 + q23 * 8 + l8;
                int col = k + q01 * 8;
                ldsm_x4(bf, bbase + (uint32_t)(row * HG_STRIDE + col) * 2);
#pragma unroll
                for (int h2 = 0; h2 < 2; ++h2)
#pragma unroll
                    for (int mi = 0; mi < 2; ++mi)
                        mma_f16(acc[mi][g * 2 + h2], af[mi], bf[h2 * 2], bf[h2 * 2 + 1]);
            }
        }
        __syncthreads();
    }

#pragma unroll
    for (int mi = 0; mi < 2; ++mi) {
        int r = m0 + wm * 32 + mi * 16 + grp;
#pragma unroll
        for (int nj = 0; nj < 8; ++nj) {
            int c = n0 + wn * 64 + nj * 8 + tig * 2;
            float bb0 = bias[c], bb1 = bias[c + 1];
            float v0 = acc[mi][nj][0] + bb0;
            float v1 = acc[mi][nj][1] + bb1;
            float v2 = acc[mi][nj][2] + bb0;
            float v3 = acc[mi][nj][3] + bb1;
            if (RELU) {
                v0 = fmaxf(v0, 0.f); v1 = fmaxf(v1, 0.f);
                v2 = fmaxf(v2, 0.f); v3 = fmaxf(v3, 0.f);
            }
            if (HALFOUT) {
                __half* C = (__half*)Cv;
                *(__half2*)&C[(size_t)r * N + c]       = __floats2half2_rn(v0, v1);
                *(__half2*)&C[(size_t)(r + 8) * N + c] = __floats2half2_rn(v2, v3);
            } else {
                float* C = (float*)Cv;
                float2 lo; lo.x = v0; lo.y = v1;
                float2 hi; hi.x = v2; hi.y = v3;
                *(float2*)&C[(size_t)r * N + c]       = lo;
                *(float2*)&C[(size_t)(r + 8) * N + c] = hi;
            }
        }
    }
}

// ---------------------------------------------------------------------------
// PoPE transform -> fp16 outputs. Each thread does 2 adjacent dims.
// ---------------------------------------------------------------------------
__device__ __forceinline__ float softplus_f(float x) {
    return fmaxf(x, 0.f) + log1pf(expf(-fabsf(x)));
}

__global__ void pope_kernel(const float* __restrict__ q, const float* __restrict__ k,
                            const int* __restrict__ positions,
                            const float* __restrict__ freqs,
                            const float* __restrict__ phase_bias,
                            __half* __restrict__ qp, __half* __restrict__ kp)
{
    int idx = blockIdx.x * blockDim.x + threadIdx.x;   // B*H*S*32
    if (idx >= BATCH * NHEADS * SEQ * 32) return;
    int d = (idx & 31) * 2;
    int s = (idx >> 5) & (SEQ - 1);
    int h = (idx >> 16) & (NHEADS - 1);
    int b = idx >> 20;

    float2 qv = *(const float2*)&q[(size_t)(b * SEQ + s) * DMODEL + h * HEADDIM + d];
    float2 kv = *(const float2*)&k[(size_t)(b * SEQ + s) * DMODEL + h * HEADDIM + d];

    float pos = (float)positions[s];
    float ph0 = pos * freqs[d]     + phase_bias[h * HEADDIM + d];
    float ph1 = pos * freqs[d + 1] + phase_bias[h * HEADDIM + d + 1];
    float c0, s0, c1, s1;
    sincosf(ph0, &s0, &c0);
    sincosf(ph1, &s1, &c1);

    float mq0 = softplus_f(qv.x) * ATTN_SCALE, mq1 = softplus_f(qv.y) * ATTN_SCALE;
    float mk0 = softplus_f(kv.x),              mk1 = softplus_f(kv.y);

    size_t base = (((size_t)(b * NHEADS + h) * SEQ) + s) * 128 + d;
    *(__half2*)&qp[base]      = __floats2half2_rn(mq0 * c0, mq1 * c1);
    *(__half2*)&qp[base + 64] = __floats2half2_rn(mq0 * s0, mq1 * s1);
    *(__half2*)&kp[base]      = __floats2half2_rn(mk0 * c0, mk1 * c1);
    *(__half2*)&kp[base + 64] = __floats2half2_rn(mk0 * s0, mk1 * s1);
}

// ---------------------------------------------------------------------------
// Flash attention with softmax1, fp16 mma + ldmatrix fragment loads.
// 128 q-rows x 64-key tiles, 8 warps, 256 threads.
// ---------------------------------------------------------------------------
#define AT_QS 136
#define AT_PS 72
#define AT_VS 72
#define AT_SMEM_HALVES (128 * AT_QS + 64 * AT_QS + 64 * AT_VS)
#define AT_SMEM_BYTES  (AT_SMEM_HALVES * 2)

__global__ __launch_bounds__(256)
void attn_h_kernel(const __half* __restrict__ qp, const __half* __restrict__ kp,
                   const __half* __restrict__ v, __half* __restrict__ out)
{
    extern __shared__ __half hsm[];
    __half* Qs = hsm;                     // 128 x 136 (staging)
    __half* Ps = hsm;                     // 128 x 72 (aliases Qs)
    __half* Ks = hsm + 128 * AT_QS;       // 64 x 136
    __half* Vt = Ks + 64 * AT_QS;         // 64(d) x 72(key)

    const int b = blockIdx.z;
    const int h = blockIdx.y;
    const int qtile = gridDim.x - 1 - blockIdx.x;   // heavy tiles first
    const int q0 = qtile * 128;

    const int tid  = threadIdx.x;
    const int lane = tid & 31, wid = tid >> 5;
    const int grp = lane >> 2, tig = lane & 3;
    const int r0 = wid * 16 + grp;

    const int l8  = lane & 7;
    const int q01 = (lane >> 3) & 1;
    const int q23 = lane >> 4;

    const uint32_t pssm = smem_u32(Ps);
    const uint32_t kssm = smem_u32(Ks);
    const uint32_t vtsm = smem_u32(Vt);

    const __half* qbase = qp + (((size_t)(b * NHEADS + h)) * SEQ) * 128;
    const __half* kbase = kp + (((size_t)(b * NHEADS + h)) * SEQ) * 128;

    // Stage Q: 128 rows x 128 halves = 2048 16B chunks
    for (int i = tid; i < 2048; i += 256) {
        int r = i >> 4, c = i & 15;
        *(uint4*)&Qs[r * AT_QS + c * 8] =
            *(const uint4*)&qbase[(size_t)(q0 + r) * 128 + c * 8];
    }
    __syncthreads();

    // Preload Q fragments via ldmatrix: 8 k16 chunks
    uint32_t qf[8][4];
    {
        const uint32_t qssm = smem_u32(Qs);
        int row = wid * 16 + q01 * 8 + l8;
#pragma unroll
        for (int kk = 0; kk < 8; ++kk) {
            int col = kk * 16 + q23 * 8;
            ldsm_x4(qf[kk], qssm + (uint32_t)(row * AT_QS + col) * 2);
        }
    }
    __syncthreads();   // done reading Qs before Ps overwrites

    float m0 = -INFINITY, m1 = -INFINITY, l0 = 0.f, l1 = 0.f;
    float o[8][4];
#pragma unroll
    for (int nj = 0; nj < 8; ++nj)
#pragma unroll
        for (int r = 0; r < 4; ++r) o[nj][r] = 0.f;

    for (int kt = 0; kt <= q0 + 64; kt += 64) {
        __syncthreads();

        // K tile: 64 x 128 halves = 1024 chunks
        for (int i = tid; i < 1024; i += 256) {
            int r = i >> 4, c = i & 15;
            *(uint4*)&Ks[r * AT_QS + c * 8] =
                *(const uint4*)&kbase[(size_t)(kt + r) * 128 + c * 8];
        }
        // V tile transposed: 64 keys x 64 dims
        for (int i = tid; i < 512; i += 256) {
            int r = i >> 3, c = i & 7;
            uint4 raw = *(const uint4*)&v[((size_t)b * SEQ + kt + r) * DMODEL + h * HEADDIM + c * 8];
            __half* hp = (__half*)&raw;
#pragma unroll
            for (int j = 0; j < 8; ++j)
                Vt[(c * 8 + j) * AT_VS + r] = hp[j];
        }
        __syncthreads();

        // scores = Q @ K^T
        float sacc[8][4];
#pragma unroll
        for (int nj = 0; nj < 8; ++nj)
#pragma unroll
            for (int r = 0; r < 4; ++r) sacc[nj][r] = 0.f;

#pragma unroll
        for (int kk = 0; kk < 8; ++kk) {
            int k = kk * 16;
#pragma unroll
            for (int g = 0; g < 4; ++g) {
                uint32_t bf[4];
                int row = g * 16 + q23 * 8 + l8;
                int col = k + q01 * 8;
                ldsm_x4(bf, kssm + (uint32_t)(row * AT_QS + col) * 2);
                mma_f16(sacc[g * 2 + 0], qf[kk], bf[0], bf[1]);
                mma_f16(sacc[g * 2 + 1], qf[kk], bf[2], bf[3]);
            }
        }

        // causal mask (last two key tiles only)
        if (kt >= q0) {
            int row0 = q0 + r0, row1 = row0 + 8;
#pragma unroll
            for (int nj = 0; nj < 8; ++nj) {
                int c = kt + nj * 8 + 2 * tig;
                if (c     > row0) sacc[nj][0] = -INFINITY;
                if (c + 1 > row0) sacc[nj][1] = -INFINITY;
                if (c     > row1) sacc[nj][2] = -INFINITY;
                if (c + 1 > row1) sacc[nj][3] = -INFINITY;
            }
        }

        // online softmax1
        float mx0 = -INFINITY, mx1 = -INFINITY;
#pragma unroll
        for (int nj = 0; nj < 8; ++nj) {
            mx0 = fmaxf(mx0, fmaxf(sacc[nj][0], sacc[nj][1]));
            mx1 = fmaxf(mx1, fmaxf(sacc[nj][2], sacc[nj][3]));
        }
        mx0 = fmaxf(mx0, __shfl_xor_sync(0xffffffffu, mx0, 1));
        mx0 = fmaxf(mx0, __shfl_xor_sync(0xffffffffu, mx0, 2));
        mx1 = fmaxf(mx1, __shfl_xor_sync(0xffffffffu, mx1, 1));
        mx1 = fmaxf(mx1, __shfl_xor_sync(0xffffffffu, mx1, 2));

        float m0n = fmaxf(m0, mx0), m1n = fmaxf(m1, mx1);
        float c0 = expf(m0 - m0n),  c1 = expf(m1 - m1n);
        m0 = m0n; m1 = m1n;

        float ls0 = 0.f, ls1 = 0.f;
#pragma unroll
        for (int nj = 0; nj < 8; ++nj) {
            float p0 = expf(sacc[nj][0] - m0n);
            float p1 = expf(sacc[nj][1] - m0n);
            float p2 = expf(sacc[nj][2] - m1n);
            float p3 = expf(sacc[nj][3] - m1n);
            ls0 += p0 + p1; ls1 += p2 + p3;
            *(__half2*)&Ps[r0       * AT_PS + nj * 8 + 2 * tig] = __floats2half2_rn(p0, p1);
            *(__half2*)&Ps[(r0 + 8) * AT_PS + nj * 8 + 2 * tig] = __floats2half2_rn(p2, p3);
        }
        ls0 += __shfl_xor_sync(0xffffffffu, ls0, 1);
        ls0 += __shfl_xor_sync(0xffffffffu, ls0, 2);
        ls1 += __shfl_xor_sync(0xffffffffu, ls1, 1);
        ls1 += __shfl_xor_sync(0xffffffffu, ls1, 2);
        l0 = l0 * c0 + ls0;
        l1 = l1 * c1 + ls1;

#pragma unroll
        for (int nj = 0; nj < 8; ++nj) {
            o[nj][0] *= c0; o[nj][1] *= c0;
            o[nj][2] *= c1; o[nj][3] *= c1;
        }
        __syncwarp();

        // O += P @ V  (4 k16 chunks over 64 keys)
#pragma unroll
        for (int kk = 0; kk < 4; ++kk) {
            int k = kk * 16;
            uint32_t af[4];
            {
                int row = wid * 16 + q01 * 8 + l8;
                int col = k + q23 * 8;
                ldsm_x4(af, pssm + (uint32_t)(row * AT_PS + col) * 2);
            }
#pragma unroll
            for (int g = 0; g < 4; ++g) {
                uint32_t bf[4];
                int row = g * 16 + q23 * 8 + l8;
                int col = k + q01 * 8;
                ldsm_x4(bf, vtsm + (uint32_t)(row * AT_VS + col) * 2);
                mma_f16(o[g * 2 + 0], af, bf[0], bf[1]);
                mma_f16(o[g * 2 + 1], af, bf[2], bf[3]);
            }
        }
    }

    // epilogue: softmax1 denominator; write fp16 (B,S,D)
    float inv0 = 1.f / (1.f + l0);
    float inv1 = 1.f / (1.f + l1);
    int row0 = q0 + r0;
#pragma unroll
    for (int nj = 0; nj < 8; ++nj) {
        int c = h * HEADDIM + nj * 8 + 2 * tig;
        *(__half2*)&out[((size_t)b * SEQ + row0)     * DMODEL + c] =
            __floats2half2_rn(o[nj][0] * inv0, o[nj][1] * inv0);
        *(__half2*)&out[((size_t)b * SEQ + row0 + 8) * DMODEL + c] =
            __floats2half2_rn(o[nj][2] * inv1, o[nj][3] * inv1);
    }
}

// ---------------------------------------------------------------------------
// Fused residual add + LayerNorm; optional fp16 copy of the output.
// ---------------------------------------------------------------------------
template<int WRITEH>
__global__ __launch_bounds__(256)
void add_ln_kernel(const float* __restrict__ x, const float* __restrict__ y,
                   const float* __restrict__ g, const float* __restrict__ beta,
                   float* __restrict__ out, __half* __restrict__ outh)
{
    __shared__ float red_s[8];
    __shared__ float red_ss[8];
    __shared__ float s_mu, s_rstd;

    const int row = blockIdx.x;
    const int tid = threadIdx.x;
    const size_t base = (size_t)row * DMODEL;

    float4 xv = ((const float4*)(x + base))[tid];
    float4 yv = ((const float4*)(y + base))[tid];
    float v0 = xv.x + yv.x, v1 = xv.y + yv.y, v2 = xv.z + yv.z, v3 = xv.w + yv.w;

    float sum = v0 + v1 + v2 + v3;
    float ssq = v0 * v0 + v1 * v1 + v2 * v2 + v3 * v3;
#pragma unroll
    for (int off = 16; off >= 1; off >>= 1) {
        sum += __shfl_down_sync(0xffffffffu, sum, off);
        ssq += __shfl_down_sync(0xffffffffu, ssq, off);
    }
    const int warp = tid >> 5;
    if ((tid & 31) == 0) { red_s[warp] = sum; red_ss[warp] = ssq; }
    __syncthreads();
    if (tid == 0) {
        float ts = 0.f, tss = 0.f;
#pragma unroll
        for (int w = 0; w < 8; ++w) { ts += red_s[w]; tss += red_ss[w]; }
        float mu  = ts / (float)DMODEL;
        float var = tss / (float)DMODEL - mu * mu;
        s_mu = mu;
        s_rstd = rsqrtf(var + LN_EPS);
    }
    __syncthreads();
    const float mu = s_mu, rstd = s_rstd;

    float4 gv = ((const float4*)g)[tid];
    float4 bv = ((const float4*)beta)[tid];
    float4 o;
    o.x = (v0 - mu) * rstd * gv.x + bv.x;
    o.y = (v1 - mu) * rstd * gv.y + bv.y;
    o.z = (v2 - mu) * rstd * gv.z + bv.z;
    o.w = (v3 - mu) * rstd * gv.w + bv.w;
    ((float4*)(out + base))[tid] = o;
    if (WRITEH) {
        __half2 h0 = __floats2half2_rn(o.x, o.y);
        __half2 h1 = __floats2half2_rn(o.z, o.w);
        ((__half2*)(outh + base))[2 * tid]     = h0;
        ((__half2*)(outh + base))[2 * tid + 1] = h1;
    }
}

// ---------------------------------------------------------------------------
// Launcher
// ---------------------------------------------------------------------------
extern "C" void kernel_launch(void* const* d_in, const int* in_sizes, int n_in,
                              void* d_out, int out_size)
{
    (void)in_sizes; (void)n_in; (void)out_size;
    const float* x          = (const float*)d_in[0];
    const int*   positions  = (const int*)  d_in[1];
    const float* Wq         = (const float*)d_in[2];
    const float* bq         = (const float*)d_in[3];
    const float* Wk         = (const float*)d_in[4];
    const float* bk         = (const float*)d_in[5];
    const float* Wv         = (const float*)d_in[6];
    const float* bv         = (const float*)d_in[7];
    const float* Wo         = (const float*)d_in[8];
    const float* bo         = (const float*)d_in[9];
    const float* phase_bias = (const float*)d_in[10];
    const float* freqs      = (const float*)d_in[11];
    const float* W1         = (const float*)d_in[12];
    const float* b1         = (const float*)d_in[13];
    const float* W2         = (const float*)d_in[14];
    const float* b2         = (const float*)d_in[15];
    const float* g1         = (const float*)d_in[16];
    const float* beta1      = (const float*)d_in[17];
    const float* g2         = (const float*)d_in[18];
    const float* beta2      = (const float*)d_in[19];
    float* outp             = (float*)d_out;

    float  *bufQ, *bufK, *bufX1;
    __half *xh, *bufVh, *QPh, *KPh, *AttnH, *X1h, *FFh;
    __half *WqT, *WkT, *WvT, *WoT, *W1T, *W2T;
    cudaGetSymbolAddress((void**)&bufQ,  g_bufQ);
    cudaGetSymbolAddress((void**)&bufK,  g_bufK);
    cudaGetSymbolAddress((void**)&bufX1, g_bufX1);
    cudaGetSymbolAddress((void**)&xh,    g_xh);
    cudaGetSymbolAddress((void**)&bufVh, g_bufVh);
    cudaGetSymbolAddress((void**)&QPh,   g_QPh);
    cudaGetSymbolAddress((void**)&KPh,   g_KPh);
    cudaGetSymbolAddress((void**)&AttnH, g_AttnH);
    cudaGetSymbolAddress((void**)&X1h,   g_X1h);
    cudaGetSymbolAddress((void**)&FFh,   g_FFh);
    cudaGetSymbolAddress((void**)&WqT,   g_WqT);
    cudaGetSymbolAddress((void**)&WkT,   g_WkT);
    cudaGetSymbolAddress((void**)&WvT,   g_WvT);
    cudaGetSymbolAddress((void**)&WoT,   g_WoT);
    cudaGetSymbolAddress((void**)&W1T,   g_W1T);
    cudaGetSymbolAddress((void**)&W2T,   g_W2T);

    cudaFuncSetAttribute(attn_h_kernel, cudaFuncAttributeMaxDynamicSharedMemorySize,
                         AT_SMEM_BYTES);
    cudaFuncSetAttribute(hgemm_kernel<0,0>, cudaFuncAttributeMaxDynamicSharedMemorySize,
                         HG_SMEM_BYTES);
    cudaFuncSetAttribute(hgemm_kernel<0,1>, cudaFuncAttributeMaxDynamicSharedMemorySize,
                         HG_SMEM_BYTES);
    cudaFuncSetAttribute(hgemm_kernel<1,1>, cudaFuncAttributeMaxDynamicSharedMemorySize,
                         HG_SMEM_BYTES);

    // 0a: x -> fp16
    f2h_kernel<<<(BS * DMODEL / 8 + 255) / 256, 256>>>(x, xh, BS * DMODEL);

    // 0b: weight transposes + fp16
    {
        dim3 blk(32, 8);
        transpose_h_kernel<<<dim3(DMODEL/32, DMODEL/32), blk>>>(Wq, WqT, DMODEL, DMODEL);
        transpose_h_kernel<<<dim3(DMODEL/32, DMODEL/32), blk>>>(Wk, WkT, DMODEL, DMODEL);
        transpose_h_kernel<<<dim3(DMODEL/32, DMODEL/32), blk>>>(Wv, WvT, DMODEL, DMODEL);
        transpose_h_kernel<<<dim3(DMODEL/32, DMODEL/32), blk>>>(Wo, WoT, DMODEL, DMODEL);
        transpose_h_kernel<<<dim3(DFF/32,    DMODEL/32), blk>>>(W1, W1T, DMODEL, DFF);
        transpose_h_kernel<<<dim3(DMODEL/32, DFF/32),    blk>>>(W2, W2T, DFF, DMODEL);
    }

    // 1-3: QKV projections (fp16 mma). Q/K -> fp32 (pope input), V -> fp16.
    {
        dim3 grid(DMODEL / 128, BS / 128);
        hgemm_kernel<0,0><<<grid, 256, HG_SMEM_BYTES>>>(xh, WqT, bq, bufQ,  BS, DMODEL, DMODEL);
        hgemm_kernel<0,0><<<grid, 256, HG_SMEM_BYTES>>>(xh, WkT, bk, bufK,  BS, DMODEL, DMODEL);
        hgemm_kernel<0,1><<<grid, 256, HG_SMEM_BYTES>>>(xh, WvT, bv, bufVh, BS, DMODEL, DMODEL);
    }

    // 4: PoPE -> fp16 qp/kp
    {
        int total = BATCH * NHEADS * SEQ * 32;
        pope_kernel<<<(total + 255) / 256, 256>>>(bufQ, bufK, positions, freqs,
                                                  phase_bias, QPh, KPh);
    }

    // 5: attention -> fp16
    {
        dim3 grid(SEQ / 128, NHEADS, BATCH);
        attn_h_kernel<<<grid, 256, AT_SMEM_BYTES>>>(QPh, KPh, bufVh, AttnH);
    }

    // 6: output projection -> fp32 (bufQ reuse)
    {
        dim3 grid(DMODEL / 128, BS / 128);
        hgemm_kernel<0,0><<<grid, 256, HG_SMEM_BYTES>>>(AttnH, WoT, bo, bufQ, BS, DMODEL, DMODEL);
    }

    // 7: residual + LN1 -> fp32 + fp16
    add_ln_kernel<1><<<BS, 256>>>(x, bufQ, g1, beta1, bufX1, X1h);

    // 8: FFN up + ReLU -> fp16
    {
        dim3 grid(DFF / 128, BS / 128);
        hgemm_kernel<1,1><<<grid, 256, HG_SMEM_BYTES>>>(X1h, W1T, b1, FFh, BS, DFF, DMODEL);
    }

    // 9: FFN down -> fp32 (bufK reuse)
    {
        dim3 grid(DMODEL / 128, BS / 128);
        hgemm_kernel<0,0><<<grid, 256, HG_SMEM_BYTES>>>(FFh, W2T, b2, bufK, BS, DMODEL, DFF);
    }

    // 10: residual + LN2 -> output
    add_ln_kernel<0><<<BS, 256>>>(bufX1, bufK, g2, beta2, outp, nullptr);
}

// round 8
// speedup vs baseline: 5.2154x; 1.1247x over previous
#include <cuda_runtime.h>
#include <cuda_fp16.h>
#include <math.h>
#include <stdint.h>

// ---------------------------------------------------------------------------
// Problem constants
// ---------------------------------------------------------------------------
#define BATCH   2
#define SEQ     2048
#define DMODEL  1024
#define NHEADS  16
#define HEADDIM 64
#define DFF     4096
#define BS      (BATCH * SEQ)          // 4096 rows
#define LN_EPS  1e-5f
#define ATTN_SCALE 0.08838834764831845f   // 1/sqrt(128)
#define QKVN    (3 * DMODEL)           // fused QKV width

// ---------------------------------------------------------------------------
// Scratch buffers
// ---------------------------------------------------------------------------
__device__ float  g_bufA   [BS * DMODEL];            // Wo out (fp32)
__device__ float  g_bufB   [BS * DMODEL];            // FFN2 out (fp32)
__device__ float  g_bufX1  [BS * DMODEL];            // LN1 out fp32
__device__ __half g_xh     [BS * DMODEL];            // x in fp16
__device__ __half g_QKVh   [BS * QKVN];              // fused QKV output fp16
__device__ __half g_QPh    [BATCH * NHEADS * SEQ * 2 * HEADDIM];
__device__ __half g_KPh    [BATCH * NHEADS * SEQ * 2 * HEADDIM];
__device__ __half g_AttnH  [BS * DMODEL];            // attention out fp16
__device__ __half g_X1h    [BS * DMODEL];            // LN1 out fp16
__device__ __half g_FFh    [BS * DFF];               // FFN hidden fp16

// Pre-transposed fp16 weights: [N][K]
__device__ __half g_WqkvT[QKVN * DMODEL];            // rows: Wq | Wk | Wv
__device__ float  g_bqkv [QKVN];
__device__ __half g_WoT[DMODEL * DMODEL];
__device__ __half g_W1T[DMODEL * DFF];
__device__ __half g_W2T[DFF * DMODEL];

// ---------------------------------------------------------------------------
// Helpers
// ---------------------------------------------------------------------------
__device__ __forceinline__ uint32_t smem_u32(const void* p) {
    uint32_t a;
    asm("{ .reg .u64 t; cvta.to.shared.u64 t, %1; cvt.u32.u64 %0, t; }"
        : "=r"(a) : "l"(p));
    return a;
}

__device__ __forceinline__ void cp_async16(uint32_t saddr, const void* gptr) {
    asm volatile("cp.async.cg.shared.global [%0], [%1], 16;"
                 :: "r"(saddr), "l"(gptr) : "memory");
}

// fp16 mma m16n8k16, fp32 accumulate
__device__ __forceinline__ void mma_f16(float (&d)[4],
                                        const uint32_t (&a)[4],
                                        uint32_t b0, uint32_t b1)
{
    asm volatile(
        "mma.sync.aligned.m16n8k16.row.col.f32.f16.f16.f32 "
        "{%0,%1,%2,%3}, {%4,%5,%6,%7}, {%8,%9}, {%0,%1,%2,%3};"
        : "+f"(d[0]), "+f"(d[1]), "+f"(d[2]), "+f"(d[3])
        : "r"(a[0]), "r"(a[1]), "r"(a[2]), "r"(a[3]), "r"(b0), "r"(b1));
}

__device__ __forceinline__ void ldsm_x4(uint32_t (&r)[4], uint32_t saddr) {
    asm volatile("ldmatrix.sync.aligned.m8n8.x4.shared.b16 {%0,%1,%2,%3}, [%4];"
                 : "=r"(r[0]), "=r"(r[1]), "=r"(r[2]), "=r"(r[3]) : "r"(saddr));
}

// ---------------------------------------------------------------------------
// fp32 -> fp16 convert (8 elements per thread)
// ---------------------------------------------------------------------------
__global__ __launch_bounds__(256)
void f2h_kernel(const float* __restrict__ in, __half* __restrict__ out, int n)
{
    int i = (blockIdx.x * blockDim.x + threadIdx.x) * 8;
    if (i >= n) return;
    float4 a = *(const float4*)(in + i);
    float4 b = *(const float4*)(in + i + 4);
    __half2 h[4];
    h[0] = __floats2half2_rn(a.x, a.y);
    h[1] = __floats2half2_rn(a.z, a.w);
    h[2] = __floats2half2_rn(b.x, b.y);
    h[3] = __floats2half2_rn(b.z, b.w);
    *(uint4*)(out + i) = *(uint4*)h;
}

// ---------------------------------------------------------------------------
// Weight transpose + fp16: in[K][N] fp32 -> out[N][K] fp16
// ---------------------------------------------------------------------------
__global__ __launch_bounds__(256)
void transpose_h_kernel(const float* __restrict__ in, __half* __restrict__ out,
                        int K, int N)
{
    __shared__ float t[32][33];
    const int n0 = blockIdx.x * 32, k0 = blockIdx.y * 32;
    const int tx = threadIdx.x, ty = threadIdx.y;
#pragma unroll
    for (int i = 0; i < 32; i += 8)
        t[ty + i][tx] = in[(size_t)(k0 + ty + i) * N + n0 + tx];
    __syncthreads();
#pragma unroll
    for (int i = 0; i < 32; i += 8)
        out[(size_t)(n0 + ty + i) * K + k0 + tx] = __float2half_rn(t[tx][ty + i]);
}

// Batched QKV transpose: z selects Wq/Wk/Wv; writes into concat buffer
__global__ __launch_bounds__(256)
void transpose_h_qkv_kernel(const float* __restrict__ Wq,
                            const float* __restrict__ Wk,
                            const float* __restrict__ Wv,
                            __half* __restrict__ outT)
{
    __shared__ float t[32][33];
    const float* in = (blockIdx.z == 0) ? Wq : (blockIdx.z == 1) ? Wk : Wv;
    __half* out = outT + (size_t)blockIdx.z * DMODEL * DMODEL;
    const int n0 = blockIdx.x * 32, k0 = blockIdx.y * 32;
    const int tx = threadIdx.x, ty = threadIdx.y;
#pragma unroll
    for (int i = 0; i < 32; i += 8)
        t[ty + i][tx] = in[(size_t)(k0 + ty + i) * DMODEL + n0 + tx];
    __syncthreads();
#pragma unroll
    for (int i = 0; i < 32; i += 8)
        out[(size_t)(n0 + ty + i) * DMODEL + k0 + tx] = __float2half_rn(t[tx][ty + i]);
}

__global__ __launch_bounds__(256)
void concat_bias_kernel(const float* __restrict__ bq, const float* __restrict__ bk,
                        const float* __restrict__ bv, float* __restrict__ out)
{
    int i = blockIdx.x * 256 + threadIdx.x;
    if (i >= QKVN) return;
    float v = (i < DMODEL) ? bq[i] : (i < 2 * DMODEL) ? bk[i - DMODEL] : bv[i - 2 * DMODEL];
    out[i] = v;
}

// ---------------------------------------------------------------------------
// fp16 mma GEMM with ldmatrix fragment loads (unchanged structure).
// ---------------------------------------------------------------------------
#define HG_STRIDE 40
#define HG_STAGE  (128 * HG_STRIDE)                   // halves
#define HG_SMEM_BYTES (4 * HG_STAGE * 2)              // 40960 B

template<int RELU, int HALFOUT>
__global__ __launch_bounds__(256, 2)
void hgemm_kernel(const __half* __restrict__ A, const __half* __restrict__ Bt,
                  const float* __restrict__ bias, void* __restrict__ Cv,
                  int M, int N, int K)
{
    extern __shared__ __half hsm[];
    __half* As = hsm;
    __half* Bs = hsm + 2 * HG_STAGE;

    const int tid  = threadIdx.x;
    const int lane = tid & 31, wid = tid >> 5;
    const int wm = wid >> 1, wn = wid & 1;
    const int grp = lane >> 2, tig = lane & 3;
    const int m0 = blockIdx.y * 128, n0 = blockIdx.x * 128;

    const uint32_t asmem = smem_u32(As);
    const uint32_t bsmem = smem_u32(Bs);

    const int l8  = lane & 7;
    const int q01 = (lane >> 3) & 1;
    const int q23 = lane >> 4;

    float acc[2][8][4];
#pragma unroll
    for (int mi = 0; mi < 2; ++mi)
#pragma unroll
        for (int nj = 0; nj < 8; ++nj)
#pragma unroll
            for (int r = 0; r < 4; ++r) acc[mi][nj][r] = 0.f;

    auto load_tiles = [&](int stage, int k0) {
        uint32_t ab = asmem + stage * HG_STAGE * 2;
        uint32_t bb = bsmem + stage * HG_STAGE * 2;
#pragma unroll
        for (int i = 0; i < 2; ++i) {
            int idx = tid + i * 256;
            int r = idx >> 2, c = idx & 3;
            cp_async16(ab + (uint32_t)(r * HG_STRIDE + c * 8) * 2,
                       A + (size_t)(m0 + r) * K + k0 + c * 8);
            cp_async16(bb + (uint32_t)(r * HG_STRIDE + c * 8) * 2,
                       Bt + (size_t)(n0 + r) * K + k0 + c * 8);
        }
    };

    load_tiles(0, 0);
    asm volatile("cp.async.commit_group;" ::: "memory");

    const int nIt = K / 32;
    for (int it = 0; it < nIt; ++it) {
        if (it + 1 < nIt) {
            load_tiles((it + 1) & 1, (it + 1) * 32);
            asm volatile("cp.async.commit_group;" ::: "memory");
            asm volatile("cp.async.wait_group 1;" ::: "memory");
        } else {
            asm volatile("cp.async.wait_group 0;" ::: "memory");
        }
        __syncthreads();

        const uint32_t abase = asmem + (it & 1) * HG_STAGE * 2;
        const uint32_t bbase = bsmem + (it & 1) * HG_STAGE * 2;

#pragma unroll
        for (int kk = 0; kk < 2; ++kk) {
            const int k = kk * 16;
            uint32_t af[2][4];
#pragma unroll
            for (int mi = 0; mi < 2; ++mi) {
                int row = wm * 32 + mi * 16 + q01 * 8 + l8;
                int col = k + q23 * 8;
                ldsm_x4(af[mi], abase + (uint32_t)(row * HG_STRIDE + col) * 2);
            }
#pragma unroll
            for (int g = 0; g < 4; ++g) {
                uint32_t bf[4];
                int row = wn * 64 + g * 16 + q23 * 8 + l8;
                int col = k + q01 * 8;
                ldsm_x4(bf, bbase + (uint32_t)(row * HG_STRIDE + col) * 2);
#pragma unroll
                for (int h2 = 0; h2 < 2; ++h2)
#pragma unroll
                    for (int mi = 0; mi < 2; ++mi)
                        mma_f16(acc[mi][g * 2 + h2], af[mi], bf[h2 * 2], bf[h2 * 2 + 1]);
            }
        }
        __syncthreads();
    }

#pragma unroll
    for (int mi = 0; mi < 2; ++mi) {
        int r = m0 + wm * 32 + mi * 16 + grp;
#pragma unroll
        for (int nj = 0; nj < 8; ++nj) {
            int c = n0 + wn * 64 + nj * 8 + tig * 2;
            float bb0 = bias[c], bb1 = bias[c + 1];
            float v0 = acc[mi][nj][0] + bb0;
            float v1 = acc[mi][nj][1] + bb1;
            float v2 = acc[mi][nj][2] + bb0;
            float v3 = acc[mi][nj][3] + bb1;
            if (RELU) {
                v0 = fmaxf(v0, 0.f); v1 = fmaxf(v1, 0.f);
                v2 = fmaxf(v2, 0.f); v3 = fmaxf(v3, 0.f);
            }
            if (HALFOUT) {
                __half* C = (__half*)Cv;
                *(__half2*)&C[(size_t)r * N + c]       = __floats2half2_rn(v0, v1);
                *(__half2*)&C[(size_t)(r + 8) * N + c] = __floats2half2_rn(v2, v3);
            } else {
                float* C = (float*)Cv;
                float2 lo; lo.x = v0; lo.y = v1;
                float2 hi; hi.x = v2; hi.y = v3;
                *(float2*)&C[(size_t)r * N + c]       = lo;
                *(float2*)&C[(size_t)(r + 8) * N + c] = hi;
            }
        }
    }
}

// ---------------------------------------------------------------------------
// PoPE transform: reads fused fp16 QKV buffer, writes fp16 qp/kp.
// ---------------------------------------------------------------------------
__device__ __forceinline__ float softplus_f(float x) {
    return fmaxf(x, 0.f) + log1pf(expf(-fabsf(x)));
}

__global__ void pope_kernel(const __half* __restrict__ qkv,
                            const int* __restrict__ positions,
                            const float* __restrict__ freqs,
                            const float* __restrict__ phase_bias,
                            __half* __restrict__ qp, __half* __restrict__ kp)
{
    int idx = blockIdx.x * blockDim.x + threadIdx.x;   // B*H*S*32
    if (idx >= BATCH * NHEADS * SEQ * 32) return;
    int d = (idx & 31) * 2;
    int s = (idx >> 5) & (SEQ - 1);
    int h = (idx >> 16) & (NHEADS - 1);
    int b = idx >> 20;

    size_t rowb = (size_t)(b * SEQ + s) * QKVN + h * HEADDIM + d;
    float2 qv = __half22float2(*(const __half2*)&qkv[rowb]);
    float2 kv = __half22float2(*(const __half2*)&qkv[rowb + DMODEL]);

    float pos = (float)positions[s];
    float ph0 = pos * freqs[d]     + phase_bias[h * HEADDIM + d];
    float ph1 = pos * freqs[d + 1] + phase_bias[h * HEADDIM + d + 1];
    float c0, s0, c1, s1;
    sincosf(ph0, &s0, &c0);
    sincosf(ph1, &s1, &c1);

    float mq0 = softplus_f(qv.x) * ATTN_SCALE, mq1 = softplus_f(qv.y) * ATTN_SCALE;
    float mk0 = softplus_f(kv.x),              mk1 = softplus_f(kv.y);

    size_t base = (((size_t)(b * NHEADS + h) * SEQ) + s) * 128 + d;
    *(__half2*)&qp[base]      = __floats2half2_rn(mq0 * c0, mq1 * c1);
    *(__half2*)&qp[base + 64] = __floats2half2_rn(mq0 * s0, mq1 * s1);
    *(__half2*)&kp[base]      = __floats2half2_rn(mk0 * c0, mk1 * c1);
    *(__half2*)&kp[base + 64] = __floats2half2_rn(mk0 * s0, mk1 * s1);
}

// ---------------------------------------------------------------------------
// Flash attention with softmax1, fp16 mma + ldmatrix. 2 CTAs/SM.
// V is read from the fused QKV buffer (row stride QKVN, offset 2*DMODEL).
// ---------------------------------------------------------------------------
#define AT_QS 136
#define AT_PS 72
#define AT_VS 72
#define AT_SMEM_HALVES (128 * AT_QS + 64 * AT_QS + 64 * AT_VS)
#define AT_SMEM_BYTES  (AT_SMEM_HALVES * 2)

__global__ __launch_bounds__(256, 2)
void attn_h_kernel(const __half* __restrict__ qp, const __half* __restrict__ kp,
                   const __half* __restrict__ qkv, __half* __restrict__ out)
{
    extern __shared__ __half hsm[];
    __half* Qs = hsm;                     // 128 x 136 (staging)
    __half* Ps = hsm;                     // 128 x 72 (aliases Qs)
    __half* Ks = hsm + 128 * AT_QS;       // 64 x 136
    __half* Vt = Ks + 64 * AT_QS;         // 64(d) x 72(key)

    const int b = blockIdx.z;
    const int h = blockIdx.y;
    const int qtile = gridDim.x - 1 - blockIdx.x;   // heavy tiles first
    const int q0 = qtile * 128;

    const int tid  = threadIdx.x;
    const int lane = tid & 31, wid = tid >> 5;
    const int grp = lane >> 2, tig = lane & 3;
    const int r0 = wid * 16 + grp;

    const int l8  = lane & 7;
    const int q01 = (lane >> 3) & 1;
    const int q23 = lane >> 4;

    const uint32_t pssm = smem_u32(Ps);
    const uint32_t kssm = smem_u32(Ks);
    const uint32_t vtsm = smem_u32(Vt);

    const __half* qbase = qp + (((size_t)(b * NHEADS + h)) * SEQ) * 128;
    const __half* kbase = kp + (((size_t)(b * NHEADS + h)) * SEQ) * 128;
    const __half* vbase = qkv + 2 * DMODEL + h * HEADDIM;   // V columns in fused buffer

    // Stage Q: 128 rows x 128 halves = 2048 16B chunks
    for (int i = tid; i < 2048; i += 256) {
        int r = i >> 4, c = i & 15;
        *(uint4*)&Qs[r * AT_QS + c * 8] =
            *(const uint4*)&qbase[(size_t)(q0 + r) * 128 + c * 8];
    }
    __syncthreads();

    // Preload Q fragments via ldmatrix: 8 k16 chunks
    uint32_t qf[8][4];
    {
        const uint32_t qssm = smem_u32(Qs);
        int row = wid * 16 + q01 * 8 + l8;
#pragma unroll
        for (int kk = 0; kk < 8; ++kk) {
            int col = kk * 16 + q23 * 8;
            ldsm_x4(qf[kk], qssm + (uint32_t)(row * AT_QS + col) * 2);
        }
    }
    __syncthreads();   // done reading Qs before Ps overwrites

    float m0 = -INFINITY, m1 = -INFINITY, l0 = 0.f, l1 = 0.f;
    float o[8][4];
#pragma unroll
    for (int nj = 0; nj < 8; ++nj)
#pragma unroll
        for (int r = 0; r < 4; ++r) o[nj][r] = 0.f;

    for (int kt = 0; kt <= q0 + 64; kt += 64) {
        __syncthreads();

        // K tile: 64 x 128 halves = 1024 chunks
        for (int i = tid; i < 1024; i += 256) {
            int r = i >> 4, c = i & 15;
            *(uint4*)&Ks[r * AT_QS + c * 8] =
                *(const uint4*)&kbase[(size_t)(kt + r) * 128 + c * 8];
        }
        // V tile transposed: 64 keys x 64 dims (from fused QKV)
        for (int i = tid; i < 512; i += 256) {
            int r = i >> 3, c = i & 7;
            uint4 raw = *(const uint4*)&vbase[((size_t)b * SEQ + kt + r) * QKVN + c * 8];
            __half* hp = (__half*)&raw;
#pragma unroll
            for (int j = 0; j < 8; ++j)
                Vt[(c * 8 + j) * AT_VS + r] = hp[j];
        }
        __syncthreads();

        // scores = Q @ K^T
        float sacc[8][4];
#pragma unroll
        for (int nj = 0; nj < 8; ++nj)
#pragma unroll
            for (int r = 0; r < 4; ++r) sacc[nj][r] = 0.f;

#pragma unroll
        for (int kk = 0; kk < 8; ++kk) {
            int k = kk * 16;
#pragma unroll
            for (int g = 0; g < 4; ++g) {
                uint32_t bf[4];
                int row = g * 16 + q23 * 8 + l8;
                int col = k + q01 * 8;
                ldsm_x4(bf, kssm + (uint32_t)(row * AT_QS + col) * 2);
                mma_f16(sacc[g * 2 + 0], qf[kk], bf[0], bf[1]);
                mma_f16(sacc[g * 2 + 1], qf[kk], bf[2], bf[3]);
            }
        }

        // causal mask (last two key tiles only)
        if (kt >= q0) {
            int row0 = q0 + r0, row1 = row0 + 8;
#pragma unroll
            for (int nj = 0; nj < 8; ++nj) {
                int c = kt + nj * 8 + 2 * tig;
                if (c     > row0) sacc[nj][0] = -INFINITY;
                if (c + 1 > row0) sacc[nj][1] = -INFINITY;
                if (c     > row1) sacc[nj][2] = -INFINITY;
                if (c + 1 > row1) sacc[nj][3] = -INFINITY;
            }
        }

        // online softmax1
        float mx0 = -INFINITY, mx1 = -INFINITY;
#pragma unroll
        for (int nj = 0; nj < 8; ++nj) {
            mx0 = fmaxf(mx0, fmaxf(sacc[nj][0], sacc[nj][1]));
            mx1 = fmaxf(mx1, fmaxf(sacc[nj][2], sacc[nj][3]));
        }
        mx0 = fmaxf(mx0, __shfl_xor_sync(0xffffffffu, mx0, 1));
        mx0 = fmaxf(mx0, __shfl_xor_sync(0xffffffffu, mx0, 2));
        mx1 = fmaxf(mx1, __shfl_xor_sync(0xffffffffu, mx1, 1));
        mx1 = fmaxf(mx1, __shfl_xor_sync(0xffffffffu, mx1, 2));

        float m0n = fmaxf(m0, mx0), m1n = fmaxf(m1, mx1);
        float c0 = expf(m0 - m0n),  c1 = expf(m1 - m1n);
        m0 = m0n; m1 = m1n;

        float ls0 = 0.f, ls1 = 0.f;
#pragma unroll
        for (int nj = 0; nj < 8; ++nj) {
            float p0 = expf(sacc[nj][0] - m0n);
            float p1 = expf(sacc[nj][1] - m0n);
            float p2 = expf(sacc[nj][2] - m1n);
            float p3 = expf(sacc[nj][3] - m1n);
            ls0 += p0 + p1; ls1 += p2 + p3;
            *(__half2*)&Ps[r0       * AT_PS + nj * 8 + 2 * tig] = __floats2half2_rn(p0, p1);
            *(__half2*)&Ps[(r0 + 8) * AT_PS + nj * 8 + 2 * tig] = __floats2half2_rn(p2, p3);
        }
        ls0 += __shfl_xor_sync(0xffffffffu, ls0, 1);
        ls0 += __shfl_xor_sync(0xffffffffu, ls0, 2);
        ls1 += __shfl_xor_sync(0xffffffffu, ls1, 1);
        ls1 += __shfl_xor_sync(0xffffffffu, ls1, 2);
        l0 = l0 * c0 + ls0;
        l1 = l1 * c1 + ls1;

#pragma unroll
        for (int nj = 0; nj < 8; ++nj) {
            o[nj][0] *= c0; o[nj][1] *= c0;
            o[nj][2] *= c1; o[nj][3] *= c1;
        }
        __syncwarp();

        // O += P @ V  (4 k16 chunks over 64 keys)
#pragma unroll
        for (int kk = 0; kk < 4; ++kk) {
            int k = kk * 16;
            uint32_t af[4];
            {
                int row = wid * 16 + q01 * 8 + l8;
                int col = k + q23 * 8;
                ldsm_x4(af, pssm + (uint32_t)(row * AT_PS + col) * 2);
            }
#pragma unroll
            for (int g = 0; g < 4; ++g) {
                uint32_t bf[4];
                int row = g * 16 + q23 * 8 + l8;
                int col = k + q01 * 8;
                ldsm_x4(bf, vtsm + (uint32_t)(row * AT_VS + col) * 2);
                mma_f16(o[g * 2 + 0], af, bf[0], bf[1]);
                mma_f16(o[g * 2 + 1], af, bf[2], bf[3]);
            }
        }
    }

    // epilogue: softmax1 denominator; write fp16 (B,S,D)
    float inv0 = 1.f / (1.f + l0);
    float inv1 = 1.f / (1.f + l1);
    int row0 = q0 + r0;
#pragma unroll
    for (int nj = 0; nj < 8; ++nj) {
        int c = h * HEADDIM + nj * 8 + 2 * tig;
        *(__half2*)&out[((size_t)b * SEQ + row0)     * DMODEL + c] =
            __floats2half2_rn(o[nj][0] * inv0, o[nj][1] * inv0);
        *(__half2*)&out[((size_t)b * SEQ + row0 + 8) * DMODEL + c] =
            __floats2half2_rn(o[nj][2] * inv1, o[nj][3] * inv1);
    }
}

// ---------------------------------------------------------------------------
// Fused residual add + LayerNorm; optional fp16 copy of the output.
// ---------------------------------------------------------------------------
template<int WRITEH>
__global__ __launch_bounds__(256)
void add_ln_kernel(const float* __restrict__ x, const float* __restrict__ y,
                   const float* __restrict__ g, const float* __restrict__ beta,
                   float* __restrict__ out, __half* __restrict__ outh)
{
    __shared__ float red_s[8];
    __shared__ float red_ss[8];
    __shared__ float s_mu, s_rstd;

    const int row = blockIdx.x;
    const int tid = threadIdx.x;
    const size_t base = (size_t)row * DMODEL;

    float4 xv = ((const float4*)(x + base))[tid];
    float4 yv = ((const float4*)(y + base))[tid];
    float v0 = xv.x + yv.x, v1 = xv.y + yv.y, v2 = xv.z + yv.z, v3 = xv.w + yv.w;

    float sum = v0 + v1 + v2 + v3;
    float ssq = v0 * v0 + v1 * v1 + v2 * v2 + v3 * v3;
#pragma unroll
    for (int off = 16; off >= 1; off >>= 1) {
        sum += __shfl_down_sync(0xffffffffu, sum, off);
        ssq += __shfl_down_sync(0xffffffffu, ssq, off);
    }
    const int warp = tid >> 5;
    if ((tid & 31) == 0) { red_s[warp] = sum; red_ss[warp] = ssq; }
    __syncthreads();
    if (tid == 0) {
        float ts = 0.f, tss = 0.f;
#pragma unroll
        for (int w = 0; w < 8; ++w) { ts += red_s[w]; tss += red_ss[w]; }
        float mu  = ts / (float)DMODEL;
        float var = tss / (float)DMODEL - mu * mu;
        s_mu = mu;
        s_rstd = rsqrtf(var + LN_EPS);
    }
    __syncthreads();
    const float mu = s_mu, rstd = s_rstd;

    float4 gv = ((const float4*)g)[tid];
    float4 bv = ((const float4*)beta)[tid];
    float4 o;
    o.x = (v0 - mu) * rstd * gv.x + bv.x;
    o.y = (v1 - mu) * rstd * gv.y + bv.y;
    o.z = (v2 - mu) * rstd * gv.z + bv.z;
    o.w = (v3 - mu) * rstd * gv.w + bv.w;
    ((float4*)(out + base))[tid] = o;
    if (WRITEH) {
        __half2 h0 = __floats2half2_rn(o.x, o.y);
        __half2 h1 = __floats2half2_rn(o.z, o.w);
        ((__half2*)(outh + base))[2 * tid]     = h0;
        ((__half2*)(outh + base))[2 * tid + 1] = h1;
    }
}

// ---------------------------------------------------------------------------
// Launcher
// ---------------------------------------------------------------------------
extern "C" void kernel_launch(void* const* d_in, const int* in_sizes, int n_in,
                              void* d_out, int out_size)
{
    (void)in_sizes; (void)n_in; (void)out_size;
    const float* x          = (const float*)d_in[0];
    const int*   positions  = (const int*)  d_in[1];
    const float* Wq         = (const float*)d_in[2];
    const float* bq         = (const float*)d_in[3];
    const float* Wk         = (const float*)d_in[4];
    const float* bk         = (const float*)d_in[5];
    const float* Wv         = (const float*)d_in[6];
    const float* bv         = (const float*)d_in[7];
    const float* Wo         = (const float*)d_in[8];
    const float* bo         = (const float*)d_in[9];
    const float* phase_bias = (const float*)d_in[10];
    const float* freqs      = (const float*)d_in[11];
    const float* W1         = (const float*)d_in[12];
    const float* b1         = (const float*)d_in[13];
    const float* W2         = (const float*)d_in[14];
    const float* b2         = (const float*)d_in[15];
    const float* g1         = (const float*)d_in[16];
    const float* beta1      = (const float*)d_in[17];
    const float* g2         = (const float*)d_in[18];
    const float* beta2      = (const float*)d_in[19];
    float* outp             = (float*)d_out;

    float  *bufA, *bufB, *bufX1, *bqkv;
    __half *xh, *QKVh, *QPh, *KPh, *AttnH, *X1h, *FFh;
    __half *WqkvT, *WoT, *W1T, *W2T;
    cudaGetSymbolAddress((void**)&bufA,  g_bufA);
    cudaGetSymbolAddress((void**)&bufB,  g_bufB);
    cudaGetSymbolAddress((void**)&bufX1, g_bufX1);
    cudaGetSymbolAddress((void**)&bqkv,  g_bqkv);
    cudaGetSymbolAddress((void**)&xh,    g_xh);
    cudaGetSymbolAddress((void**)&QKVh,  g_QKVh);
    cudaGetSymbolAddress((void**)&QPh,   g_QPh);
    cudaGetSymbolAddress((void**)&KPh,   g_KPh);
    cudaGetSymbolAddress((void**)&AttnH, g_AttnH);
    cudaGetSymbolAddress((void**)&X1h,   g_X1h);
    cudaGetSymbolAddress((void**)&FFh,   g_FFh);
    cudaGetSymbolAddress((void**)&WqkvT, g_WqkvT);
    cudaGetSymbolAddress((void**)&WoT,   g_WoT);
    cudaGetSymbolAddress((void**)&W1T,   g_W1T);
    cudaGetSymbolAddress((void**)&W2T,   g_W2T);

    cudaFuncSetAttribute(attn_h_kernel, cudaFuncAttributeMaxDynamicSharedMemorySize,
                         AT_SMEM_BYTES);
    cudaFuncSetAttribute(hgemm_kernel<0,0>, cudaFuncAttributeMaxDynamicSharedMemorySize,
                         HG_SMEM_BYTES);
    cudaFuncSetAttribute(hgemm_kernel<0,1>, cudaFuncAttributeMaxDynamicSharedMemorySize,
                         HG_SMEM_BYTES);
    cudaFuncSetAttribute(hgemm_kernel<1,1>, cudaFuncAttributeMaxDynamicSharedMemorySize,
                         HG_SMEM_BYTES);

    // 0a: x -> fp16
    f2h_kernel<<<(BS * DMODEL / 8 + 255) / 256, 256>>>(x, xh, BS * DMODEL);

    // 0b: weight transposes + fp16 (QKV batched into concat buffer)
    {
        dim3 blk(32, 8);
        transpose_h_qkv_kernel<<<dim3(DMODEL/32, DMODEL/32, 3), blk>>>(Wq, Wk, Wv, WqkvT);
        transpose_h_kernel<<<dim3(DMODEL/32, DMODEL/32), blk>>>(Wo, WoT, DMODEL, DMODEL);
        transpose_h_kernel<<<dim3(DFF/32,    DMODEL/32), blk>>>(W1, W1T, DMODEL, DFF);
        transpose_h_kernel<<<dim3(DMODEL/32, DFF/32),    blk>>>(W2, W2T, DFF, DMODEL);
        concat_bias_kernel<<<(QKVN + 255) / 256, 256>>>(bq, bk, bv, bqkv);
    }

    // 1: fused QKV projection (N=3072), fp16 out
    {
        dim3 grid(QKVN / 128, BS / 128);
        hgemm_kernel<0,1><<<grid, 256, HG_SMEM_BYTES>>>(xh, WqkvT, bqkv, QKVh, BS, QKVN, DMODEL);
    }

    // 2: PoPE (fp16 in/out)
    {
        int total = BATCH * NHEADS * SEQ * 32;
        pope_kernel<<<(total + 255) / 256, 256>>>(QKVh, positions, freqs,
                                                  phase_bias, QPh, KPh);
    }

    // 3: attention -> fp16
    {
        dim3 grid(SEQ / 128, NHEADS, BATCH);
        attn_h_kernel<<<grid, 256, AT_SMEM_BYTES>>>(QPh, KPh, QKVh, AttnH);
    }

    // 4: output projection -> fp32
    {
        dim3 grid(DMODEL / 128, BS / 128);
        hgemm_kernel<0,0><<<grid, 256, HG_SMEM_BYTES>>>(AttnH, WoT, bo, bufA, BS, DMODEL, DMODEL);
    }

    // 5: residual + LN1 -> fp32 + fp16
    add_ln_kernel<1><<<BS, 256>>>(x, bufA, g1, beta1, bufX1, X1h);

    // 6: FFN up + ReLU -> fp16
    {
        dim3 grid(DFF / 128, BS / 128);
        hgemm_kernel<1,1><<<grid, 256, HG_SMEM_BYTES>>>(X1h, W1T, b1, FFh, BS, DFF, DMODEL);
    }

    // 7: FFN down -> fp32
    {
        dim3 grid(DMODEL / 128, BS / 128);
        hgemm_kernel<0,0><<<grid, 256, HG_SMEM_BYTES>>>(FFh, W2T, b2, bufB, BS, DMODEL, DFF);
    }

    // 8: residual + LN2 -> output
    add_ln_kernel<0><<<BS, 256>>>(bufX1, bufB, g2, beta2, outp, nullptr);
}

// round 9
// speedup vs baseline: 5.9609x; 1.1429x over previous
#include <cuda_runtime.h>
#include <cuda_fp16.h>
#include <math.h>
#include <stdint.h>

// ---------------------------------------------------------------------------
// Problem constants
// ---------------------------------------------------------------------------
#define BATCH   2
#define SEQ     2048
#define DMODEL  1024
#define NHEADS  16
#define HEADDIM 64
#define DFF     4096
#define BS      (BATCH * SEQ)          // 4096 rows
#define LN_EPS  1e-5f
#define ATTN_SCALE 0.08838834764831845f   // 1/sqrt(128)
#define QKVN    (3 * DMODEL)           // fused QKV width

// ---------------------------------------------------------------------------
// Scratch buffers
// ---------------------------------------------------------------------------
__device__ float  g_bufA   [BS * DMODEL];            // Wo out (fp32)
__device__ float  g_bufB   [BS * DMODEL];            // FFN2 out (fp32)
__device__ float  g_bufX1  [BS * DMODEL];            // LN1 out fp32
__device__ __half g_xh     [BS * DMODEL];            // x in fp16
__device__ __half g_QKVh   [BS * QKVN];              // fused QKV output fp16
__device__ __half g_QPh    [BATCH * NHEADS * SEQ * 2 * HEADDIM];
__device__ __half g_KPh    [BATCH * NHEADS * SEQ * 2 * HEADDIM];
__device__ __half g_AttnH  [BS * DMODEL];            // attention out fp16
__device__ __half g_X1h    [BS * DMODEL];            // LN1 out fp16
__device__ __half g_FFh    [BS * DFF];               // FFN hidden fp16

// Pre-transposed fp16 weights: [N][K]
__device__ __half g_WqkvT[QKVN * DMODEL];            // rows: Wq | Wk | Wv
__device__ float  g_bqkv [QKVN];
__device__ __half g_WoT[DMODEL * DMODEL];
__device__ __half g_W1T[DMODEL * DFF];
__device__ __half g_W2T[DFF * DMODEL];

// ---------------------------------------------------------------------------
// Helpers
// ---------------------------------------------------------------------------
__device__ __forceinline__ uint32_t smem_u32(const void* p) {
    uint32_t a;
    asm("{ .reg .u64 t; cvta.to.shared.u64 t, %1; cvt.u32.u64 %0, t; }"
        : "=r"(a) : "l"(p));
    return a;
}

__device__ __forceinline__ void cp_async16(uint32_t saddr, const void* gptr) {
    asm volatile("cp.async.cg.shared.global [%0], [%1], 16;"
                 :: "r"(saddr), "l"(gptr) : "memory");
}

// fp16 mma m16n8k16, fp32 accumulate
__device__ __forceinline__ void mma_f16(float (&d)[4],
                                        const uint32_t (&a)[4],
                                        uint32_t b0, uint32_t b1)
{
    asm volatile(
        "mma.sync.aligned.m16n8k16.row.col.f32.f16.f16.f32 "
        "{%0,%1,%2,%3}, {%4,%5,%6,%7}, {%8,%9}, {%0,%1,%2,%3};"
        : "+f"(d[0]), "+f"(d[1]), "+f"(d[2]), "+f"(d[3])
        : "r"(a[0]), "r"(a[1]), "r"(a[2]), "r"(a[3]), "r"(b0), "r"(b1));
}

__device__ __forceinline__ void ldsm_x4(uint32_t (&r)[4], uint32_t saddr) {
    asm volatile("ldmatrix.sync.aligned.m8n8.x4.shared.b16 {%0,%1,%2,%3}, [%4];"
                 : "=r"(r[0]), "=r"(r[1]), "=r"(r[2]), "=r"(r[3]) : "r"(saddr));
}

__device__ __forceinline__ void ldsm_x4_t(uint32_t (&r)[4], uint32_t saddr) {
    asm volatile("ldmatrix.sync.aligned.m8n8.x4.trans.shared.b16 {%0,%1,%2,%3}, [%4];"
                 : "=r"(r[0]), "=r"(r[1]), "=r"(r[2]), "=r"(r[3]) : "r"(saddr));
}

// ---------------------------------------------------------------------------
// fp32 -> fp16 convert (8 elements per thread)
// ---------------------------------------------------------------------------
__global__ __launch_bounds__(256)
void f2h_kernel(const float* __restrict__ in, __half* __restrict__ out, int n)
{
    int i = (blockIdx.x * blockDim.x + threadIdx.x) * 8;
    if (i >= n) return;
    float4 a = *(const float4*)(in + i);
    float4 b = *(const float4*)(in + i + 4);
    __half2 h[4];
    h[0] = __floats2half2_rn(a.x, a.y);
    h[1] = __floats2half2_rn(a.z, a.w);
    h[2] = __floats2half2_rn(b.x, b.y);
    h[3] = __floats2half2_rn(b.z, b.w);
    *(uint4*)(out + i) = *(uint4*)h;
}

// ---------------------------------------------------------------------------
// Weight transpose + fp16: in[K][N] fp32 -> out[N][K] fp16
// ---------------------------------------------------------------------------
__global__ __launch_bounds__(256)
void transpose_h_kernel(const float* __restrict__ in, __half* __restrict__ out,
                        int K, int N)
{
    __shared__ float t[32][33];
    const int n0 = blockIdx.x * 32, k0 = blockIdx.y * 32;
    const int tx = threadIdx.x, ty = threadIdx.y;
#pragma unroll
    for (int i = 0; i < 32; i += 8)
        t[ty + i][tx] = in[(size_t)(k0 + ty + i) * N + n0 + tx];
    __syncthreads();
#pragma unroll
    for (int i = 0; i < 32; i += 8)
        out[(size_t)(n0 + ty + i) * K + k0 + tx] = __float2half_rn(t[tx][ty + i]);
}

// Batched QKV transpose: z selects Wq/Wk/Wv; writes into concat buffer
__global__ __launch_bounds__(256)
void transpose_h_qkv_kernel(const float* __restrict__ Wq,
                            const float* __restrict__ Wk,
                            const float* __restrict__ Wv,
                            __half* __restrict__ outT)
{
    __shared__ float t[32][33];
    const float* in = (blockIdx.z == 0) ? Wq : (blockIdx.z == 1) ? Wk : Wv;
    __half* out = outT + (size_t)blockIdx.z * DMODEL * DMODEL;
    const int n0 = blockIdx.x * 32, k0 = blockIdx.y * 32;
    const int tx = threadIdx.x, ty = threadIdx.y;
#pragma unroll
    for (int i = 0; i < 32; i += 8)
        t[ty + i][tx] = in[(size_t)(k0 + ty + i) * DMODEL + n0 + tx];
    __syncthreads();
#pragma unroll
    for (int i = 0; i < 32; i += 8)
        out[(size_t)(n0 + ty + i) * DMODEL + k0 + tx] = __float2half_rn(t[tx][ty + i]);
}

__global__ __launch_bounds__(256)
void concat_bias_kernel(const float* __restrict__ bq, const float* __restrict__ bk,
                        const float* __restrict__ bv, float* __restrict__ out)
{
    int i = blockIdx.x * 256 + threadIdx.x;
    if (i >= QKVN) return;
    float v = (i < DMODEL) ? bq[i] : (i < 2 * DMODEL) ? bk[i - DMODEL] : bv[i - 2 * DMODEL];
    out[i] = v;
}

// ---------------------------------------------------------------------------
// fp16 mma GEMM: 128x128x32 tiles, 8 warps, 4-stage cp.async pipeline with a
// single __syncthreads per K-iteration. ldmatrix fragment loads, stride 40.
// ---------------------------------------------------------------------------
#define HG_STRIDE 40
#define HG_STAGES 4
#define HG_STAGE_HALVES (2 * 128 * HG_STRIDE)         // A+B per stage
#define HG_SMEM_BYTES (HG_STAGES * HG_STAGE_HALVES * 2)   // 81920 B

template<int RELU, int HALFOUT>
__global__ __launch_bounds__(256, 2)
void hgemm_kernel(const __half* __restrict__ A, const __half* __restrict__ Bt,
                  const float* __restrict__ bias, void* __restrict__ Cv,
                  int M, int N, int K)
{
    extern __shared__ __half hsm[];

    const int tid  = threadIdx.x;
    const int lane = tid & 31, wid = tid >> 5;
    const int wm = wid >> 1, wn = wid & 1;
    const int grp = lane >> 2, tig = lane & 3;
    const int m0 = blockIdx.y * 128, n0 = blockIdx.x * 128;

    const uint32_t smbase = smem_u32(hsm);

    const int l8  = lane & 7;
    const int q01 = (lane >> 3) & 1;
    const int q23 = lane >> 4;

    float acc[2][8][4];
#pragma unroll
    for (int mi = 0; mi < 2; ++mi)
#pragma unroll
        for (int nj = 0; nj < 8; ++nj)
#pragma unroll
            for (int r = 0; r < 4; ++r) acc[mi][nj][r] = 0.f;

    auto load_tiles = [&](int stage, int k0) {
        uint32_t ab = smbase + stage * HG_STAGE_HALVES * 2;
        uint32_t bb = ab + 128 * HG_STRIDE * 2;
#pragma unroll
        for (int i = 0; i < 2; ++i) {
            int idx = tid + i * 256;
            int r = idx >> 2, c = idx & 3;
            cp_async16(ab + (uint32_t)(r * HG_STRIDE + c * 8) * 2,
                       A + (size_t)(m0 + r) * K + k0 + c * 8);
            cp_async16(bb + (uint32_t)(r * HG_STRIDE + c * 8) * 2,
                       Bt + (size_t)(n0 + r) * K + k0 + c * 8);
        }
    };

    const int nIt = K / 32;
#pragma unroll
    for (int s = 0; s < HG_STAGES - 1; ++s) {
        load_tiles(s, s * 32);
        asm volatile("cp.async.commit_group;" ::: "memory");
    }

    for (int it = 0; it < nIt; ++it) {
        asm volatile("cp.async.wait_group 2;" ::: "memory");
        __syncthreads();
        if (it + HG_STAGES - 1 < nIt) {
            load_tiles((it + HG_STAGES - 1) & (HG_STAGES - 1),
                       (it + HG_STAGES - 1) * 32);
            asm volatile("cp.async.commit_group;" ::: "memory");
        }

        const uint32_t abase = smbase + (it & (HG_STAGES - 1)) * HG_STAGE_HALVES * 2;
        const uint32_t bbase = abase + 128 * HG_STRIDE * 2;

#pragma unroll
        for (int kk = 0; kk < 2; ++kk) {
            const int k = kk * 16;
            uint32_t af[2][4];
#pragma unroll
            for (int mi = 0; mi < 2; ++mi) {
                int row = wm * 32 + mi * 16 + q01 * 8 + l8;
                int col = k + q23 * 8;
                ldsm_x4(af[mi], abase + (uint32_t)(row * HG_STRIDE + col) * 2);
            }
#pragma unroll
            for (int g = 0; g < 4; ++g) {
                uint32_t bf[4];
                int row = wn * 64 + g * 16 + q23 * 8 + l8;
                int col = k + q01 * 8;
                ldsm_x4(bf, bbase + (uint32_t)(row * HG_STRIDE + col) * 2);
#pragma unroll
                for (int h2 = 0; h2 < 2; ++h2)
#pragma unroll
                    for (int mi = 0; mi < 2; ++mi)
                        mma_f16(acc[mi][g * 2 + h2], af[mi], bf[h2 * 2], bf[h2 * 2 + 1]);
            }
        }
    }

#pragma unroll
    for (int mi = 0; mi < 2; ++mi) {
        int r = m0 + wm * 32 + mi * 16 + grp;
#pragma unroll
        for (int nj = 0; nj < 8; ++nj) {
            int c = n0 + wn * 64 + nj * 8 + tig * 2;
            float bb0 = bias[c], bb1 = bias[c + 1];
            float v0 = acc[mi][nj][0] + bb0;
            float v1 = acc[mi][nj][1] + bb1;
            float v2 = acc[mi][nj][2] + bb0;
            float v3 = acc[mi][nj][3] + bb1;
            if (RELU) {
                v0 = fmaxf(v0, 0.f); v1 = fmaxf(v1, 0.f);
                v2 = fmaxf(v2, 0.f); v3 = fmaxf(v3, 0.f);
            }
            if (HALFOUT) {
                __half* C = (__half*)Cv;
                *(__half2*)&C[(size_t)r * N + c]       = __floats2half2_rn(v0, v1);
                *(__half2*)&C[(size_t)(r + 8) * N + c] = __floats2half2_rn(v2, v3);
            } else {
                float* C = (float*)Cv;
                float2 lo; lo.x = v0; lo.y = v1;
                float2 hi; hi.x = v2; hi.y = v3;
                *(float2*)&C[(size_t)r * N + c]       = lo;
                *(float2*)&C[(size_t)(r + 8) * N + c] = hi;
            }
        }
    }
}

// ---------------------------------------------------------------------------
// PoPE transform: reads fused fp16 QKV buffer, writes fp16 qp/kp.
// ---------------------------------------------------------------------------
__device__ __forceinline__ float softplus_f(float x) {
    return fmaxf(x, 0.f) + log1pf(expf(-fabsf(x)));
}

__global__ void pope_kernel(const __half* __restrict__ qkv,
                            const int* __restrict__ positions,
                            const float* __restrict__ freqs,
                            const float* __restrict__ phase_bias,
                            __half* __restrict__ qp, __half* __restrict__ kp)
{
    int idx = blockIdx.x * blockDim.x + threadIdx.x;   // B*H*S*32
    if (idx >= BATCH * NHEADS * SEQ * 32) return;
    int d = (idx & 31) * 2;
    int s = (idx >> 5) & (SEQ - 1);
    int h = (idx >> 16) & (NHEADS - 1);
    int b = idx >> 20;

    size_t rowb = (size_t)(b * SEQ + s) * QKVN + h * HEADDIM + d;
    float2 qv = __half22float2(*(const __half2*)&qkv[rowb]);
    float2 kv = __half22float2(*(const __half2*)&qkv[rowb + DMODEL]);

    float pos = (float)positions[s];
    float ph0 = pos * freqs[d]     + phase_bias[h * HEADDIM + d];
    float ph1 = pos * freqs[d + 1] + phase_bias[h * HEADDIM + d + 1];
    float c0, s0, c1, s1;
    sincosf(ph0, &s0, &c0);
    sincosf(ph1, &s1, &c1);

    float mq0 = softplus_f(qv.x) * ATTN_SCALE, mq1 = softplus_f(qv.y) * ATTN_SCALE;
    float mk0 = softplus_f(kv.x),              mk1 = softplus_f(kv.y);

    size_t base = (((size_t)(b * NHEADS + h) * SEQ) + s) * 128 + d;
    *(__half2*)&qp[base]      = __floats2half2_rn(mq0 * c0, mq1 * c1);
    *(__half2*)&qp[base + 64] = __floats2half2_rn(mq0 * s0, mq1 * s1);
    *(__half2*)&kp[base]      = __floats2half2_rn(mk0 * c0, mk1 * c1);
    *(__half2*)&kp[base + 64] = __floats2half2_rn(mk0 * s0, mk1 * s1);
}

// ---------------------------------------------------------------------------
// Flash attention with softmax1, fp16 mma + ldmatrix. 2 CTAs/SM.
// Double-buffered cp.async K/V tiles, one __syncthreads per key tile.
// V kept row-major [key][dim]; PV B-fragments via ldmatrix.trans.
// ---------------------------------------------------------------------------
#define AT_QS 136
#define AT_PS 72
#define AT_KS 136
#define AT_VS 72
#define AT_Q_HALVES (128 * AT_QS)             // aliased by Ps (128 x 72)
#define AT_K_STAGE  (64 * AT_KS)
#define AT_V_STAGE  (64 * AT_VS)
#define AT_SMEM_HALVES (AT_Q_HALVES + 2 * AT_K_STAGE + 2 * AT_V_STAGE)
#define AT_SMEM_BYTES  (AT_SMEM_HALVES * 2)   // 88064 B

__global__ __launch_bounds__(256, 2)
void attn_h_kernel(const __half* __restrict__ qp, const __half* __restrict__ kp,
                   const __half* __restrict__ qkv, __half* __restrict__ out)
{
    extern __shared__ __half hsm[];
    __half* Qs = hsm;                           // 128 x 136 (staging)
    __half* Ps = hsm;                           // 128 x 72 (aliases Qs)

    const int b = blockIdx.z;
    const int h = blockIdx.y;
    const int qtile = gridDim.x - 1 - blockIdx.x;   // heavy tiles first
    const int q0 = qtile * 128;

    const int tid  = threadIdx.x;
    const int lane = tid & 31, wid = tid >> 5;
    const int grp = lane >> 2, tig = lane & 3;
    const int r0 = wid * 16 + grp;

    const int l8  = lane & 7;
    const int q01 = (lane >> 3) & 1;
    const int q23 = lane >> 4;

    const uint32_t smbase = smem_u32(hsm);
    const uint32_t pssm  = smbase;                               // Ps
    const uint32_t kssm0 = smbase + AT_Q_HALVES * 2;             // K stage 0
    const uint32_t vssm0 = kssm0 + 2 * AT_K_STAGE * 2;           // V stage 0

    const __half* qbase = qp + (((size_t)(b * NHEADS + h)) * SEQ) * 128;
    const __half* kbase = kp + (((size_t)(b * NHEADS + h)) * SEQ) * 128;
    const __half* vbase = qkv + 2 * DMODEL + h * HEADDIM;        // V cols in fused buffer

    auto load_kv = [&](int stage, int kt) {
        uint32_t kb = kssm0 + stage * AT_K_STAGE * 2;
#pragma unroll
        for (int i = 0; i < 4; ++i) {
            int idx = tid + i * 256;
            int r = idx >> 4, c = idx & 15;
            cp_async16(kb + (uint32_t)(r * AT_KS + c * 8) * 2,
                       kbase + (size_t)(kt + r) * 128 + c * 8);
        }
        uint32_t vb = vssm0 + stage * AT_V_STAGE * 2;
#pragma unroll
        for (int i = 0; i < 2; ++i) {
            int idx = tid + i * 256;
            int r = idx >> 3, c = idx & 7;
            cp_async16(vb + (uint32_t)(r * AT_VS + c * 8) * 2,
                       vbase + ((size_t)b * SEQ + kt + r) * QKVN + c * 8);
        }
    };

    // Prologue: start K/V tile 0 fetch, then stage Q.
    load_kv(0, 0);
    asm volatile("cp.async.commit_group;" ::: "memory");

    for (int i = tid; i < 2048; i += 256) {
        int r = i >> 4, c = i & 15;
        *(uint4*)&Qs[r * AT_QS + c * 8] =
            *(const uint4*)&qbase[(size_t)(q0 + r) * 128 + c * 8];
    }
    __syncthreads();

    // Preload Q fragments via ldmatrix: 8 k16 chunks
    uint32_t qf[8][4];
    {
        int row = wid * 16 + q01 * 8 + l8;
#pragma unroll
        for (int kk = 0; kk < 8; ++kk) {
            int col = kk * 16 + q23 * 8;
            ldsm_x4(qf[kk], smbase + (uint32_t)(row * AT_QS + col) * 2);
        }
    }
    __syncthreads();   // done reading Qs before Ps overwrites

    float m0 = -INFINITY, m1 = -INFINITY, l0 = 0.f, l1 = 0.f;
    float o[8][4];
#pragma unroll
    for (int nj = 0; nj < 8; ++nj)
#pragma unroll
        for (int r = 0; r < 4; ++r) o[nj][r] = 0.f;

    const int nT = q0 / 64 + 2;
    for (int t = 0; t < nT; ++t) {
        const int kt = t * 64;
        asm volatile("cp.async.wait_group 0;" ::: "memory");
        __syncthreads();
        if (t + 1 < nT) {
            load_kv((t + 1) & 1, (t + 1) * 64);
            asm volatile("cp.async.commit_group;" ::: "memory");
        }
        const uint32_t kst = kssm0 + (t & 1) * AT_K_STAGE * 2;
        const uint32_t vst = vssm0 + (t & 1) * AT_V_STAGE * 2;

        // scores = Q @ K^T
        float sacc[8][4];
#pragma unroll
        for (int nj = 0; nj < 8; ++nj)
#pragma unroll
            for (int r = 0; r < 4; ++r) sacc[nj][r] = 0.f;

#pragma unroll
        for (int kk = 0; kk < 8; ++kk) {
            int k = kk * 16;
#pragma unroll
            for (int g = 0; g < 4; ++g) {
                uint32_t bf[4];
                int row = g * 16 + q23 * 8 + l8;
                int col = k + q01 * 8;
                ldsm_x4(bf, kst + (uint32_t)(row * AT_KS + col) * 2);
                mma_f16(sacc[g * 2 + 0], qf[kk], bf[0], bf[1]);
                mma_f16(sacc[g * 2 + 1], qf[kk], bf[2], bf[3]);
            }
        }

        // causal mask (last two key tiles only)
        if (kt >= q0) {
            int row0 = q0 + r0, row1 = row0 + 8;
#pragma unroll
            for (int nj = 0; nj < 8; ++nj) {
                int c = kt + nj * 8 + 2 * tig;
                if (c     > row0) sacc[nj][0] = -INFINITY;
                if (c + 1 > row0) sacc[nj][1] = -INFINITY;
                if (c     > row1) sacc[nj][2] = -INFINITY;
                if (c + 1 > row1) sacc[nj][3] = -INFINITY;
            }
        }

        // online softmax1
        float mx0 = -INFINITY, mx1 = -INFINITY;
#pragma unroll
        for (int nj = 0; nj < 8; ++nj) {
            mx0 = fmaxf(mx0, fmaxf(sacc[nj][0], sacc[nj][1]));
            mx1 = fmaxf(mx1, fmaxf(sacc[nj][2], sacc[nj][3]));
        }
        mx0 = fmaxf(mx0, __shfl_xor_sync(0xffffffffu, mx0, 1));
        mx0 = fmaxf(mx0, __shfl_xor_sync(0xffffffffu, mx0, 2));
        mx1 = fmaxf(mx1, __shfl_xor_sync(0xffffffffu, mx1, 1));
        mx1 = fmaxf(mx1, __shfl_xor_sync(0xffffffffu, mx1, 2));

        float m0n = fmaxf(m0, mx0), m1n = fmaxf(m1, mx1);
        float c0 = expf(m0 - m0n),  c1 = expf(m1 - m1n);
        m0 = m0n; m1 = m1n;

        float ls0 = 0.f, ls1 = 0.f;
#pragma unroll
        for (int nj = 0; nj < 8; ++nj) {
            float p0 = expf(sacc[nj][0] - m0n);
            float p1 = expf(sacc[nj][1] - m0n);
            float p2 = expf(sacc[nj][2] - m1n);
            float p3 = expf(sacc[nj][3] - m1n);
            ls0 += p0 + p1; ls1 += p2 + p3;
            *(__half2*)&Ps[r0       * AT_PS + nj * 8 + 2 * tig] = __floats2half2_rn(p0, p1);
            *(__half2*)&Ps[(r0 + 8) * AT_PS + nj * 8 + 2 * tig] = __floats2half2_rn(p2, p3);
        }
        ls0 += __shfl_xor_sync(0xffffffffu, ls0, 1);
        ls0 += __shfl_xor_sync(0xffffffffu, ls0, 2);
        ls1 += __shfl_xor_sync(0xffffffffu, ls1, 1);
        ls1 += __shfl_xor_sync(0xffffffffu, ls1, 2);
        l0 = l0 * c0 + ls0;
        l1 = l1 * c1 + ls1;

#pragma unroll
        for (int nj = 0; nj < 8; ++nj) {
            o[nj][0] *= c0; o[nj][1] *= c0;
            o[nj][2] *= c1; o[nj][3] *= c1;
        }
        __syncwarp();

        // O += P @ V (V row-major [key][dim]; B fragments via ldmatrix.trans)
#pragma unroll
        for (int kk = 0; kk < 4; ++kk) {
            int k = kk * 16;
            uint32_t af[4];
            {
                int row = wid * 16 + q01 * 8 + l8;
                int col = k + q23 * 8;
                ldsm_x4(af, pssm + (uint32_t)(row * AT_PS + col) * 2);
            }
#pragma unroll
            for (int g = 0; g < 4; ++g) {
                uint32_t bf[4];
                int row = k + q01 * 8 + l8;          // key index
                int col = g * 16 + q23 * 8;          // dim index
                ldsm_x4_t(bf, vst + (uint32_t)(row * AT_VS + col) * 2);
                mma_f16(o[g * 2 + 0], af, bf[0], bf[1]);
                mma_f16(o[g * 2 + 1], af, bf[2], bf[3]);
            }
        }
    }

    // epilogue: softmax1 denominator; write fp16 (B,S,D)
    float inv0 = 1.f / (1.f + l0);
    float inv1 = 1.f / (1.f + l1);
    int row0 = q0 + r0;
#pragma unroll
    for (int nj = 0; nj < 8; ++nj) {
        int c = h * HEADDIM + nj * 8 + 2 * tig;
        *(__half2*)&out[((size_t)b * SEQ + row0)     * DMODEL + c] =
            __floats2half2_rn(o[nj][0] * inv0, o[nj][1] * inv0);
        *(__half2*)&out[((size_t)b * SEQ + row0 + 8) * DMODEL + c] =
            __floats2half2_rn(o[nj][2] * inv1, o[nj][3] * inv1);
    }
}

// ---------------------------------------------------------------------------
// Fused residual add + LayerNorm; optional fp16 copy of the output.
// ---------------------------------------------------------------------------
template<int WRITEH>
__global__ __launch_bounds__(256)
void add_ln_kernel(const float* __restrict__ x, const float* __restrict__ y,
                   const float* __restrict__ g, const float* __restrict__ beta,
                   float* __restrict__ out, __half* __restrict__ outh)
{
    __shared__ float red_s[8];
    __shared__ float red_ss[8];
    __shared__ float s_mu, s_rstd;

    const int row = blockIdx.x;
    const int tid = threadIdx.x;
    const size_t base = (size_t)row * DMODEL;

    float4 xv = ((const float4*)(x + base))[tid];
    float4 yv = ((const float4*)(y + base))[tid];
    float v0 = xv.x + yv.x, v1 = xv.y + yv.y, v2 = xv.z + yv.z, v3 = xv.w + yv.w;

    float sum = v0 + v1 + v2 + v3;
    float ssq = v0 * v0 + v1 * v1 + v2 * v2 + v3 * v3;
#pragma unroll
    for (int off = 16; off >= 1; off >>= 1) {
        sum += __shfl_down_sync(0xffffffffu, sum, off);
        ssq += __shfl_down_sync(0xffffffffu, ssq, off);
    }
    const int warp = tid >> 5;
    if ((tid & 31) == 0) { red_s[warp] = sum; red_ss[warp] = ssq; }
    __syncthreads();
    if (tid == 0) {
        float ts = 0.f, tss = 0.f;
#pragma unroll
        for (int w = 0; w < 8; ++w) { ts += red_s[w]; tss += red_ss[w]; }
        float mu  = ts / (float)DMODEL;
        float var = tss / (float)DMODEL - mu * mu;
        s_mu = mu;
        s_rstd = rsqrtf(var + LN_EPS);
    }
    __syncthreads();
    const float mu = s_mu, rstd = s_rstd;

    float4 gv = ((const float4*)g)[tid];
    float4 bv = ((const float4*)beta)[tid];
    float4 o;
    o.x = (v0 - mu) * rstd * gv.x + bv.x;
    o.y = (v1 - mu) * rstd * gv.y + bv.y;
    o.z = (v2 - mu) * rstd * gv.z + bv.z;
    o.w = (v3 - mu) * rstd * gv.w + bv.w;
    ((float4*)(out + base))[tid] = o;
    if (WRITEH) {
        __half2 h0 = __floats2half2_rn(o.x, o.y);
        __half2 h1 = __floats2half2_rn(o.z, o.w);
        ((__half2*)(outh + base))[2 * tid]     = h0;
        ((__half2*)(outh + base))[2 * tid + 1] = h1;
    }
}

// ---------------------------------------------------------------------------
// Launcher
// ---------------------------------------------------------------------------
extern "C" void kernel_launch(void* const* d_in, const int* in_sizes, int n_in,
                              void* d_out, int out_size)
{
    (void)in_sizes; (void)n_in; (void)out_size;
    const float* x          = (const float*)d_in[0];
    const int*   positions  = (const int*)  d_in[1];
    const float* Wq         = (const float*)d_in[2];
    const float* bq         = (const float*)d_in[3];
    const float* Wk         = (const float*)d_in[4];
    const float* bk         = (const float*)d_in[5];
    const float* Wv         = (const float*)d_in[6];
    const float* bv         = (const float*)d_in[7];
    const float* Wo         = (const float*)d_in[8];
    const float* bo         = (const float*)d_in[9];
    const float* phase_bias = (const float*)d_in[10];
    const float* freqs      = (const float*)d_in[11];
    const float* W1         = (const float*)d_in[12];
    const float* b1         = (const float*)d_in[13];
    const float* W2         = (const float*)d_in[14];
    const float* b2         = (const float*)d_in[15];
    const float* g1         = (const float*)d_in[16];
    const float* beta1      = (const float*)d_in[17];
    const float* g2         = (const float*)d_in[18];
    const float* beta2      = (const float*)d_in[19];
    float* outp             = (float*)d_out;

    float  *bufA, *bufB, *bufX1, *bqkv;
    __half *xh, *QKVh, *QPh, *KPh, *AttnH, *X1h, *FFh;
    __half *WqkvT, *WoT, *W1T, *W2T;
    cudaGetSymbolAddress((void**)&bufA,  g_bufA);
    cudaGetSymbolAddress((void**)&bufB,  g_bufB);
    cudaGetSymbolAddress((void**)&bufX1, g_bufX1);
    cudaGetSymbolAddress((void**)&bqkv,  g_bqkv);
    cudaGetSymbolAddress((void**)&xh,    g_xh);
    cudaGetSymbolAddress((void**)&QKVh,  g_QKVh);
    cudaGetSymbolAddress((void**)&QPh,   g_QPh);
    cudaGetSymbolAddress((void**)&KPh,   g_KPh);
    cudaGetSymbolAddress((void**)&AttnH, g_AttnH);
    cudaGetSymbolAddress((void**)&X1h,   g_X1h);
    cudaGetSymbolAddress((void**)&FFh,   g_FFh);
    cudaGetSymbolAddress((void**)&WqkvT, g_WqkvT);
    cudaGetSymbolAddress((void**)&WoT,   g_WoT);
    cudaGetSymbolAddress((void**)&W1T,   g_W1T);
    cudaGetSymbolAddress((void**)&W2T,   g_W2T);

    cudaFuncSetAttribute(attn_h_kernel, cudaFuncAttributeMaxDynamicSharedMemorySize,
                         AT_SMEM_BYTES);
    cudaFuncSetAttribute(hgemm_kernel<0,0>, cudaFuncAttributeMaxDynamicSharedMemorySize,
                         HG_SMEM_BYTES);
    cudaFuncSetAttribute(hgemm_kernel<0,1>, cudaFuncAttributeMaxDynamicSharedMemorySize,
                         HG_SMEM_BYTES);
    cudaFuncSetAttribute(hgemm_kernel<1,1>, cudaFuncAttributeMaxDynamicSharedMemorySize,
                         HG_SMEM_BYTES);

    // 0a: x -> fp16
    f2h_kernel<<<(BS * DMODEL / 8 + 255) / 256, 256>>>(x, xh, BS * DMODEL);

    // 0b: weight transposes + fp16 (QKV batched into concat buffer)
    {
        dim3 blk(32, 8);
        transpose_h_qkv_kernel<<<dim3(DMODEL/32, DMODEL/32, 3), blk>>>(Wq, Wk, Wv, WqkvT);
        transpose_h_kernel<<<dim3(DMODEL/32, DMODEL/32), blk>>>(Wo, WoT, DMODEL, DMODEL);
        transpose_h_kernel<<<dim3(DFF/32,    DMODEL/32), blk>>>(W1, W1T, DMODEL, DFF);
        transpose_h_kernel<<<dim3(DMODEL/32, DFF/32),    blk>>>(W2, W2T, DFF, DMODEL);
        concat_bias_kernel<<<(QKVN + 255) / 256, 256>>>(bq, bk, bv, bqkv);
    }

    // 1: fused QKV projection (N=3072), fp16 out
    {
        dim3 grid(QKVN / 128, BS / 128);
        hgemm_kernel<0,1><<<grid, 256, HG_SMEM_BYTES>>>(xh, WqkvT, bqkv, QKVh, BS, QKVN, DMODEL);
    }

    // 2: PoPE (fp16 in/out)
    {
        int total = BATCH * NHEADS * SEQ * 32;
        pope_kernel<<<(total + 255) / 256, 256>>>(QKVh, positions, freqs,
                                                  phase_bias, QPh, KPh);
    }

    // 3: attention -> fp16
    {
        dim3 grid(SEQ / 128, NHEADS, BATCH);
        attn_h_kernel<<<grid, 256, AT_SMEM_BYTES>>>(QPh, KPh, QKVh, AttnH);
    }

    // 4: output projection -> fp32
    {
        dim3 grid(DMODEL / 128, BS / 128);
        hgemm_kernel<0,0><<<grid, 256, HG_SMEM_BYTES>>>(AttnH, WoT, bo, bufA, BS, DMODEL, DMODEL);
    }

    // 5: residual + LN1 -> fp32 + fp16
    add_ln_kernel<1><<<BS, 256>>>(x, bufA, g1, beta1, bufX1, X1h);

    // 6: FFN up + ReLU -> fp16
    {
        dim3 grid(DFF / 128, BS / 128);
        hgemm_kernel<1,1><<<grid, 256, HG_SMEM_BYTES>>>(X1h, W1T, b1, FFh, BS, DFF, DMODEL);
    }

    // 7: FFN down -> fp32
    {
        dim3 grid(DMODEL / 128, BS / 128);
        hgemm_kernel<0,0><<<grid, 256, HG_SMEM_BYTES>>>(FFh, W2T, b2, bufB, BS, DMODEL, DFF);
    }

    // 8: residual + LN2 -> output
    add_ln_kernel<0><<<BS, 256>>>(bufX1, bufB, g2, beta2, outp, nullptr);
}